// round 1
// baseline (speedup 1.0000x reference)
#include <cuda_runtime.h>
#include <cuda_bf16.h>
#include <math.h>

// ---------------- problem constants ----------------
#define S 2048
#define HID 4096
#define NH 32
#define NKV 8
#define HD 128
#define GROUPS 4
#define EPS 1e-8f
#define ATT_SCALE 0.08838834764831845f   // 128^-0.5
#define LN10000 9.210340371976184f

// ---------------- scratch (device globals; no allocation allowed) ----------------
__device__ float g_qproj[S * HID];        // [s][h*128+d]
__device__ float g_kproj[S * NKV * HD];   // [s][kv*128+d]
__device__ float g_vproj[S * NKV * HD];
__device__ float g_qn[S * HID];
__device__ float g_kn[S * NKV * HD];
__device__ float g_memout[S * HID];
__device__ float g_attnout[S * HID];
__device__ float g_vdelta[S * NKV * HD];
__device__ float g_knsum[NKV * HD];
__device__ float g_combined[S * HID];

// ---------------- generic tiled SGEMM: C[M,N] = A[M,K] @ B[K,N], row-major ----------------
// BM=BN=128, BK=8, TM=TN=8, 256 threads
__global__ __launch_bounds__(256) void sgemm_kernel(
    const float* __restrict__ A, const float* __restrict__ B, float* __restrict__ C,
    int M, int N, int K)
{
    __shared__ float As[8][128];
    __shared__ float Bs[8][128];
    const int bx = blockIdx.x;   // N tile
    const int by = blockIdx.y;   // M tile
    const int tid = threadIdx.x;
    const int tcol = tid & 15;   // 0..15
    const int trow = tid >> 4;   // 0..15
    const int aRow = tid >> 1;          // 0..127
    const int aCol = (tid & 1) << 2;    // 0 or 4
    const int bRow = tid >> 5;          // 0..7
    const int bCol = (tid & 31) << 2;   // 0..124

    const float* Ap = A + (size_t)(by * 128) * K;
    const float* Bp = B + bx * 128;

    float acc[8][8];
#pragma unroll
    for (int i = 0; i < 8; i++)
#pragma unroll
        for (int j = 0; j < 8; j++) acc[i][j] = 0.f;

    for (int k0 = 0; k0 < K; k0 += 8) {
        float4 a4 = *(const float4*)(Ap + (size_t)aRow * K + k0 + aCol);
        As[aCol + 0][aRow] = a4.x;
        As[aCol + 1][aRow] = a4.y;
        As[aCol + 2][aRow] = a4.z;
        As[aCol + 3][aRow] = a4.w;
        float4 b4 = *(const float4*)(Bp + (size_t)(k0 + bRow) * N + bCol);
        *(float4*)(&Bs[bRow][bCol]) = b4;
        __syncthreads();
#pragma unroll
        for (int kk = 0; kk < 8; kk++) {
            float regM[8], regN[8];
            *(float4*)(&regM[0]) = *(const float4*)(&As[kk][trow * 8]);
            *(float4*)(&regM[4]) = *(const float4*)(&As[kk][trow * 8 + 4]);
            *(float4*)(&regN[0]) = *(const float4*)(&Bs[kk][tcol * 8]);
            *(float4*)(&regN[4]) = *(const float4*)(&Bs[kk][tcol * 8 + 4]);
#pragma unroll
            for (int i = 0; i < 8; i++)
#pragma unroll
                for (int j = 0; j < 8; j++)
                    acc[i][j] += regM[i] * regN[j];
        }
        __syncthreads();
    }
    float* Cp = C + (size_t)(by * 128 + trow * 8) * N + bx * 128 + tcol * 8;
#pragma unroll
    for (int i = 0; i < 8; i++) {
        float4 c0 = make_float4(acc[i][0], acc[i][1], acc[i][2], acc[i][3]);
        float4 c1 = make_float4(acc[i][4], acc[i][5], acc[i][6], acc[i][7]);
        *(float4*)(Cp + (size_t)i * N) = c0;
        *(float4*)(Cp + (size_t)i * N + 4) = c1;
    }
}

// ---------------- qn / kn: elu(x)+1 then row-normalize (pre-RoPE) ----------------
__global__ __launch_bounds__(128) void qn_kernel(const float* __restrict__ qp, float* __restrict__ qn)
{
    const int s = blockIdx.x;
    const int d = threadIdx.x;
    __shared__ float wsum[4];
    for (int h = 0; h < NH; h++) {
        float x = qp[(size_t)s * HID + h * HD + d];
        float f = x > 0.f ? x + 1.f : expf(x);
        float v = f;
#pragma unroll
        for (int o = 16; o; o >>= 1) v += __shfl_xor_sync(0xffffffffu, v, o);
        if ((d & 31) == 0) wsum[d >> 5] = v;
        __syncthreads();
        float tot = wsum[0] + wsum[1] + wsum[2] + wsum[3];
        qn[(size_t)s * HID + h * HD + d] = f / (tot + EPS);
        __syncthreads();
    }
}

__global__ __launch_bounds__(128) void kn_kernel(const float* __restrict__ kp, float* __restrict__ kn)
{
    const int s = blockIdx.x;
    const int d = threadIdx.x;
    __shared__ float wsum[4];
    for (int h = 0; h < NKV; h++) {
        float x = kp[(size_t)s * (NKV * HD) + h * HD + d];
        float f = x > 0.f ? x + 1.f : expf(x);
        float v = f;
#pragma unroll
        for (int o = 16; o; o >>= 1) v += __shfl_xor_sync(0xffffffffu, v, o);
        if ((d & 31) == 0) wsum[d >> 5] = v;
        __syncthreads();
        float tot = wsum[0] + wsum[1] + wsum[2] + wsum[3];
        kn[(size_t)s * (NKV * HD) + h * HD + d] = f / (tot + EPS);
        __syncthreads();
    }
}

// knsum[h][d] = sum_s kn[h,s,d]  (deterministic reduction, grid = 8 blocks)
__global__ __launch_bounds__(128) void knsum_kernel(const float* __restrict__ kn, float* __restrict__ knsum)
{
    const int h = blockIdx.x;
    const int d = threadIdx.x;
    float acc = 0.f;
    for (int s = 0; s < S; s++)
        acc += kn[(size_t)s * (NKV * HD) + h * HD + d];
    knsum[h * HD + d] = acc;
}

// ---------------- memory retrieval: mem_out = (qn @ M) / (qn @ N^T + eps) ----------------
// grid (128 s-tiles of 16, 32 heads), block 128 (thread = output dim e)
__global__ __launch_bounds__(128) void retrieve_kernel(
    const float* __restrict__ qn, const float* __restrict__ memory,
    const float* __restrict__ norm_m, float* __restrict__ memout)
{
    const int h = blockIdx.y;
    const int st = blockIdx.x;
    const int hm = h & (NKV - 1);
    const int e = threadIdx.x;
    __shared__ float Qs[16][128];
    __shared__ float Ms[32][128];
    __shared__ float Ns[128][33];

    for (int i = e; i < 16 * 128; i += 128) {
        int r = i >> 7, d = i & 127;
        Qs[r][d] = qn[(size_t)(st * 16 + r) * HID + h * HD + d];
    }
    float num[16], den[16];
#pragma unroll
    for (int r = 0; r < 16; r++) { num[r] = 0.f; den[r] = 0.f; }
    const float* M = memory + hm * HD * HD;
    const float* Nm = norm_m + hm * HD * HD;

    for (int d0 = 0; d0 < 128; d0 += 32) {
        __syncthreads();
        for (int i = e; i < 32 * 128; i += 128) {
            int dd = i >> 7, ee = i & 127;
            Ms[dd][ee] = M[(d0 + dd) * HD + ee];
        }
        for (int i = e; i < 128 * 32; i += 128) {
            int ee = i >> 5, dd = i & 31;
            Ns[ee][dd] = Nm[ee * HD + d0 + dd];
        }
        __syncthreads();
#pragma unroll 4
        for (int dd = 0; dd < 32; dd++) {
            float mv = Ms[dd][e];
            float nv = Ns[e][dd];
#pragma unroll
            for (int r = 0; r < 16; r++) {
                float qv = Qs[r][d0 + dd];
                num[r] += qv * mv;
                den[r] += qv * nv;
            }
        }
    }
#pragma unroll
    for (int r = 0; r < 16; r++)
        memout[(size_t)(st * 16 + r) * HID + h * HD + e] = num[r] / (den[r] + EPS);
}

// ---------------- v - v_ret for delta rule (kv heads) ----------------
__global__ __launch_bounds__(128) void vdelta_kernel(
    const float* __restrict__ kn, const float* __restrict__ vproj,
    const float* __restrict__ memory, const float* __restrict__ norm_m,
    float* __restrict__ vdelta)
{
    const int h = blockIdx.y;   // 0..7
    const int st = blockIdx.x;
    const int e = threadIdx.x;
    __shared__ float Qs[16][128];
    __shared__ float Ms[32][128];
    __shared__ float Ns[128][33];

    for (int i = e; i < 16 * 128; i += 128) {
        int r = i >> 7, d = i & 127;
        Qs[r][d] = kn[(size_t)(st * 16 + r) * (NKV * HD) + h * HD + d];
    }
    float num[16], den[16];
#pragma unroll
    for (int r = 0; r < 16; r++) { num[r] = 0.f; den[r] = 0.f; }
    const float* M = memory + h * HD * HD;
    const float* Nm = norm_m + h * HD * HD;

    for (int d0 = 0; d0 < 128; d0 += 32) {
        __syncthreads();
        for (int i = e; i < 32 * 128; i += 128) {
            int dd = i >> 7, ee = i & 127;
            Ms[dd][ee] = M[(d0 + dd) * HD + ee];
        }
        for (int i = e; i < 128 * 32; i += 128) {
            int ee = i >> 5, dd = i & 31;
            Ns[ee][dd] = Nm[ee * HD + d0 + dd];
        }
        __syncthreads();
#pragma unroll 4
        for (int dd = 0; dd < 32; dd++) {
            float mv = Ms[dd][e];
            float nv = Ns[e][dd];
#pragma unroll
            for (int r = 0; r < 16; r++) {
                float qv = Qs[r][d0 + dd];
                num[r] += qv * mv;
                den[r] += qv * nv;
            }
        }
    }
#pragma unroll
    for (int r = 0; r < 16; r++) {
        size_t idx = (size_t)(st * 16 + r) * (NKV * HD) + h * HD + e;
        vdelta[idx] = vproj[idx] - num[r] / (den[r] + EPS);
    }
}

// ---------------- RoPE (in place on q_proj and k_proj, post qn/kn) ----------------
__global__ __launch_bounds__(256) void rope_kernel(
    float* __restrict__ q, float* __restrict__ k, const int* __restrict__ pos)
{
    const int s = blockIdx.x;
    const int idx = blockIdx.y * 256 + threadIdx.x;   // 0..2559
    if (idx >= (NH + NKV) * 64) return;
    const int head = idx >> 6;
    const int d = idx & 63;
    const float p = (float)pos[s];
    const float invf = expf(-(2.0f * (float)d / 128.0f) * LN10000);
    const float a = p * invf;
    const float c = cosf(a), sn = sinf(a);
    float* base = (head < NH) ? (q + (size_t)s * HID + head * HD)
                              : (k + (size_t)s * (NKV * HD) + (head - NH) * HD);
    float x0 = base[d], x1 = base[d + 64];
    base[d]      = x0 * c - x1 * sn;
    base[d + 64] = x1 * c + x0 * sn;
}

// ---------------- causal flash attention, fp32 ----------------
// grid (64 q-tiles, 32 heads), block 128. Thread t owns output dim e=t, all 32 rows.
__global__ __launch_bounds__(128) void attn_kernel(
    const float* __restrict__ q, const float* __restrict__ k,
    const float* __restrict__ v, float* __restrict__ out)
{
    const int h = blockIdx.y;
    const int qt = gridDim.x - 1 - blockIdx.x;   // heavy tiles launch first
    const int kvh = h >> 2;
    const int t = threadIdx.x;
    __shared__ float Qs[32][128];
    __shared__ float KVs[32][129];
    __shared__ float P[32][33];
    __shared__ float sm_m[32], sm_l[32], sm_sc[32];

    for (int i = t; i < 32 * 128; i += 128) {
        int r = i >> 7, d = i & 127;
        Qs[r][d] = q[(size_t)(qt * 32 + r) * HID + h * HD + d];
    }
    if (t < 32) { sm_m[t] = -1e30f; sm_l[t] = 0.f; }
    float o_acc[32];
#pragma unroll
    for (int i = 0; i < 32; i++) o_acc[i] = 0.f;

    const int kjl = t & 31;
    const int qb = t >> 5;

    for (int kt = 0; kt <= qt; kt++) {
        __syncthreads();   // KVs reuse fence (and Qs load fence on first iter)
        for (int i = t; i < 32 * 128; i += 128) {
            int r = i >> 7, d = i & 127;
            KVs[r][d] = k[(size_t)(kt * 32 + r) * (NKV * HD) + kvh * HD + d];
        }
        __syncthreads();
        float acc[8];
#pragma unroll
        for (int r = 0; r < 8; r++) acc[r] = 0.f;
#pragma unroll 4
        for (int d = 0; d < 128; d++) {
            float kv = KVs[kjl][d];
#pragma unroll
            for (int r = 0; r < 8; r++) acc[r] += Qs[r * 4 + qb][d] * kv;
        }
#pragma unroll
        for (int r = 0; r < 8; r++) {
            int qi = r * 4 + qb;
            float sc = acc[r] * ATT_SCALE;
            if (kt == qt && kjl > qi) sc = -1e30f;
            P[qi][kjl] = sc;
        }
        __syncthreads();
        if (t < 32) {
            float m_old = sm_m[t], mx = m_old;
#pragma unroll 8
            for (int j = 0; j < 32; j++) mx = fmaxf(mx, P[t][j]);
            float scl = expf(m_old - mx);
            float lsum = 0.f;
#pragma unroll 8
            for (int j = 0; j < 32; j++) {
                float pv = expf(P[t][j] - mx);
                P[t][j] = pv;
                lsum += pv;
            }
            sm_l[t] = sm_l[t] * scl + lsum;
            sm_m[t] = mx;
            sm_sc[t] = scl;
        }
        __syncthreads();
        for (int i = t; i < 32 * 128; i += 128) {   // V into KVs
            int r = i >> 7, d = i & 127;
            KVs[r][d] = v[(size_t)(kt * 32 + r) * (NKV * HD) + kvh * HD + d];
        }
        __syncthreads();
#pragma unroll
        for (int qi = 0; qi < 32; qi++) o_acc[qi] *= sm_sc[qi];
        for (int kj = 0; kj < 32; kj++) {
            float vv = KVs[kj][t];
#pragma unroll
            for (int qi = 0; qi < 32; qi++) o_acc[qi] += P[qi][kj] * vv;
        }
    }
    __syncthreads();
#pragma unroll
    for (int qi = 0; qi < 32; qi++)
        out[(size_t)(qt * 32 + qi) * HID + h * HD + t] = o_acc[qi] / sm_l[qi];
}

// ---------------- sigmoid-gated combine ----------------
__global__ __launch_bounds__(256) void combine_kernel(
    const float* __restrict__ memout, const float* __restrict__ attnout,
    const float* __restrict__ beta, float* __restrict__ combined)
{
    const int i = blockIdx.x * 256 + threadIdx.x;
    const float g = 1.f / (1.f + expf(-beta[0]));
    combined[i] = g * memout[i] + (1.f - g) * attnout[i];
}

// ---------------- delta-rule memory update: out = memory + kn^T @ vdelta ----------------
// grid 8 (one block per kv head), 256 threads, 8x8 per thread, deterministic.
__global__ __launch_bounds__(256) void delta_kernel(
    const float* __restrict__ kn, const float* __restrict__ vd,
    const float* __restrict__ memory, float* __restrict__ outmem)
{
    const int h = blockIdx.x;
    __shared__ float Ak[32][128];
    __shared__ float Bv[32][128];
    const int trow = (threadIdx.x >> 4) * 8;
    const int tcol = (threadIdx.x & 15) * 8;
    float acc[8][8];
#pragma unroll
    for (int i = 0; i < 8; i++)
#pragma unroll
        for (int j = 0; j < 8; j++) acc[i][j] = 0.f;

    for (int s0 = 0; s0 < S; s0 += 32) {
        for (int i = threadIdx.x; i < 32 * 128; i += 256) {
            int ss = i >> 7, dd = i & 127;
            size_t idx = (size_t)(s0 + ss) * (NKV * HD) + h * HD + dd;
            Ak[ss][dd] = kn[idx];
            Bv[ss][dd] = vd[idx];
        }
        __syncthreads();
#pragma unroll 4
        for (int ss = 0; ss < 32; ss++) {
            float ra[8], rb[8];
#pragma unroll
            for (int i = 0; i < 8; i++) ra[i] = Ak[ss][trow + i];
#pragma unroll
            for (int j = 0; j < 8; j++) rb[j] = Bv[ss][tcol + j];
#pragma unroll
            for (int i = 0; i < 8; i++)
#pragma unroll
                for (int j = 0; j < 8; j++) acc[i][j] += ra[i] * rb[j];
        }
        __syncthreads();
    }
    const float* Mh = memory + h * HD * HD;
    float* Oh = outmem + h * HD * HD;
#pragma unroll
    for (int i = 0; i < 8; i++)
#pragma unroll
        for (int j = 0; j < 8; j++) {
            int idx = (trow + i) * HD + tcol + j;
            Oh[idx] = Mh[idx] + acc[i][j];
        }
}

// ---------------- updated_norm ----------------
__global__ __launch_bounds__(256) void norm_kernel(
    const float* __restrict__ norm_m, const float* __restrict__ knsum, float* __restrict__ out)
{
    const int i = blockIdx.x * 256 + threadIdx.x;   // < 8*128*128
    const int h = i >> 14;
    const int j = i & 127;
    out[i] = norm_m[i] + knsum[h * HD + j];
}

// ---------------- launch ----------------
extern "C" void kernel_launch(void* const* d_in, const int* in_sizes, int n_in,
                              void* d_out, int out_size)
{
    const float* hidden = (const float*)d_in[0];
    const int*   pos    = (const int*)d_in[1];
    const float* wq     = (const float*)d_in[2];
    const float* wk     = (const float*)d_in[3];
    const float* wv     = (const float*)d_in[4];
    const float* wo     = (const float*)d_in[5];
    const float* memory = (const float*)d_in[6];
    const float* norm_m = (const float*)d_in[7];
    const float* beta   = (const float*)d_in[8];
    float* out = (float*)d_out;

    float *qproj, *kproj, *vproj, *qn, *kn, *memout, *attnout, *vdelta, *knsum, *combined;
    cudaGetSymbolAddress((void**)&qproj, g_qproj);
    cudaGetSymbolAddress((void**)&kproj, g_kproj);
    cudaGetSymbolAddress((void**)&vproj, g_vproj);
    cudaGetSymbolAddress((void**)&qn, g_qn);
    cudaGetSymbolAddress((void**)&kn, g_kn);
    cudaGetSymbolAddress((void**)&memout, g_memout);
    cudaGetSymbolAddress((void**)&attnout, g_attnout);
    cudaGetSymbolAddress((void**)&vdelta, g_vdelta);
    cudaGetSymbolAddress((void**)&knsum, g_knsum);
    cudaGetSymbolAddress((void**)&combined, g_combined);

    // projections
    sgemm_kernel<<<dim3(HID / 128, S / 128), 256>>>(hidden, wq, qproj, S, HID, HID);
    sgemm_kernel<<<dim3(NKV * HD / 128, S / 128), 256>>>(hidden, wk, kproj, S, NKV * HD, HID);
    sgemm_kernel<<<dim3(NKV * HD / 128, S / 128), 256>>>(hidden, wv, vproj, S, NKV * HD, HID);

    // normalized features from PRE-RoPE q/k
    qn_kernel<<<S, 128>>>(qproj, qn);
    kn_kernel<<<S, 128>>>(kproj, kn);
    knsum_kernel<<<NKV, 128>>>(kn, knsum);

    // compressive-memory retrieval + delta-rule prep
    retrieve_kernel<<<dim3(S / 16, NH), 128>>>(qn, memory, norm_m, memout);
    vdelta_kernel<<<dim3(S / 16, NKV), 128>>>(kn, vproj, memory, norm_m, vdelta);

    // RoPE in place, then causal attention
    rope_kernel<<<dim3(S, 10), 256>>>(qproj, kproj, pos);
    attn_kernel<<<dim3(S / 32, NH), 128>>>(qproj, kproj, vproj, attnout);

    // gated combine + output projection
    combine_kernel<<<(S * HID) / 256, 256>>>(memout, attnout, beta, combined);
    sgemm_kernel<<<dim3(HID / 128, S / 128), 256>>>(combined, wo, out, S, HID, HID);

    // memory & norm updates (appended after the 8.4M-element `out`)
    delta_kernel<<<NKV, 256>>>(kn, vdelta, memory, out + (size_t)S * HID);
    norm_kernel<<<(NKV * HD * HD) / 256, 256>>>(norm_m, knsum,
                                                out + (size_t)S * HID + NKV * HD * HD);
}

// round 3
// speedup vs baseline: 1.5740x; 1.5740x over previous
#include <cuda_runtime.h>
#include <cuda_bf16.h>
#include <math.h>
#include <stdint.h>

// ---------------- problem constants ----------------
#define S 2048
#define HID 4096
#define NH 32
#define NKV 8
#define HD 128
#define GROUPS 4
#define EPS 1e-8f
#define ATT_SCALE 0.08838834764831845f   // 128^-0.5
#define LN10000 9.210340371976184f

// ---------------- scratch (device globals; no allocation allowed) ----------------
__device__ float g_qproj[S * HID];        // [s][h*128+d]
__device__ float g_kproj[S * NKV * HD];   // [s][kv*128+d]
__device__ float g_vproj[S * NKV * HD];
__device__ float g_qn[S * HID];
__device__ float g_kn[S * NKV * HD];
__device__ float g_memout[S * HID];
__device__ float g_attnout[S * HID];
__device__ float g_vdelta[S * NKV * HD];
__device__ float g_knsum[NKV * HD];
__device__ float g_knsum_part[16][NKV * HD];
__device__ float g_combined[S * HID];

// ---------------- tf32 helpers ----------------
// cvt.rna.tf32.f32 requires a b32 (integer) destination register.
__device__ __forceinline__ uint32_t f2tf32(float x) {
    uint32_t y;
    asm("cvt.rna.tf32.f32 %0, %1;" : "=r"(y) : "f"(x));
    return y;
}
__device__ __forceinline__ float f2tf32f(float x) {
    return __uint_as_float(f2tf32(x));
}

__device__ __forceinline__ void mma_tf32(
    float& c0, float& c1, float& c2, float& c3,
    uint32_t a0, uint32_t a1, uint32_t a2, uint32_t a3,
    uint32_t b0, uint32_t b1)
{
    asm volatile(
        "mma.sync.aligned.m16n8k8.row.col.f32.tf32.tf32.f32 "
        "{%0,%1,%2,%3},{%4,%5,%6,%7},{%8,%9},{%0,%1,%2,%3};"
        : "+f"(c0), "+f"(c1), "+f"(c2), "+f"(c3)
        : "r"(a0), "r"(a1), "r"(a2), "r"(a3), "r"(b0), "r"(b1));
}

// ---------------- tf32 tensor-core GEMM ----------------
// C[M,N] = A[M,K] @ B[K,N], row-major fp32 in/out, tf32 compute.
// Block tile 128x128, BK=16, 256 threads (8 warps, warp tile 64x32).
// blockIdx.z selects (B0,C0) vs (B1,C1) to fuse K/V projections.
#define GPAD 132
__global__ __launch_bounds__(256) void gemm_tf32_kernel(
    const float* __restrict__ A,
    const float* __restrict__ B0, float* __restrict__ C0,
    const float* __restrict__ B1, float* __restrict__ C1,
    int N, int K)
{
    const float* B = (blockIdx.z == 0) ? B0 : B1;
    float* C = (blockIdx.z == 0) ? C0 : C1;

    __shared__ float As[2][16][GPAD];   // k-major: As[k][m]
    __shared__ float Bs[2][16][GPAD];   // k-major: Bs[k][n]

    const int tid = threadIdx.x;
    const int lane = tid & 31;
    const int wid = tid >> 5;
    const int wm = wid >> 2;          // 0..1 -> 64 rows
    const int wn = wid & 3;           // 0..3 -> 32 cols
    const int lr = lane >> 2;         // 0..7
    const int lc = lane & 3;          // 0..3

    const int by = blockIdx.y;        // M tile
    const int bx = blockIdx.x;        // N tile

    // global load mapping
    const int am = tid >> 1;                 // 0..127
    const int ak = (tid & 1) * 8;            // 0 or 8
    const int bk = tid >> 4;                 // 0..15
    const int bn = (tid & 15) * 8;           // 0..120

    const float* Ag = A + (size_t)(by * 128 + am) * K + ak;
    const float* Bg = B + (size_t)bk * N + bx * 128 + bn;

    float acc[4][4][4];
#pragma unroll
    for (int i = 0; i < 4; i++)
#pragma unroll
        for (int j = 0; j < 4; j++)
#pragma unroll
            for (int r = 0; r < 4; r++) acc[i][j][r] = 0.f;

    const int NT = K / 16;

    // prologue: tile 0
    {
        float4 ra0 = *(const float4*)(Ag);
        float4 ra1 = *(const float4*)(Ag + 4);
        float4 rb0 = *(const float4*)(Bg);
        float4 rb1 = *(const float4*)(Bg + 4);
        As[0][ak + 0][am] = f2tf32f(ra0.x);
        As[0][ak + 1][am] = f2tf32f(ra0.y);
        As[0][ak + 2][am] = f2tf32f(ra0.z);
        As[0][ak + 3][am] = f2tf32f(ra0.w);
        As[0][ak + 4][am] = f2tf32f(ra1.x);
        As[0][ak + 5][am] = f2tf32f(ra1.y);
        As[0][ak + 6][am] = f2tf32f(ra1.z);
        As[0][ak + 7][am] = f2tf32f(ra1.w);
        float4 tb0 = make_float4(f2tf32f(rb0.x), f2tf32f(rb0.y), f2tf32f(rb0.z), f2tf32f(rb0.w));
        float4 tb1 = make_float4(f2tf32f(rb1.x), f2tf32f(rb1.y), f2tf32f(rb1.z), f2tf32f(rb1.w));
        *(float4*)(&Bs[0][bk][bn]) = tb0;
        *(float4*)(&Bs[0][bk][bn + 4]) = tb1;
    }
    __syncthreads();

    for (int it = 0; it < NT; it++) {
        const int cur = it & 1;
        float4 na0, na1, nb0, nb1;
        const bool more = (it + 1 < NT);
        if (more) {
            const float* Ap = Ag + (size_t)(it + 1) * 16;
            const float* Bp = Bg + (size_t)(it + 1) * 16 * N;
            na0 = *(const float4*)(Ap);
            na1 = *(const float4*)(Ap + 4);
            nb0 = *(const float4*)(Bp);
            nb1 = *(const float4*)(Bp + 4);
        }

        // compute on buffer cur
#pragma unroll
        for (int ks = 0; ks < 2; ks++) {
            const int kb = ks * 8;
            uint32_t af[4][4], bf[4][2];
#pragma unroll
            for (int mt = 0; mt < 4; mt++) {
                const int m0 = wm * 64 + mt * 16 + lr;
                af[mt][0] = __float_as_uint(As[cur][kb + lc][m0]);
                af[mt][1] = __float_as_uint(As[cur][kb + lc][m0 + 8]);
                af[mt][2] = __float_as_uint(As[cur][kb + 4 + lc][m0]);
                af[mt][3] = __float_as_uint(As[cur][kb + 4 + lc][m0 + 8]);
            }
#pragma unroll
            for (int nt = 0; nt < 4; nt++) {
                const int n0 = wn * 32 + nt * 8 + lr;
                bf[nt][0] = __float_as_uint(Bs[cur][kb + lc][n0]);
                bf[nt][1] = __float_as_uint(Bs[cur][kb + 4 + lc][n0]);
            }
#pragma unroll
            for (int mt = 0; mt < 4; mt++)
#pragma unroll
                for (int nt = 0; nt < 4; nt++)
                    mma_tf32(acc[mt][nt][0], acc[mt][nt][1], acc[mt][nt][2], acc[mt][nt][3],
                             af[mt][0], af[mt][1], af[mt][2], af[mt][3],
                             bf[nt][0], bf[nt][1]);
        }

        if (more) {
            const int nxt = cur ^ 1;
            As[nxt][ak + 0][am] = f2tf32f(na0.x);
            As[nxt][ak + 1][am] = f2tf32f(na0.y);
            As[nxt][ak + 2][am] = f2tf32f(na0.z);
            As[nxt][ak + 3][am] = f2tf32f(na0.w);
            As[nxt][ak + 4][am] = f2tf32f(na1.x);
            As[nxt][ak + 5][am] = f2tf32f(na1.y);
            As[nxt][ak + 6][am] = f2tf32f(na1.z);
            As[nxt][ak + 7][am] = f2tf32f(na1.w);
            float4 tb0 = make_float4(f2tf32f(nb0.x), f2tf32f(nb0.y), f2tf32f(nb0.z), f2tf32f(nb0.w));
            float4 tb1 = make_float4(f2tf32f(nb1.x), f2tf32f(nb1.y), f2tf32f(nb1.z), f2tf32f(nb1.w));
            *(float4*)(&Bs[nxt][bk][bn]) = tb0;
            *(float4*)(&Bs[nxt][bk][bn + 4]) = tb1;
        }
        __syncthreads();
    }

    // epilogue
#pragma unroll
    for (int mt = 0; mt < 4; mt++) {
        const int row = by * 128 + wm * 64 + mt * 16 + lr;
#pragma unroll
        for (int nt = 0; nt < 4; nt++) {
            const int col = bx * 128 + wn * 32 + nt * 8 + lc * 2;
            float2 v01 = make_float2(acc[mt][nt][0], acc[mt][nt][1]);
            float2 v23 = make_float2(acc[mt][nt][2], acc[mt][nt][3]);
            *(float2*)(C + (size_t)row * N + col) = v01;
            *(float2*)(C + (size_t)(row + 8) * N + col) = v23;
        }
    }
}

// ---------------- qn / kn: elu(x)+1 then row-normalize (pre-RoPE) ----------------
__global__ __launch_bounds__(128) void qn_kernel(const float* __restrict__ qp, float* __restrict__ qn)
{
    const int s = blockIdx.x;
    const int d = threadIdx.x;
    __shared__ float wsum[4];
    for (int h = 0; h < NH; h++) {
        float x = qp[(size_t)s * HID + h * HD + d];
        float f = x > 0.f ? x + 1.f : expf(x);
        float v = f;
#pragma unroll
        for (int o = 16; o; o >>= 1) v += __shfl_xor_sync(0xffffffffu, v, o);
        if ((d & 31) == 0) wsum[d >> 5] = v;
        __syncthreads();
        float tot = wsum[0] + wsum[1] + wsum[2] + wsum[3];
        qn[(size_t)s * HID + h * HD + d] = f / (tot + EPS);
        __syncthreads();
    }
}

__global__ __launch_bounds__(128) void kn_kernel(const float* __restrict__ kp, float* __restrict__ kn)
{
    const int s = blockIdx.x;
    const int d = threadIdx.x;
    __shared__ float wsum[4];
    for (int h = 0; h < NKV; h++) {
        float x = kp[(size_t)s * (NKV * HD) + h * HD + d];
        float f = x > 0.f ? x + 1.f : expf(x);
        float v = f;
#pragma unroll
        for (int o = 16; o; o >>= 1) v += __shfl_xor_sync(0xffffffffu, v, o);
        if ((d & 31) == 0) wsum[d >> 5] = v;
        __syncthreads();
        float tot = wsum[0] + wsum[1] + wsum[2] + wsum[3];
        kn[(size_t)s * (NKV * HD) + h * HD + d] = f / (tot + EPS);
        __syncthreads();
    }
}

// knsum two-pass deterministic reduction
__global__ __launch_bounds__(128) void knsum_part_kernel(const float* __restrict__ kn, float* __restrict__ part)
{
    const int h = blockIdx.x;
    const int p = blockIdx.y;
    const int d = threadIdx.x;
    float acc = 0.f;
    const int s0 = p * 128;
#pragma unroll 4
    for (int s = s0; s < s0 + 128; s++)
        acc += kn[(size_t)s * (NKV * HD) + h * HD + d];
    part[p * (NKV * HD) + h * HD + d] = acc;
}

__global__ __launch_bounds__(1024) void knsum_final_kernel(const float* __restrict__ part, float* __restrict__ knsum)
{
    const int i = threadIdx.x;  // 0..1023
    float acc = 0.f;
#pragma unroll
    for (int p = 0; p < 16; p++) acc += part[p * (NKV * HD) + i];
    knsum[i] = acc;
}

// ---------------- memory retrieval: mem_out = (qn @ M) / (qn @ N^T + eps) ----------------
__global__ __launch_bounds__(128) void retrieve_kernel(
    const float* __restrict__ qn, const float* __restrict__ memory,
    const float* __restrict__ norm_m, float* __restrict__ memout)
{
    const int h = blockIdx.y;
    const int st = blockIdx.x;
    const int hm = h & (NKV - 1);
    const int e = threadIdx.x;
    __shared__ float Qs[16][128];
    __shared__ float Ms[32][128];
    __shared__ float Ns[128][33];

    for (int i = e; i < 16 * 128; i += 128) {
        int r = i >> 7, d = i & 127;
        Qs[r][d] = qn[(size_t)(st * 16 + r) * HID + h * HD + d];
    }
    float num[16], den[16];
#pragma unroll
    for (int r = 0; r < 16; r++) { num[r] = 0.f; den[r] = 0.f; }
    const float* M = memory + hm * HD * HD;
    const float* Nm = norm_m + hm * HD * HD;

    for (int d0 = 0; d0 < 128; d0 += 32) {
        __syncthreads();
        for (int i = e; i < 32 * 128; i += 128) {
            int dd = i >> 7, ee = i & 127;
            Ms[dd][ee] = M[(d0 + dd) * HD + ee];
        }
        for (int i = e; i < 128 * 32; i += 128) {
            int ee = i >> 5, dd = i & 31;
            Ns[ee][dd] = Nm[ee * HD + d0 + dd];
        }
        __syncthreads();
#pragma unroll 4
        for (int dd = 0; dd < 32; dd++) {
            float mv = Ms[dd][e];
            float nv = Ns[e][dd];
#pragma unroll
            for (int r = 0; r < 16; r++) {
                float qv = Qs[r][d0 + dd];
                num[r] += qv * mv;
                den[r] += qv * nv;
            }
        }
    }
#pragma unroll
    for (int r = 0; r < 16; r++)
        memout[(size_t)(st * 16 + r) * HID + h * HD + e] = num[r] / (den[r] + EPS);
}

// ---------------- v - v_ret for delta rule (kv heads) ----------------
__global__ __launch_bounds__(128) void vdelta_kernel(
    const float* __restrict__ kn, const float* __restrict__ vproj,
    const float* __restrict__ memory, const float* __restrict__ norm_m,
    float* __restrict__ vdelta)
{
    const int h = blockIdx.y;   // 0..7
    const int st = blockIdx.x;
    const int e = threadIdx.x;
    __shared__ float Qs[16][128];
    __shared__ float Ms[32][128];
    __shared__ float Ns[128][33];

    for (int i = e; i < 16 * 128; i += 128) {
        int r = i >> 7, d = i & 127;
        Qs[r][d] = kn[(size_t)(st * 16 + r) * (NKV * HD) + h * HD + d];
    }
    float num[16], den[16];
#pragma unroll
    for (int r = 0; r < 16; r++) { num[r] = 0.f; den[r] = 0.f; }
    const float* M = memory + h * HD * HD;
    const float* Nm = norm_m + h * HD * HD;

    for (int d0 = 0; d0 < 128; d0 += 32) {
        __syncthreads();
        for (int i = e; i < 32 * 128; i += 128) {
            int dd = i >> 7, ee = i & 127;
            Ms[dd][ee] = M[(d0 + dd) * HD + ee];
        }
        for (int i = e; i < 128 * 32; i += 128) {
            int ee = i >> 5, dd = i & 31;
            Ns[ee][dd] = Nm[ee * HD + d0 + dd];
        }
        __syncthreads();
#pragma unroll 4
        for (int dd = 0; dd < 32; dd++) {
            float mv = Ms[dd][e];
            float nv = Ns[e][dd];
#pragma unroll
            for (int r = 0; r < 16; r++) {
                float qv = Qs[r][d0 + dd];
                num[r] += qv * mv;
                den[r] += qv * nv;
            }
        }
    }
#pragma unroll
    for (int r = 0; r < 16; r++) {
        size_t idx = (size_t)(st * 16 + r) * (NKV * HD) + h * HD + e;
        vdelta[idx] = vproj[idx] - num[r] / (den[r] + EPS);
    }
}

// ---------------- RoPE (in place on q_proj and k_proj, post qn/kn) ----------------
__global__ __launch_bounds__(256) void rope_kernel(
    float* __restrict__ q, float* __restrict__ k, const int* __restrict__ pos)
{
    const int s = blockIdx.x;
    const int idx = blockIdx.y * 256 + threadIdx.x;   // 0..2559
    if (idx >= (NH + NKV) * 64) return;
    const int head = idx >> 6;
    const int d = idx & 63;
    const float p = (float)pos[s];
    const float invf = expf(-(2.0f * (float)d / 128.0f) * LN10000);
    const float a = p * invf;
    const float c = cosf(a), sn = sinf(a);
    float* base = (head < NH) ? (q + (size_t)s * HID + head * HD)
                              : (k + (size_t)s * (NKV * HD) + (head - NH) * HD);
    float x0 = base[d], x1 = base[d + 64];
    base[d]      = x0 * c - x1 * sn;
    base[d + 64] = x1 * c + x0 * sn;
}

// ---------------- causal flash attention, fp32 ----------------
__global__ __launch_bounds__(128) void attn_kernel(
    const float* __restrict__ q, const float* __restrict__ k,
    const float* __restrict__ v, float* __restrict__ out)
{
    const int h = blockIdx.y;
    const int qt = gridDim.x - 1 - blockIdx.x;   // heavy tiles launch first
    const int kvh = h >> 2;
    const int t = threadIdx.x;
    __shared__ float Qs[32][128];
    __shared__ float KVs[32][129];
    __shared__ float P[32][33];
    __shared__ float sm_m[32], sm_l[32], sm_sc[32];

    for (int i = t; i < 32 * 128; i += 128) {
        int r = i >> 7, d = i & 127;
        Qs[r][d] = q[(size_t)(qt * 32 + r) * HID + h * HD + d];
    }
    if (t < 32) { sm_m[t] = -1e30f; sm_l[t] = 0.f; }
    float o_acc[32];
#pragma unroll
    for (int i = 0; i < 32; i++) o_acc[i] = 0.f;

    const int kjl = t & 31;
    const int qb = t >> 5;

    for (int kt = 0; kt <= qt; kt++) {
        __syncthreads();
        for (int i = t; i < 32 * 128; i += 128) {
            int r = i >> 7, d = i & 127;
            KVs[r][d] = k[(size_t)(kt * 32 + r) * (NKV * HD) + kvh * HD + d];
        }
        __syncthreads();
        float acc[8];
#pragma unroll
        for (int r = 0; r < 8; r++) acc[r] = 0.f;
#pragma unroll 4
        for (int d = 0; d < 128; d++) {
            float kv = KVs[kjl][d];
#pragma unroll
            for (int r = 0; r < 8; r++) acc[r] += Qs[r * 4 + qb][d] * kv;
        }
#pragma unroll
        for (int r = 0; r < 8; r++) {
            int qi = r * 4 + qb;
            float sc = acc[r] * ATT_SCALE;
            if (kt == qt && kjl > qi) sc = -1e30f;
            P[qi][kjl] = sc;
        }
        __syncthreads();
        if (t < 32) {
            float m_old = sm_m[t], mx = m_old;
#pragma unroll 8
            for (int j = 0; j < 32; j++) mx = fmaxf(mx, P[t][j]);
            float scl = expf(m_old - mx);
            float lsum = 0.f;
#pragma unroll 8
            for (int j = 0; j < 32; j++) {
                float pv = expf(P[t][j] - mx);
                P[t][j] = pv;
                lsum += pv;
            }
            sm_l[t] = sm_l[t] * scl + lsum;
            sm_m[t] = mx;
            sm_sc[t] = scl;
        }
        __syncthreads();
        for (int i = t; i < 32 * 128; i += 128) {
            int r = i >> 7, d = i & 127;
            KVs[r][d] = v[(size_t)(kt * 32 + r) * (NKV * HD) + kvh * HD + d];
        }
        __syncthreads();
#pragma unroll
        for (int qi = 0; qi < 32; qi++) o_acc[qi] *= sm_sc[qi];
        for (int kj = 0; kj < 32; kj++) {
            float vv = KVs[kj][t];
#pragma unroll
            for (int qi = 0; qi < 32; qi++) o_acc[qi] += P[qi][kj] * vv;
        }
    }
    __syncthreads();
#pragma unroll
    for (int qi = 0; qi < 32; qi++)
        out[(size_t)(qt * 32 + qi) * HID + h * HD + t] = o_acc[qi] / sm_l[qi];
}

// ---------------- sigmoid-gated combine ----------------
__global__ __launch_bounds__(256) void combine_kernel(
    const float* __restrict__ memout, const float* __restrict__ attnout,
    const float* __restrict__ beta, float* __restrict__ combined)
{
    const int i = blockIdx.x * 256 + threadIdx.x;
    const float g = 1.f / (1.f + expf(-beta[0]));
    combined[i] = g * memout[i] + (1.f - g) * attnout[i];
}

// ---------------- delta-rule memory update: out = memory + kn^T @ vdelta ----------------
__global__ __launch_bounds__(256) void delta_kernel(
    const float* __restrict__ kn, const float* __restrict__ vd,
    const float* __restrict__ memory, float* __restrict__ outmem)
{
    const int h = blockIdx.x;
    __shared__ float Ak[32][128];
    __shared__ float Bv[32][128];
    const int trow = (threadIdx.x >> 4) * 8;
    const int tcol = (threadIdx.x & 15) * 8;
    float acc[8][8];
#pragma unroll
    for (int i = 0; i < 8; i++)
#pragma unroll
        for (int j = 0; j < 8; j++) acc[i][j] = 0.f;

    for (int s0 = 0; s0 < S; s0 += 32) {
        for (int i = threadIdx.x; i < 32 * 128; i += 256) {
            int ss = i >> 7, dd = i & 127;
            size_t idx = (size_t)(s0 + ss) * (NKV * HD) + h * HD + dd;
            Ak[ss][dd] = kn[idx];
            Bv[ss][dd] = vd[idx];
        }
        __syncthreads();
#pragma unroll 4
        for (int ss = 0; ss < 32; ss++) {
            float ra[8], rb[8];
#pragma unroll
            for (int i = 0; i < 8; i++) ra[i] = Ak[ss][trow + i];
#pragma unroll
            for (int j = 0; j < 8; j++) rb[j] = Bv[ss][tcol + j];
#pragma unroll
            for (int i = 0; i < 8; i++)
#pragma unroll
                for (int j = 0; j < 8; j++) acc[i][j] += ra[i] * rb[j];
        }
        __syncthreads();
    }
    const float* Mh = memory + h * HD * HD;
    float* Oh = outmem + h * HD * HD;
#pragma unroll
    for (int i = 0; i < 8; i++)
#pragma unroll
        for (int j = 0; j < 8; j++) {
            int idx = (trow + i) * HD + tcol + j;
            Oh[idx] = Mh[idx] + acc[i][j];
        }
}

// ---------------- updated_norm ----------------
__global__ __launch_bounds__(256) void norm_kernel(
    const float* __restrict__ norm_m, const float* __restrict__ knsum, float* __restrict__ out)
{
    const int i = blockIdx.x * 256 + threadIdx.x;   // < 8*128*128
    const int h = i >> 14;
    const int j = i & 127;
    out[i] = norm_m[i] + knsum[h * HD + j];
}

// ---------------- launch ----------------
extern "C" void kernel_launch(void* const* d_in, const int* in_sizes, int n_in,
                              void* d_out, int out_size)
{
    const float* hidden = (const float*)d_in[0];
    const int*   pos    = (const int*)d_in[1];
    const float* wq     = (const float*)d_in[2];
    const float* wk     = (const float*)d_in[3];
    const float* wv     = (const float*)d_in[4];
    const float* wo     = (const float*)d_in[5];
    const float* memory = (const float*)d_in[6];
    const float* norm_m = (const float*)d_in[7];
    const float* beta   = (const float*)d_in[8];
    float* out = (float*)d_out;

    float *qproj, *kproj, *vproj, *qn, *kn, *memout, *attnout, *vdelta, *knsum, *knpart, *combined;
    cudaGetSymbolAddress((void**)&qproj, g_qproj);
    cudaGetSymbolAddress((void**)&kproj, g_kproj);
    cudaGetSymbolAddress((void**)&vproj, g_vproj);
    cudaGetSymbolAddress((void**)&qn, g_qn);
    cudaGetSymbolAddress((void**)&kn, g_kn);
    cudaGetSymbolAddress((void**)&memout, g_memout);
    cudaGetSymbolAddress((void**)&attnout, g_attnout);
    cudaGetSymbolAddress((void**)&vdelta, g_vdelta);
    cudaGetSymbolAddress((void**)&knsum, g_knsum);
    cudaGetSymbolAddress((void**)&knpart, g_knsum_part);
    cudaGetSymbolAddress((void**)&combined, g_combined);

    // projections (tf32 tensor cores). K/V fused via gridDim.z.
    gemm_tf32_kernel<<<dim3(HID / 128, S / 128, 1), 256>>>(hidden, wq, qproj, wq, qproj, HID, HID);
    gemm_tf32_kernel<<<dim3(NKV * HD / 128, S / 128, 2), 256>>>(hidden, wk, kproj, wv, vproj, NKV * HD, HID);

    // normalized features from PRE-RoPE q/k
    qn_kernel<<<S, 128>>>(qproj, qn);
    kn_kernel<<<S, 128>>>(kproj, kn);
    knsum_part_kernel<<<dim3(NKV, 16), 128>>>(kn, knpart);
    knsum_final_kernel<<<1, 1024>>>(knpart, knsum);

    // compressive-memory retrieval + delta-rule prep
    retrieve_kernel<<<dim3(S / 16, NH), 128>>>(qn, memory, norm_m, memout);
    vdelta_kernel<<<dim3(S / 16, NKV), 128>>>(kn, vproj, memory, norm_m, vdelta);

    // RoPE in place, then causal attention
    rope_kernel<<<dim3(S, 10), 256>>>(qproj, kproj, pos);
    attn_kernel<<<dim3(S / 32, NH), 128>>>(qproj, kproj, vproj, attnout);

    // gated combine + output projection (tf32)
    combine_kernel<<<(S * HID) / 256, 256>>>(memout, attnout, beta, combined);
    gemm_tf32_kernel<<<dim3(HID / 128, S / 128, 1), 256>>>(combined, wo, out, wo, out, HID, HID);

    // memory & norm updates (appended after the 8.4M-element `out`)
    delta_kernel<<<NKV, 256>>>(kn, vdelta, memory, out + (size_t)S * HID);
    norm_kernel<<<(NKV * HD * HD) / 256, 256>>>(norm_m, knsum,
                                                out + (size_t)S * HID + NKV * HD * HD);
}

// round 4
// speedup vs baseline: 2.2932x; 1.4569x over previous
#include <cuda_runtime.h>
#include <cuda_bf16.h>
#include <math.h>
#include <stdint.h>

// ---------------- problem constants ----------------
#define S 2048
#define HID 4096
#define NH 32
#define NKV 8
#define HD 128
#define GROUPS 4
#define EPS 1e-8f
#define ATT_SCALE 0.08838834764831845f   // 128^-0.5
#define LN10000 9.210340371976184f

// ---------------- scratch (device globals; no allocation allowed) ----------------
__device__ float g_qproj[S * HID];        // [s][h*128+d]
__device__ float g_kproj[S * NKV * HD];   // [s][kv*128+d]
__device__ float g_vproj[S * NKV * HD];
__device__ float g_qn[S * HID];
__device__ float g_kn[S * NKV * HD];
__device__ float g_memout[S * HID];
__device__ float g_vdelta[S * NKV * HD];
__device__ float g_knsum[NKV * HD];
__device__ float g_knsum_part[16][NKV * HD];
__device__ float g_combined[S * HID];
__device__ float g_delta_part[8][NKV * HD * HD];   // 8 s-chunks of partial kn^T@vd

// ---------------- tf32 helpers ----------------
__device__ __forceinline__ uint32_t f2tf32(float x) {
    uint32_t y;
    asm("cvt.rna.tf32.f32 %0, %1;" : "=r"(y) : "f"(x));
    return y;
}
__device__ __forceinline__ float f2tf32f(float x) {
    return __uint_as_float(f2tf32(x));
}
__device__ __forceinline__ void split_tf32(float f, uint32_t& hi, uint32_t& lo) {
    hi = f2tf32(f);
    lo = f2tf32(f - __uint_as_float(hi));
}

__device__ __forceinline__ void mma_tf32(
    float& c0, float& c1, float& c2, float& c3,
    uint32_t a0, uint32_t a1, uint32_t a2, uint32_t a3,
    uint32_t b0, uint32_t b1)
{
    asm volatile(
        "mma.sync.aligned.m16n8k8.row.col.f32.tf32.tf32.f32 "
        "{%0,%1,%2,%3},{%4,%5,%6,%7},{%8,%9},{%0,%1,%2,%3};"
        : "+f"(c0), "+f"(c1), "+f"(c2), "+f"(c3)
        : "r"(a0), "r"(a1), "r"(a2), "r"(a3), "r"(b0), "r"(b1));
}

// ---------------- tf32 tensor-core GEMM (unchanged from R3) ----------------
#define GPAD 132
__global__ __launch_bounds__(256) void gemm_tf32_kernel(
    const float* __restrict__ A,
    const float* __restrict__ B0, float* __restrict__ C0,
    const float* __restrict__ B1, float* __restrict__ C1,
    int N, int K)
{
    const float* B = (blockIdx.z == 0) ? B0 : B1;
    float* C = (blockIdx.z == 0) ? C0 : C1;

    __shared__ float As[2][16][GPAD];
    __shared__ float Bs[2][16][GPAD];

    const int tid = threadIdx.x;
    const int lane = tid & 31;
    const int wid = tid >> 5;
    const int wm = wid >> 2;
    const int wn = wid & 3;
    const int lr = lane >> 2;
    const int lc = lane & 3;

    const int by = blockIdx.y;
    const int bx = blockIdx.x;

    const int am = tid >> 1;
    const int ak = (tid & 1) * 8;
    const int bk = tid >> 4;
    const int bn = (tid & 15) * 8;

    const float* Ag = A + (size_t)(by * 128 + am) * K + ak;
    const float* Bg = B + (size_t)bk * N + bx * 128 + bn;

    float acc[4][4][4];
#pragma unroll
    for (int i = 0; i < 4; i++)
#pragma unroll
        for (int j = 0; j < 4; j++)
#pragma unroll
            for (int r = 0; r < 4; r++) acc[i][j][r] = 0.f;

    const int NT = K / 16;

    {
        float4 ra0 = *(const float4*)(Ag);
        float4 ra1 = *(const float4*)(Ag + 4);
        float4 rb0 = *(const float4*)(Bg);
        float4 rb1 = *(const float4*)(Bg + 4);
        As[0][ak + 0][am] = f2tf32f(ra0.x);
        As[0][ak + 1][am] = f2tf32f(ra0.y);
        As[0][ak + 2][am] = f2tf32f(ra0.z);
        As[0][ak + 3][am] = f2tf32f(ra0.w);
        As[0][ak + 4][am] = f2tf32f(ra1.x);
        As[0][ak + 5][am] = f2tf32f(ra1.y);
        As[0][ak + 6][am] = f2tf32f(ra1.z);
        As[0][ak + 7][am] = f2tf32f(ra1.w);
        float4 tb0 = make_float4(f2tf32f(rb0.x), f2tf32f(rb0.y), f2tf32f(rb0.z), f2tf32f(rb0.w));
        float4 tb1 = make_float4(f2tf32f(rb1.x), f2tf32f(rb1.y), f2tf32f(rb1.z), f2tf32f(rb1.w));
        *(float4*)(&Bs[0][bk][bn]) = tb0;
        *(float4*)(&Bs[0][bk][bn + 4]) = tb1;
    }
    __syncthreads();

    for (int it = 0; it < NT; it++) {
        const int cur = it & 1;
        float4 na0, na1, nb0, nb1;
        const bool more = (it + 1 < NT);
        if (more) {
            const float* Ap = Ag + (size_t)(it + 1) * 16;
            const float* Bp = Bg + (size_t)(it + 1) * 16 * N;
            na0 = *(const float4*)(Ap);
            na1 = *(const float4*)(Ap + 4);
            nb0 = *(const float4*)(Bp);
            nb1 = *(const float4*)(Bp + 4);
        }

#pragma unroll
        for (int ks = 0; ks < 2; ks++) {
            const int kb = ks * 8;
            uint32_t af[4][4], bf[4][2];
#pragma unroll
            for (int mt = 0; mt < 4; mt++) {
                const int m0 = wm * 64 + mt * 16 + lr;
                af[mt][0] = __float_as_uint(As[cur][kb + lc][m0]);
                af[mt][1] = __float_as_uint(As[cur][kb + lc][m0 + 8]);
                af[mt][2] = __float_as_uint(As[cur][kb + 4 + lc][m0]);
                af[mt][3] = __float_as_uint(As[cur][kb + 4 + lc][m0 + 8]);
            }
#pragma unroll
            for (int nt = 0; nt < 4; nt++) {
                const int n0 = wn * 32 + nt * 8 + lr;
                bf[nt][0] = __float_as_uint(Bs[cur][kb + lc][n0]);
                bf[nt][1] = __float_as_uint(Bs[cur][kb + 4 + lc][n0]);
            }
#pragma unroll
            for (int mt = 0; mt < 4; mt++)
#pragma unroll
                for (int nt = 0; nt < 4; nt++)
                    mma_tf32(acc[mt][nt][0], acc[mt][nt][1], acc[mt][nt][2], acc[mt][nt][3],
                             af[mt][0], af[mt][1], af[mt][2], af[mt][3],
                             bf[nt][0], bf[nt][1]);
        }

        if (more) {
            const int nxt = cur ^ 1;
            As[nxt][ak + 0][am] = f2tf32f(na0.x);
            As[nxt][ak + 1][am] = f2tf32f(na0.y);
            As[nxt][ak + 2][am] = f2tf32f(na0.z);
            As[nxt][ak + 3][am] = f2tf32f(na0.w);
            As[nxt][ak + 4][am] = f2tf32f(na1.x);
            As[nxt][ak + 5][am] = f2tf32f(na1.y);
            As[nxt][ak + 6][am] = f2tf32f(na1.z);
            As[nxt][ak + 7][am] = f2tf32f(na1.w);
            float4 tb0 = make_float4(f2tf32f(nb0.x), f2tf32f(nb0.y), f2tf32f(nb0.z), f2tf32f(nb0.w));
            float4 tb1 = make_float4(f2tf32f(nb1.x), f2tf32f(nb1.y), f2tf32f(nb1.z), f2tf32f(nb1.w));
            *(float4*)(&Bs[nxt][bk][bn]) = tb0;
            *(float4*)(&Bs[nxt][bk][bn + 4]) = tb1;
        }
        __syncthreads();
    }

#pragma unroll
    for (int mt = 0; mt < 4; mt++) {
        const int row = by * 128 + wm * 64 + mt * 16 + lr;
#pragma unroll
        for (int nt = 0; nt < 4; nt++) {
            const int col = bx * 128 + wn * 32 + nt * 8 + lc * 2;
            float2 v01 = make_float2(acc[mt][nt][0], acc[mt][nt][1]);
            float2 v23 = make_float2(acc[mt][nt][2], acc[mt][nt][3]);
            *(float2*)(C + (size_t)row * N + col) = v01;
            *(float2*)(C + (size_t)(row + 8) * N + col) = v23;
        }
    }
}

// ---------------- qn / kn ----------------
__global__ __launch_bounds__(128) void qn_kernel(const float* __restrict__ qp, float* __restrict__ qn)
{
    const int s = blockIdx.x;
    const int d = threadIdx.x;
    __shared__ float wsum[4];
    for (int h = 0; h < NH; h++) {
        float x = qp[(size_t)s * HID + h * HD + d];
        float f = x > 0.f ? x + 1.f : expf(x);
        float v = f;
#pragma unroll
        for (int o = 16; o; o >>= 1) v += __shfl_xor_sync(0xffffffffu, v, o);
        if ((d & 31) == 0) wsum[d >> 5] = v;
        __syncthreads();
        float tot = wsum[0] + wsum[1] + wsum[2] + wsum[3];
        qn[(size_t)s * HID + h * HD + d] = f / (tot + EPS);
        __syncthreads();
    }
}

__global__ __launch_bounds__(128) void kn_kernel(const float* __restrict__ kp, float* __restrict__ kn)
{
    const int s = blockIdx.x;
    const int d = threadIdx.x;
    __shared__ float wsum[4];
    for (int h = 0; h < NKV; h++) {
        float x = kp[(size_t)s * (NKV * HD) + h * HD + d];
        float f = x > 0.f ? x + 1.f : expf(x);
        float v = f;
#pragma unroll
        for (int o = 16; o; o >>= 1) v += __shfl_xor_sync(0xffffffffu, v, o);
        if ((d & 31) == 0) wsum[d >> 5] = v;
        __syncthreads();
        float tot = wsum[0] + wsum[1] + wsum[2] + wsum[3];
        kn[(size_t)s * (NKV * HD) + h * HD + d] = f / (tot + EPS);
        __syncthreads();
    }
}

// knsum two-pass deterministic reduction
__global__ __launch_bounds__(128) void knsum_part_kernel(const float* __restrict__ kn, float* __restrict__ part)
{
    const int h = blockIdx.x;
    const int p = blockIdx.y;
    const int d = threadIdx.x;
    float acc = 0.f;
    const int s0 = p * 128;
#pragma unroll 4
    for (int s = s0; s < s0 + 128; s++)
        acc += kn[(size_t)s * (NKV * HD) + h * HD + d];
    part[p * (NKV * HD) + h * HD + d] = acc;
}

__global__ __launch_bounds__(1024) void knsum_final_kernel(const float* __restrict__ part, float* __restrict__ knsum)
{
    const int i = threadIdx.x;
    float acc = 0.f;
#pragma unroll
    for (int p = 0; p < 16; p++) acc += part[p * (NKV * HD) + i];
    knsum[i] = acc;
}

// ---------------- memory retrieval ----------------
__global__ __launch_bounds__(128) void retrieve_kernel(
    const float* __restrict__ qn, const float* __restrict__ memory,
    const float* __restrict__ norm_m, float* __restrict__ memout)
{
    const int h = blockIdx.y;
    const int st = blockIdx.x;
    const int hm = h & (NKV - 1);
    const int e = threadIdx.x;
    __shared__ float Qs[16][128];
    __shared__ float Ms[32][128];
    __shared__ float Ns[128][33];

    for (int i = e; i < 16 * 128; i += 128) {
        int r = i >> 7, d = i & 127;
        Qs[r][d] = qn[(size_t)(st * 16 + r) * HID + h * HD + d];
    }
    float num[16], den[16];
#pragma unroll
    for (int r = 0; r < 16; r++) { num[r] = 0.f; den[r] = 0.f; }
    const float* M = memory + hm * HD * HD;
    const float* Nm = norm_m + hm * HD * HD;

    for (int d0 = 0; d0 < 128; d0 += 32) {
        __syncthreads();
        for (int i = e; i < 32 * 128; i += 128) {
            int dd = i >> 7, ee = i & 127;
            Ms[dd][ee] = M[(d0 + dd) * HD + ee];
        }
        for (int i = e; i < 128 * 32; i += 128) {
            int ee = i >> 5, dd = i & 31;
            Ns[ee][dd] = Nm[ee * HD + d0 + dd];
        }
        __syncthreads();
#pragma unroll 4
        for (int dd = 0; dd < 32; dd++) {
            float mv = Ms[dd][e];
            float nv = Ns[e][dd];
#pragma unroll
            for (int r = 0; r < 16; r++) {
                float qv = Qs[r][d0 + dd];
                num[r] += qv * mv;
                den[r] += qv * nv;
            }
        }
    }
#pragma unroll
    for (int r = 0; r < 16; r++)
        memout[(size_t)(st * 16 + r) * HID + h * HD + e] = num[r] / (den[r] + EPS);
}

// ---------------- v - v_ret for delta rule ----------------
__global__ __launch_bounds__(128) void vdelta_kernel(
    const float* __restrict__ kn, const float* __restrict__ vproj,
    const float* __restrict__ memory, const float* __restrict__ norm_m,
    float* __restrict__ vdelta)
{
    const int h = blockIdx.y;
    const int st = blockIdx.x;
    const int e = threadIdx.x;
    __shared__ float Qs[16][128];
    __shared__ float Ms[32][128];
    __shared__ float Ns[128][33];

    for (int i = e; i < 16 * 128; i += 128) {
        int r = i >> 7, d = i & 127;
        Qs[r][d] = kn[(size_t)(st * 16 + r) * (NKV * HD) + h * HD + d];
    }
    float num[16], den[16];
#pragma unroll
    for (int r = 0; r < 16; r++) { num[r] = 0.f; den[r] = 0.f; }
    const float* M = memory + h * HD * HD;
    const float* Nm = norm_m + h * HD * HD;

    for (int d0 = 0; d0 < 128; d0 += 32) {
        __syncthreads();
        for (int i = e; i < 32 * 128; i += 128) {
            int dd = i >> 7, ee = i & 127;
            Ms[dd][ee] = M[(d0 + dd) * HD + ee];
        }
        for (int i = e; i < 128 * 32; i += 128) {
            int ee = i >> 5, dd = i & 31;
            Ns[ee][dd] = Nm[ee * HD + d0 + dd];
        }
        __syncthreads();
#pragma unroll 4
        for (int dd = 0; dd < 32; dd++) {
            float mv = Ms[dd][e];
            float nv = Ns[e][dd];
#pragma unroll
            for (int r = 0; r < 16; r++) {
                float qv = Qs[r][d0 + dd];
                num[r] += qv * mv;
                den[r] += qv * nv;
            }
        }
    }
#pragma unroll
    for (int r = 0; r < 16; r++) {
        size_t idx = (size_t)(st * 16 + r) * (NKV * HD) + h * HD + e;
        vdelta[idx] = vproj[idx] - num[r] / (den[r] + EPS);
    }
}

// ---------------- RoPE ----------------
__global__ __launch_bounds__(256) void rope_kernel(
    float* __restrict__ q, float* __restrict__ k, const int* __restrict__ pos)
{
    const int s = blockIdx.x;
    const int idx = blockIdx.y * 256 + threadIdx.x;
    if (idx >= (NH + NKV) * 64) return;
    const int head = idx >> 6;
    const int d = idx & 63;
    const float p = (float)pos[s];
    const float invf = expf(-(2.0f * (float)d / 128.0f) * LN10000);
    const float a = p * invf;
    const float c = cosf(a), sn = sinf(a);
    float* base = (head < NH) ? (q + (size_t)s * HID + head * HD)
                              : (k + (size_t)s * (NKV * HD) + (head - NH) * HD);
    float x0 = base[d], x1 = base[d + 64];
    base[d]      = x0 * c - x1 * sn;
    base[d + 64] = x1 * c + x0 * sn;
}

// ---------------- MMA flash attention (3x-split tf32, fp32-accurate) ----------------
// Bq=128, Bk=64, 8 warps (256 thr). Warp w owns query rows w*16..w*16+15.
// Fuses sigmoid-gated combine: outc = g*memout + (1-g)*attn.
#define QS_STR 132
#define KS_STR 132
#define VS_STR 136
#define PS_STR 68
#define ATT_SMEM_FLOATS (128 * QS_STR + 64 * KS_STR + 64 * VS_STR + 128 * PS_STR)
#define ATT_SMEM_BYTES (ATT_SMEM_FLOATS * 4)

__global__ __launch_bounds__(256) void attn_mma_kernel(
    const float* __restrict__ q, const float* __restrict__ k,
    const float* __restrict__ v, const float* __restrict__ memout,
    const float* __restrict__ beta, float* __restrict__ outc)
{
    const int h = blockIdx.y;
    const int qt = (int)gridDim.x - 1 - (int)blockIdx.x;   // heavy tiles first
    const int kvh = h >> 2;
    const int tid = threadIdx.x;
    const int warp = tid >> 5;
    const int lane = tid & 31;
    const int lr = lane >> 2;   // 0..7
    const int lc = lane & 3;    // 0..3

    extern __shared__ float smem[];
    float* Qs = smem;                        // [128][QS_STR]
    float* Ks = Qs + 128 * QS_STR;           // [64][KS_STR]
    float* Vs = Ks + 64 * KS_STR;            // [64][VS_STR]
    float* Ps = Vs + 64 * VS_STR;            // [128][PS_STR]

    // load Q tile (fp32)
#pragma unroll
    for (int it = 0; it < 16; it++) {
        int i = it * 256 + tid;
        int row = i >> 5, c4 = (i & 31) * 4;
        float4 t = *(const float4*)(q + (size_t)(qt * 128 + row) * HID + h * HD + c4);
        *(float4*)(Qs + row * QS_STR + c4) = t;
    }

    const int row0 = warp * 16 + lr;
    const int row1 = row0 + 8;
    const int grow0 = qt * 128 + row0;
    const int grow1 = grow0 + 8;

    float m0 = -1e30f, m1 = -1e30f, l0 = 0.f, l1 = 0.f;
    float o[16][4];
#pragma unroll
    for (int nt = 0; nt < 16; nt++)
#pragma unroll
        for (int r = 0; r < 4; r++) o[nt][r] = 0.f;

    const int ktmax = 2 * qt + 1;
    for (int kt = 0; kt <= ktmax; kt++) {
        __syncthreads();   // previous iter's K/V/P consumed
        // load K,V tiles (fp32, coalesced)
#pragma unroll
        for (int it = 0; it < 8; it++) {
            int i = it * 256 + tid;
            int key = i >> 5, c4 = (i & 31) * 4;
            size_t gidx = (size_t)(kt * 64 + key) * (NKV * HD) + kvh * HD + c4;
            float4 tk = *(const float4*)(k + gidx);
            *(float4*)(Ks + key * KS_STR + c4) = tk;
            float4 tv = *(const float4*)(v + gidx);
            *(float4*)(Vs + key * VS_STR + c4) = tv;
        }
        __syncthreads();

        // ---- scores S = Q K^T (3x tf32) ----
        float sc[8][4];
#pragma unroll
        for (int nt = 0; nt < 8; nt++)
#pragma unroll
            for (int r = 0; r < 4; r++) sc[nt][r] = 0.f;

#pragma unroll
        for (int ks = 0; ks < 16; ks++) {
            const int d0 = ks * 8;
            uint32_t ah[4], al[4];
            split_tf32(Qs[row0 * QS_STR + d0 + lc],     ah[0], al[0]);
            split_tf32(Qs[row1 * QS_STR + d0 + lc],     ah[1], al[1]);
            split_tf32(Qs[row0 * QS_STR + d0 + lc + 4], ah[2], al[2]);
            split_tf32(Qs[row1 * QS_STR + d0 + lc + 4], ah[3], al[3]);
#pragma unroll
            for (int nt = 0; nt < 8; nt++) {
                uint32_t bh0, bl0, bh1, bl1;
                split_tf32(Ks[(nt * 8 + lr) * KS_STR + d0 + lc],     bh0, bl0);
                split_tf32(Ks[(nt * 8 + lr) * KS_STR + d0 + lc + 4], bh1, bl1);
                mma_tf32(sc[nt][0], sc[nt][1], sc[nt][2], sc[nt][3],
                         ah[0], ah[1], ah[2], ah[3], bh0, bh1);
                mma_tf32(sc[nt][0], sc[nt][1], sc[nt][2], sc[nt][3],
                         ah[0], ah[1], ah[2], ah[3], bl0, bl1);
                mma_tf32(sc[nt][0], sc[nt][1], sc[nt][2], sc[nt][3],
                         al[0], al[1], al[2], al[3], bh0, bh1);
            }
        }

        // ---- online softmax (fp32) ----
        const bool need_mask = (kt >= 2 * qt);
        float mx0 = -1e30f, mx1 = -1e30f;
#pragma unroll
        for (int nt = 0; nt < 8; nt++) {
#pragma unroll
            for (int j = 0; j < 2; j++) {
                int col = kt * 64 + nt * 8 + 2 * lc + j;
                float s0 = sc[nt][j] * ATT_SCALE;
                float s1 = sc[nt][2 + j] * ATT_SCALE;
                if (need_mask) {
                    if (col > grow0) s0 = -1e30f;
                    if (col > grow1) s1 = -1e30f;
                }
                sc[nt][j] = s0;
                sc[nt][2 + j] = s1;
                mx0 = fmaxf(mx0, s0);
                mx1 = fmaxf(mx1, s1);
            }
        }
        mx0 = fmaxf(mx0, __shfl_xor_sync(0xffffffffu, mx0, 1));
        mx0 = fmaxf(mx0, __shfl_xor_sync(0xffffffffu, mx0, 2));
        mx1 = fmaxf(mx1, __shfl_xor_sync(0xffffffffu, mx1, 1));
        mx1 = fmaxf(mx1, __shfl_xor_sync(0xffffffffu, mx1, 2));
        const float mn0 = fmaxf(m0, mx0);
        const float mn1 = fmaxf(m1, mx1);
        const float scl0 = __expf(m0 - mn0);
        const float scl1 = __expf(m1 - mn1);
        float ls0 = 0.f, ls1 = 0.f;
#pragma unroll
        for (int nt = 0; nt < 8; nt++) {
#pragma unroll
            for (int j = 0; j < 2; j++) {
                float p0 = __expf(sc[nt][j] - mn0);
                float p1 = __expf(sc[nt][2 + j] - mn1);
                ls0 += p0;
                ls1 += p1;
                Ps[row0 * PS_STR + nt * 8 + 2 * lc + j] = p0;
                Ps[row1 * PS_STR + nt * 8 + 2 * lc + j] = p1;
            }
        }
        ls0 += __shfl_xor_sync(0xffffffffu, ls0, 1);
        ls0 += __shfl_xor_sync(0xffffffffu, ls0, 2);
        ls1 += __shfl_xor_sync(0xffffffffu, ls1, 1);
        ls1 += __shfl_xor_sync(0xffffffffu, ls1, 2);
        l0 = l0 * scl0 + ls0;
        l1 = l1 * scl1 + ls1;
        m0 = mn0;
        m1 = mn1;

        // rescale accumulators
#pragma unroll
        for (int nt = 0; nt < 16; nt++) {
            o[nt][0] *= scl0;
            o[nt][1] *= scl0;
            o[nt][2] *= scl1;
            o[nt][3] *= scl1;
        }
        __syncwarp();   // P rows of this warp visible to all its lanes

        // ---- O += P V (3x tf32) ----
#pragma unroll
        for (int ks2 = 0; ks2 < 8; ks2++) {
            const int k0 = ks2 * 8;
            uint32_t ah[4], al[4];
            split_tf32(Ps[row0 * PS_STR + k0 + lc],     ah[0], al[0]);
            split_tf32(Ps[row1 * PS_STR + k0 + lc],     ah[1], al[1]);
            split_tf32(Ps[row0 * PS_STR + k0 + lc + 4], ah[2], al[2]);
            split_tf32(Ps[row1 * PS_STR + k0 + lc + 4], ah[3], al[3]);
#pragma unroll
            for (int nt = 0; nt < 16; nt++) {
                uint32_t bh0, bl0, bh1, bl1;
                split_tf32(Vs[(k0 + lc) * VS_STR + nt * 8 + lr],       bh0, bl0);
                split_tf32(Vs[(k0 + 4 + lc) * VS_STR + nt * 8 + lr],   bh1, bl1);
                mma_tf32(o[nt][0], o[nt][1], o[nt][2], o[nt][3],
                         ah[0], ah[1], ah[2], ah[3], bh0, bh1);
                mma_tf32(o[nt][0], o[nt][1], o[nt][2], o[nt][3],
                         ah[0], ah[1], ah[2], ah[3], bl0, bl1);
                mma_tf32(o[nt][0], o[nt][1], o[nt][2], o[nt][3],
                         al[0], al[1], al[2], al[3], bh0, bh1);
            }
        }
    }

    // ---- epilogue: gate-combine with memout ----
    const float g = 1.f / (1.f + __expf(-beta[0]));
    const float og = 1.f - g;
    const float li0 = 1.f / l0;
    const float li1 = 1.f / l1;
#pragma unroll
    for (int nt = 0; nt < 16; nt++) {
        const int col = nt * 8 + 2 * lc;
        size_t i0 = (size_t)grow0 * HID + h * HD + col;
        size_t i1 = (size_t)grow1 * HID + h * HD + col;
        float2 mo0 = *(const float2*)(memout + i0);
        float2 mo1 = *(const float2*)(memout + i1);
        float2 r0, r1;
        r0.x = g * mo0.x + og * (o[nt][0] * li0);
        r0.y = g * mo0.y + og * (o[nt][1] * li0);
        r1.x = g * mo1.x + og * (o[nt][2] * li1);
        r1.y = g * mo1.y + og * (o[nt][3] * li1);
        *(float2*)(outc + i0) = r0;
        *(float2*)(outc + i1) = r1;
    }
}

// ---------------- delta-rule partials: part[c] = kn[c-chunk]^T @ vd[c-chunk] ----------------
__global__ __launch_bounds__(256) void delta_part_kernel(
    const float* __restrict__ kn, const float* __restrict__ vd, float* __restrict__ part)
{
    const int h = blockIdx.x;
    const int c = blockIdx.y;
    __shared__ float Ak[32][128];
    __shared__ float Bv[32][128];
    const int trow = (threadIdx.x >> 4) * 8;
    const int tcol = (threadIdx.x & 15) * 8;
    float acc[8][8];
#pragma unroll
    for (int i = 0; i < 8; i++)
#pragma unroll
        for (int j = 0; j < 8; j++) acc[i][j] = 0.f;

    const int sbeg = c * 256;
    for (int s0 = sbeg; s0 < sbeg + 256; s0 += 32) {
        for (int i = threadIdx.x; i < 32 * 128; i += 256) {
            int ss = i >> 7, dd = i & 127;
            size_t idx = (size_t)(s0 + ss) * (NKV * HD) + h * HD + dd;
            Ak[ss][dd] = kn[idx];
            Bv[ss][dd] = vd[idx];
        }
        __syncthreads();
#pragma unroll 4
        for (int ss = 0; ss < 32; ss++) {
            float ra[8], rb[8];
#pragma unroll
            for (int i = 0; i < 8; i++) ra[i] = Ak[ss][trow + i];
#pragma unroll
            for (int j = 0; j < 8; j++) rb[j] = Bv[ss][tcol + j];
#pragma unroll
            for (int i = 0; i < 8; i++)
#pragma unroll
                for (int j = 0; j < 8; j++) acc[i][j] += ra[i] * rb[j];
        }
        __syncthreads();
    }
    float* Ph = part + (size_t)c * (NKV * HD * HD) + h * HD * HD;
#pragma unroll
    for (int i = 0; i < 8; i++)
#pragma unroll
        for (int j = 0; j < 8; j++)
            Ph[(trow + i) * HD + tcol + j] = acc[i][j];
}

__global__ __launch_bounds__(256) void delta_final_kernel(
    const float* __restrict__ part, const float* __restrict__ memory, float* __restrict__ outmem)
{
    const int i = blockIdx.x * 256 + threadIdx.x;   // < NKV*HD*HD
    float acc = memory[i];
#pragma unroll
    for (int c = 0; c < 8; c++) acc += part[(size_t)c * (NKV * HD * HD) + i];
    outmem[i] = acc;
}

// ---------------- updated_norm ----------------
__global__ __launch_bounds__(256) void norm_kernel(
    const float* __restrict__ norm_m, const float* __restrict__ knsum, float* __restrict__ out)
{
    const int i = blockIdx.x * 256 + threadIdx.x;
    const int h = i >> 14;
    const int j = i & 127;
    out[i] = norm_m[i] + knsum[h * HD + j];
}

// ---------------- launch ----------------
extern "C" void kernel_launch(void* const* d_in, const int* in_sizes, int n_in,
                              void* d_out, int out_size)
{
    const float* hidden = (const float*)d_in[0];
    const int*   pos    = (const int*)d_in[1];
    const float* wq     = (const float*)d_in[2];
    const float* wk     = (const float*)d_in[3];
    const float* wv     = (const float*)d_in[4];
    const float* wo     = (const float*)d_in[5];
    const float* memory = (const float*)d_in[6];
    const float* norm_m = (const float*)d_in[7];
    const float* beta   = (const float*)d_in[8];
    float* out = (float*)d_out;

    float *qproj, *kproj, *vproj, *qn, *kn, *memout, *vdelta, *knsum, *knpart, *combined, *dpart;
    cudaGetSymbolAddress((void**)&qproj, g_qproj);
    cudaGetSymbolAddress((void**)&kproj, g_kproj);
    cudaGetSymbolAddress((void**)&vproj, g_vproj);
    cudaGetSymbolAddress((void**)&qn, g_qn);
    cudaGetSymbolAddress((void**)&kn, g_kn);
    cudaGetSymbolAddress((void**)&memout, g_memout);
    cudaGetSymbolAddress((void**)&vdelta, g_vdelta);
    cudaGetSymbolAddress((void**)&knsum, g_knsum);
    cudaGetSymbolAddress((void**)&knpart, g_knsum_part);
    cudaGetSymbolAddress((void**)&combined, g_combined);
    cudaGetSymbolAddress((void**)&dpart, g_delta_part);

    cudaFuncSetAttribute(attn_mma_kernel,
                         cudaFuncAttributeMaxDynamicSharedMemorySize, ATT_SMEM_BYTES);

    // projections (tf32 tensor cores). K/V fused via gridDim.z.
    gemm_tf32_kernel<<<dim3(HID / 128, S / 128, 1), 256>>>(hidden, wq, qproj, wq, qproj, HID, HID);
    gemm_tf32_kernel<<<dim3(NKV * HD / 128, S / 128, 2), 256>>>(hidden, wk, kproj, wv, vproj, NKV * HD, HID);

    // normalized features from PRE-RoPE q/k
    qn_kernel<<<S, 128>>>(qproj, qn);
    kn_kernel<<<S, 128>>>(kproj, kn);
    knsum_part_kernel<<<dim3(NKV, 16), 128>>>(kn, knpart);
    knsum_final_kernel<<<1, 1024>>>(knpart, knsum);

    // compressive-memory retrieval + delta-rule prep
    retrieve_kernel<<<dim3(S / 16, NH), 128>>>(qn, memory, norm_m, memout);
    vdelta_kernel<<<dim3(S / 16, NKV), 128>>>(kn, vproj, memory, norm_m, vdelta);

    // RoPE in place, then MMA flash attention (fuses gated combine)
    rope_kernel<<<dim3(S, 10), 256>>>(qproj, kproj, pos);
    attn_mma_kernel<<<dim3(S / 128, NH), 256, ATT_SMEM_BYTES>>>(
        qproj, kproj, vproj, memout, beta, combined);

    // output projection (tf32)
    gemm_tf32_kernel<<<dim3(HID / 128, S / 128, 1), 256>>>(combined, wo, out, wo, out, HID, HID);

    // memory & norm updates (appended after the 8.4M-element `out`)
    delta_part_kernel<<<dim3(NKV, 8), 256>>>(kn, vdelta, dpart);
    delta_final_kernel<<<(NKV * HD * HD) / 256, 256>>>(dpart, memory, out + (size_t)S * HID);
    norm_kernel<<<(NKV * HD * HD) / 256, 256>>>(norm_m, knsum,
                                                out + (size_t)S * HID + NKV * HD * HD);
}

// round 5
// speedup vs baseline: 2.7249x; 1.1883x over previous
#include <cuda_runtime.h>
#include <cuda_bf16.h>
#include <math.h>
#include <stdint.h>

// ---------------- problem constants ----------------
#define S 2048
#define HID 4096
#define NH 32
#define NKV 8
#define HD 128
#define GROUPS 4
#define EPS 1e-8f
#define ATT_SCALE 0.08838834764831845f   // 128^-0.5
#define LN10000 9.210340371976184f

// ---------------- scratch (device globals; no allocation allowed) ----------------
__device__ float g_qproj[S * HID];
__device__ float g_kproj[S * NKV * HD];
__device__ float g_vproj[S * NKV * HD];
__device__ float g_qn[S * HID];
__device__ float g_kn[S * NKV * HD];
__device__ float g_memout[S * HID];
__device__ float g_vdelta[S * NKV * HD];
__device__ float g_knsum[NKV * HD];
__device__ float g_knsum_part[16][NKV * HD];
__device__ float g_combined[S * HID];
__device__ float g_delta_part[8][NKV * HD * HD];
// tf32-pre-rounded copies of GEMM inputs
__device__ float g_hid_r[S * HID];
__device__ float g_wq_r[HID * HID];
__device__ float g_wk_r[HID * NKV * HD];
__device__ float g_wv_r[HID * NKV * HD];
__device__ float g_wo_r[HID * HID];

// ---------------- tf32 helpers ----------------
__device__ __forceinline__ uint32_t f2tf32(float x) {
    uint32_t y;
    asm("cvt.rna.tf32.f32 %0, %1;" : "=r"(y) : "f"(x));
    return y;
}
__device__ __forceinline__ float f2tf32f(float x) {
    return __uint_as_float(f2tf32(x));
}
__device__ __forceinline__ void split_tf32(float f, uint32_t& hi, uint32_t& lo) {
    hi = f2tf32(f);
    lo = f2tf32(f - __uint_as_float(hi));
}

__device__ __forceinline__ void mma_tf32(
    float& c0, float& c1, float& c2, float& c3,
    uint32_t a0, uint32_t a1, uint32_t a2, uint32_t a3,
    uint32_t b0, uint32_t b1)
{
    asm volatile(
        "mma.sync.aligned.m16n8k8.row.col.f32.tf32.tf32.f32 "
        "{%0,%1,%2,%3},{%4,%5,%6,%7},{%8,%9},{%0,%1,%2,%3};"
        : "+f"(c0), "+f"(c1), "+f"(c2), "+f"(c3)
        : "r"(a0), "r"(a1), "r"(a2), "r"(a3), "r"(b0), "r"(b1));
}

// ---------------- elementwise tf32 pre-round (float4 vectorized) ----------------
__global__ __launch_bounds__(256) void round4_kernel(
    const float* __restrict__ src, float* __restrict__ dst, int n4)
{
    for (int i = blockIdx.x * 256 + threadIdx.x; i < n4; i += gridDim.x * 256) {
        float4 v = ((const float4*)src)[i];
        v.x = f2tf32f(v.x);
        v.y = f2tf32f(v.y);
        v.z = f2tf32f(v.z);
        v.w = f2tf32f(v.w);
        ((float4*)dst)[i] = v;
    }
}

// ---------------- cp.async 4-stage tf32 GEMM ----------------
// C[M,N] = A[M,K] @ B[K,N]; A,B already tf32-rounded fp32 (bits pass through MMA exactly).
// Block tile 128x128, BK=16, 256 threads (8 warps, warp tile 64x32), 4 stages.
#define AS_STR 20     // As[m][k] row stride (floats): 80B, 16B-aligned, conflict-free frags
#define BS_STR 136    // Bs[k][n] row stride: 544B, conflict-free frag loads
#define STG_FLOATS (128 * AS_STR + 16 * BS_STR)   // 2560 + 2176 = 4736
#define GEMM_SMEM_BYTES (4 * STG_FLOATS * 4)      // 75776

#define CP16(dst_u32, src_ptr) \
    asm volatile("cp.async.cg.shared.global [%0], [%1], 16;" :: "r"(dst_u32), "l"(src_ptr))

__global__ __launch_bounds__(256, 2) void gemm_async_kernel(
    const float* __restrict__ A,
    const float* __restrict__ B0, float* __restrict__ C0,
    const float* __restrict__ B1, float* __restrict__ C1,
    int N, int K)
{
    const float* B = (blockIdx.z == 0) ? B0 : B1;
    float* C = (blockIdx.z == 0) ? C0 : C1;

    extern __shared__ float sm[];
    const uint32_t smu = (uint32_t)__cvta_generic_to_shared(sm);

    const int tid = threadIdx.x;
    const int lane = tid & 31;
    const int wid = tid >> 5;
    const int wm = wid >> 2;          // 0..1
    const int wn = wid & 3;           // 0..3
    const int lr = lane >> 2;         // 0..7
    const int lc = lane & 3;          // 0..3

    const int by = blockIdx.y;
    const int bx = blockIdx.x;

    const int am = tid >> 1;          // 0..127 (A row)
    const int ak = (tid & 1) * 8;     // 0 or 8
    const int bk = tid >> 4;          // 0..15  (B row)
    const int bn = (tid & 15) * 8;    // 0..120

    const float* Ag = A + (size_t)(by * 128 + am) * K + ak;
    const float* Bg = B + (size_t)bk * N + bx * 128 + bn;
    const uint32_t a_dst = (uint32_t)((am * AS_STR + ak) * 4);
    const uint32_t b_dst = (uint32_t)((128 * AS_STR + bk * BS_STR + bn) * 4);

    float acc[4][4][4];
#pragma unroll
    for (int i = 0; i < 4; i++)
#pragma unroll
        for (int j = 0; j < 4; j++)
#pragma unroll
            for (int r = 0; r < 4; r++) acc[i][j][r] = 0.f;

    const int NT = K / 16;

    // prologue: stages 0..2
#pragma unroll
    for (int t = 0; t < 3; t++) {
        const uint32_t sbase = smu + (uint32_t)(t * STG_FLOATS * 4);
        const float* Ap = Ag + (size_t)t * 16;
        CP16(sbase + a_dst, Ap);
        CP16(sbase + a_dst + 16, Ap + 4);
        const float* Bp = Bg + (size_t)t * 16 * N;
        CP16(sbase + b_dst, Bp);
        CP16(sbase + b_dst + 16, Bp + 4);
        asm volatile("cp.async.commit_group;" ::: "memory");
    }

    for (int it = 0; it < NT; it++) {
        asm volatile("cp.async.wait_group 2;" ::: "memory");
        __syncthreads();

        const int pf = it + 3;
        if (pf < NT) {
            const uint32_t sbase = smu + (uint32_t)((pf & 3) * STG_FLOATS * 4);
            const float* Ap = Ag + (size_t)pf * 16;
            CP16(sbase + a_dst, Ap);
            CP16(sbase + a_dst + 16, Ap + 4);
            const float* Bp = Bg + (size_t)pf * 16 * N;
            CP16(sbase + b_dst, Bp);
            CP16(sbase + b_dst + 16, Bp + 4);
        }
        asm volatile("cp.async.commit_group;" ::: "memory");

        const float* As_ = sm + (it & 3) * STG_FLOATS;
        const float* Bs_ = As_ + 128 * AS_STR;

#pragma unroll
        for (int ks = 0; ks < 2; ks++) {
            const int kb = ks * 8;
            uint32_t af[4][4], bf[4][2];
#pragma unroll
            for (int mt = 0; mt < 4; mt++) {
                const int m0 = wm * 64 + mt * 16 + lr;
                af[mt][0] = __float_as_uint(As_[m0 * AS_STR + kb + lc]);
                af[mt][1] = __float_as_uint(As_[(m0 + 8) * AS_STR + kb + lc]);
                af[mt][2] = __float_as_uint(As_[m0 * AS_STR + kb + 4 + lc]);
                af[mt][3] = __float_as_uint(As_[(m0 + 8) * AS_STR + kb + 4 + lc]);
            }
#pragma unroll
            for (int nt = 0; nt < 4; nt++) {
                const int n0 = wn * 32 + nt * 8 + lr;
                bf[nt][0] = __float_as_uint(Bs_[(kb + lc) * BS_STR + n0]);
                bf[nt][1] = __float_as_uint(Bs_[(kb + 4 + lc) * BS_STR + n0]);
            }
#pragma unroll
            for (int mt = 0; mt < 4; mt++)
#pragma unroll
                for (int nt = 0; nt < 4; nt++)
                    mma_tf32(acc[mt][nt][0], acc[mt][nt][1], acc[mt][nt][2], acc[mt][nt][3],
                             af[mt][0], af[mt][1], af[mt][2], af[mt][3],
                             bf[nt][0], bf[nt][1]);
        }
    }

    // epilogue
#pragma unroll
    for (int mt = 0; mt < 4; mt++) {
        const int row = by * 128 + wm * 64 + mt * 16 + lr;
#pragma unroll
        for (int nt = 0; nt < 4; nt++) {
            const int col = bx * 128 + wn * 32 + nt * 8 + lc * 2;
            float2 v01 = make_float2(acc[mt][nt][0], acc[mt][nt][1]);
            float2 v23 = make_float2(acc[mt][nt][2], acc[mt][nt][3]);
            *(float2*)(C + (size_t)row * N + col) = v01;
            *(float2*)(C + (size_t)(row + 8) * N + col) = v23;
        }
    }
}

// ---------------- qn / kn ----------------
__global__ __launch_bounds__(128) void qn_kernel(const float* __restrict__ qp, float* __restrict__ qn)
{
    const int s = blockIdx.x;
    const int d = threadIdx.x;
    __shared__ float wsum[4];
    for (int h = 0; h < NH; h++) {
        float x = qp[(size_t)s * HID + h * HD + d];
        float f = x > 0.f ? x + 1.f : expf(x);
        float v = f;
#pragma unroll
        for (int o = 16; o; o >>= 1) v += __shfl_xor_sync(0xffffffffu, v, o);
        if ((d & 31) == 0) wsum[d >> 5] = v;
        __syncthreads();
        float tot = wsum[0] + wsum[1] + wsum[2] + wsum[3];
        qn[(size_t)s * HID + h * HD + d] = f / (tot + EPS);
        __syncthreads();
    }
}

__global__ __launch_bounds__(128) void kn_kernel(const float* __restrict__ kp, float* __restrict__ kn)
{
    const int s = blockIdx.x;
    const int d = threadIdx.x;
    __shared__ float wsum[4];
    for (int h = 0; h < NKV; h++) {
        float x = kp[(size_t)s * (NKV * HD) + h * HD + d];
        float f = x > 0.f ? x + 1.f : expf(x);
        float v = f;
#pragma unroll
        for (int o = 16; o; o >>= 1) v += __shfl_xor_sync(0xffffffffu, v, o);
        if ((d & 31) == 0) wsum[d >> 5] = v;
        __syncthreads();
        float tot = wsum[0] + wsum[1] + wsum[2] + wsum[3];
        kn[(size_t)s * (NKV * HD) + h * HD + d] = f / (tot + EPS);
        __syncthreads();
    }
}

// knsum two-pass deterministic reduction
__global__ __launch_bounds__(128) void knsum_part_kernel(const float* __restrict__ kn, float* __restrict__ part)
{
    const int h = blockIdx.x;
    const int p = blockIdx.y;
    const int d = threadIdx.x;
    float acc = 0.f;
    const int s0 = p * 128;
#pragma unroll 4
    for (int s = s0; s < s0 + 128; s++)
        acc += kn[(size_t)s * (NKV * HD) + h * HD + d];
    part[p * (NKV * HD) + h * HD + d] = acc;
}

__global__ __launch_bounds__(1024) void knsum_final_kernel(const float* __restrict__ part, float* __restrict__ knsum)
{
    const int i = threadIdx.x;
    float acc = 0.f;
#pragma unroll
    for (int p = 0; p < 16; p++) acc += part[p * (NKV * HD) + i];
    knsum[i] = acc;
}

// ---------------- memory retrieval ----------------
__global__ __launch_bounds__(128) void retrieve_kernel(
    const float* __restrict__ qn, const float* __restrict__ memory,
    const float* __restrict__ norm_m, float* __restrict__ memout)
{
    const int h = blockIdx.y;
    const int st = blockIdx.x;
    const int hm = h & (NKV - 1);
    const int e = threadIdx.x;
    __shared__ float Qs[16][128];
    __shared__ float Ms[32][128];
    __shared__ float Ns[128][33];

    for (int i = e; i < 16 * 128; i += 128) {
        int r = i >> 7, d = i & 127;
        Qs[r][d] = qn[(size_t)(st * 16 + r) * HID + h * HD + d];
    }
    float num[16], den[16];
#pragma unroll
    for (int r = 0; r < 16; r++) { num[r] = 0.f; den[r] = 0.f; }
    const float* M = memory + hm * HD * HD;
    const float* Nm = norm_m + hm * HD * HD;

    for (int d0 = 0; d0 < 128; d0 += 32) {
        __syncthreads();
        for (int i = e; i < 32 * 128; i += 128) {
            int dd = i >> 7, ee = i & 127;
            Ms[dd][ee] = M[(d0 + dd) * HD + ee];
        }
        for (int i = e; i < 128 * 32; i += 128) {
            int ee = i >> 5, dd = i & 31;
            Ns[ee][dd] = Nm[ee * HD + d0 + dd];
        }
        __syncthreads();
#pragma unroll 4
        for (int dd = 0; dd < 32; dd++) {
            float mv = Ms[dd][e];
            float nv = Ns[e][dd];
#pragma unroll
            for (int r = 0; r < 16; r++) {
                float qv = Qs[r][d0 + dd];
                num[r] += qv * mv;
                den[r] += qv * nv;
            }
        }
    }
#pragma unroll
    for (int r = 0; r < 16; r++)
        memout[(size_t)(st * 16 + r) * HID + h * HD + e] = num[r] / (den[r] + EPS);
}

// ---------------- v - v_ret for delta rule ----------------
__global__ __launch_bounds__(128) void vdelta_kernel(
    const float* __restrict__ kn, const float* __restrict__ vproj,
    const float* __restrict__ memory, const float* __restrict__ norm_m,
    float* __restrict__ vdelta)
{
    const int h = blockIdx.y;
    const int st = blockIdx.x;
    const int e = threadIdx.x;
    __shared__ float Qs[16][128];
    __shared__ float Ms[32][128];
    __shared__ float Ns[128][33];

    for (int i = e; i < 16 * 128; i += 128) {
        int r = i >> 7, d = i & 127;
        Qs[r][d] = kn[(size_t)(st * 16 + r) * (NKV * HD) + h * HD + d];
    }
    float num[16], den[16];
#pragma unroll
    for (int r = 0; r < 16; r++) { num[r] = 0.f; den[r] = 0.f; }
    const float* M = memory + h * HD * HD;
    const float* Nm = norm_m + h * HD * HD;

    for (int d0 = 0; d0 < 128; d0 += 32) {
        __syncthreads();
        for (int i = e; i < 32 * 128; i += 128) {
            int dd = i >> 7, ee = i & 127;
            Ms[dd][ee] = M[(d0 + dd) * HD + ee];
        }
        for (int i = e; i < 128 * 32; i += 128) {
            int ee = i >> 5, dd = i & 31;
            Ns[ee][dd] = Nm[ee * HD + d0 + dd];
        }
        __syncthreads();
#pragma unroll 4
        for (int dd = 0; dd < 32; dd++) {
            float mv = Ms[dd][e];
            float nv = Ns[e][dd];
#pragma unroll
            for (int r = 0; r < 16; r++) {
                float qv = Qs[r][d0 + dd];
                num[r] += qv * mv;
                den[r] += qv * nv;
            }
        }
    }
#pragma unroll
    for (int r = 0; r < 16; r++) {
        size_t idx = (size_t)(st * 16 + r) * (NKV * HD) + h * HD + e;
        vdelta[idx] = vproj[idx] - num[r] / (den[r] + EPS);
    }
}

// ---------------- RoPE ----------------
__global__ __launch_bounds__(256) void rope_kernel(
    float* __restrict__ q, float* __restrict__ k, const int* __restrict__ pos)
{
    const int s = blockIdx.x;
    const int idx = blockIdx.y * 256 + threadIdx.x;
    if (idx >= (NH + NKV) * 64) return;
    const int head = idx >> 6;
    const int d = idx & 63;
    const float p = (float)pos[s];
    const float invf = expf(-(2.0f * (float)d / 128.0f) * LN10000);
    const float a = p * invf;
    const float c = cosf(a), sn = sinf(a);
    float* base = (head < NH) ? (q + (size_t)s * HID + head * HD)
                              : (k + (size_t)s * (NKV * HD) + (head - NH) * HD);
    float x0 = base[d], x1 = base[d + 64];
    base[d]      = x0 * c - x1 * sn;
    base[d + 64] = x1 * c + x0 * sn;
}

// ---------------- MMA flash attention (3x-split tf32, fp32-accurate) ----------------
// Output (combined) is stored tf32-rounded: the O-projection GEMM would round it anyway.
#define QS_STR 132
#define KS_STR 132
#define VS_STR 136
#define PS_STR 68
#define ATT_SMEM_FLOATS (128 * QS_STR + 64 * KS_STR + 64 * VS_STR + 128 * PS_STR)
#define ATT_SMEM_BYTES (ATT_SMEM_FLOATS * 4)

__global__ __launch_bounds__(256) void attn_mma_kernel(
    const float* __restrict__ q, const float* __restrict__ k,
    const float* __restrict__ v, const float* __restrict__ memout,
    const float* __restrict__ beta, float* __restrict__ outc)
{
    const int h = blockIdx.y;
    const int qt = (int)gridDim.x - 1 - (int)blockIdx.x;
    const int kvh = h >> 2;
    const int tid = threadIdx.x;
    const int warp = tid >> 5;
    const int lane = tid & 31;
    const int lr = lane >> 2;
    const int lc = lane & 3;

    extern __shared__ float smem[];
    float* Qs = smem;
    float* Ks = Qs + 128 * QS_STR;
    float* Vs = Ks + 64 * KS_STR;
    float* Ps = Vs + 64 * VS_STR;

#pragma unroll
    for (int it = 0; it < 16; it++) {
        int i = it * 256 + tid;
        int row = i >> 5, c4 = (i & 31) * 4;
        float4 t = *(const float4*)(q + (size_t)(qt * 128 + row) * HID + h * HD + c4);
        *(float4*)(Qs + row * QS_STR + c4) = t;
    }

    const int row0 = warp * 16 + lr;
    const int row1 = row0 + 8;
    const int grow0 = qt * 128 + row0;
    const int grow1 = grow0 + 8;

    float m0 = -1e30f, m1 = -1e30f, l0 = 0.f, l1 = 0.f;
    float o[16][4];
#pragma unroll
    for (int nt = 0; nt < 16; nt++)
#pragma unroll
        for (int r = 0; r < 4; r++) o[nt][r] = 0.f;

    const int ktmax = 2 * qt + 1;
    for (int kt = 0; kt <= ktmax; kt++) {
        __syncthreads();
#pragma unroll
        for (int it = 0; it < 8; it++) {
            int i = it * 256 + tid;
            int key = i >> 5, c4 = (i & 31) * 4;
            size_t gidx = (size_t)(kt * 64 + key) * (NKV * HD) + kvh * HD + c4;
            float4 tk = *(const float4*)(k + gidx);
            *(float4*)(Ks + key * KS_STR + c4) = tk;
            float4 tv = *(const float4*)(v + gidx);
            *(float4*)(Vs + key * VS_STR + c4) = tv;
        }
        __syncthreads();

        float sc[8][4];
#pragma unroll
        for (int nt = 0; nt < 8; nt++)
#pragma unroll
            for (int r = 0; r < 4; r++) sc[nt][r] = 0.f;

#pragma unroll
        for (int ks = 0; ks < 16; ks++) {
            const int d0 = ks * 8;
            uint32_t ah[4], al[4];
            split_tf32(Qs[row0 * QS_STR + d0 + lc],     ah[0], al[0]);
            split_tf32(Qs[row1 * QS_STR + d0 + lc],     ah[1], al[1]);
            split_tf32(Qs[row0 * QS_STR + d0 + lc + 4], ah[2], al[2]);
            split_tf32(Qs[row1 * QS_STR + d0 + lc + 4], ah[3], al[3]);
#pragma unroll
            for (int nt = 0; nt < 8; nt++) {
                uint32_t bh0, bl0, bh1, bl1;
                split_tf32(Ks[(nt * 8 + lr) * KS_STR + d0 + lc],     bh0, bl0);
                split_tf32(Ks[(nt * 8 + lr) * KS_STR + d0 + lc + 4], bh1, bl1);
                mma_tf32(sc[nt][0], sc[nt][1], sc[nt][2], sc[nt][3],
                         ah[0], ah[1], ah[2], ah[3], bh0, bh1);
                mma_tf32(sc[nt][0], sc[nt][1], sc[nt][2], sc[nt][3],
                         ah[0], ah[1], ah[2], ah[3], bl0, bl1);
                mma_tf32(sc[nt][0], sc[nt][1], sc[nt][2], sc[nt][3],
                         al[0], al[1], al[2], al[3], bh0, bh1);
            }
        }

        const bool need_mask = (kt >= 2 * qt);
        float mx0 = -1e30f, mx1 = -1e30f;
#pragma unroll
        for (int nt = 0; nt < 8; nt++) {
#pragma unroll
            for (int j = 0; j < 2; j++) {
                int col = kt * 64 + nt * 8 + 2 * lc + j;
                float s0 = sc[nt][j] * ATT_SCALE;
                float s1 = sc[nt][2 + j] * ATT_SCALE;
                if (need_mask) {
                    if (col > grow0) s0 = -1e30f;
                    if (col > grow1) s1 = -1e30f;
                }
                sc[nt][j] = s0;
                sc[nt][2 + j] = s1;
                mx0 = fmaxf(mx0, s0);
                mx1 = fmaxf(mx1, s1);
            }
        }
        mx0 = fmaxf(mx0, __shfl_xor_sync(0xffffffffu, mx0, 1));
        mx0 = fmaxf(mx0, __shfl_xor_sync(0xffffffffu, mx0, 2));
        mx1 = fmaxf(mx1, __shfl_xor_sync(0xffffffffu, mx1, 1));
        mx1 = fmaxf(mx1, __shfl_xor_sync(0xffffffffu, mx1, 2));
        const float mn0 = fmaxf(m0, mx0);
        const float mn1 = fmaxf(m1, mx1);
        const float scl0 = __expf(m0 - mn0);
        const float scl1 = __expf(m1 - mn1);
        float ls0 = 0.f, ls1 = 0.f;
#pragma unroll
        for (int nt = 0; nt < 8; nt++) {
#pragma unroll
            for (int j = 0; j < 2; j++) {
                float p0 = __expf(sc[nt][j] - mn0);
                float p1 = __expf(sc[nt][2 + j] - mn1);
                ls0 += p0;
                ls1 += p1;
                Ps[row0 * PS_STR + nt * 8 + 2 * lc + j] = p0;
                Ps[row1 * PS_STR + nt * 8 + 2 * lc + j] = p1;
            }
        }
        ls0 += __shfl_xor_sync(0xffffffffu, ls0, 1);
        ls0 += __shfl_xor_sync(0xffffffffu, ls0, 2);
        ls1 += __shfl_xor_sync(0xffffffffu, ls1, 1);
        ls1 += __shfl_xor_sync(0xffffffffu, ls1, 2);
        l0 = l0 * scl0 + ls0;
        l1 = l1 * scl1 + ls1;
        m0 = mn0;
        m1 = mn1;

#pragma unroll
        for (int nt = 0; nt < 16; nt++) {
            o[nt][0] *= scl0;
            o[nt][1] *= scl0;
            o[nt][2] *= scl1;
            o[nt][3] *= scl1;
        }
        __syncwarp();

#pragma unroll
        for (int ks2 = 0; ks2 < 8; ks2++) {
            const int k0 = ks2 * 8;
            uint32_t ah[4], al[4];
            split_tf32(Ps[row0 * PS_STR + k0 + lc],     ah[0], al[0]);
            split_tf32(Ps[row1 * PS_STR + k0 + lc],     ah[1], al[1]);
            split_tf32(Ps[row0 * PS_STR + k0 + lc + 4], ah[2], al[2]);
            split_tf32(Ps[row1 * PS_STR + k0 + lc + 4], ah[3], al[3]);
#pragma unroll
            for (int nt = 0; nt < 16; nt++) {
                uint32_t bh0, bl0, bh1, bl1;
                split_tf32(Vs[(k0 + lc) * VS_STR + nt * 8 + lr],       bh0, bl0);
                split_tf32(Vs[(k0 + 4 + lc) * VS_STR + nt * 8 + lr],   bh1, bl1);
                mma_tf32(o[nt][0], o[nt][1], o[nt][2], o[nt][3],
                         ah[0], ah[1], ah[2], ah[3], bh0, bh1);
                mma_tf32(o[nt][0], o[nt][1], o[nt][2], o[nt][3],
                         ah[0], ah[1], ah[2], ah[3], bl0, bl1);
                mma_tf32(o[nt][0], o[nt][1], o[nt][2], o[nt][3],
                         al[0], al[1], al[2], al[3], bh0, bh1);
            }
        }
    }

    // epilogue: gate-combine, store tf32-rounded (O-proj GEMM consumes raw bits)
    const float g = 1.f / (1.f + __expf(-beta[0]));
    const float og = 1.f - g;
    const float li0 = 1.f / l0;
    const float li1 = 1.f / l1;
#pragma unroll
    for (int nt = 0; nt < 16; nt++) {
        const int col = nt * 8 + 2 * lc;
        size_t i0 = (size_t)grow0 * HID + h * HD + col;
        size_t i1 = (size_t)grow1 * HID + h * HD + col;
        float2 mo0 = *(const float2*)(memout + i0);
        float2 mo1 = *(const float2*)(memout + i1);
        float2 r0, r1;
        r0.x = f2tf32f(g * mo0.x + og * (o[nt][0] * li0));
        r0.y = f2tf32f(g * mo0.y + og * (o[nt][1] * li0));
        r1.x = f2tf32f(g * mo1.x + og * (o[nt][2] * li1));
        r1.y = f2tf32f(g * mo1.y + og * (o[nt][3] * li1));
        *(float2*)(outc + i0) = r0;
        *(float2*)(outc + i1) = r1;
    }
}

// ---------------- delta-rule partials ----------------
__global__ __launch_bounds__(256) void delta_part_kernel(
    const float* __restrict__ kn, const float* __restrict__ vd, float* __restrict__ part)
{
    const int h = blockIdx.x;
    const int c = blockIdx.y;
    __shared__ float Ak[32][128];
    __shared__ float Bv[32][128];
    const int trow = (threadIdx.x >> 4) * 8;
    const int tcol = (threadIdx.x & 15) * 8;
    float acc[8][8];
#pragma unroll
    for (int i = 0; i < 8; i++)
#pragma unroll
        for (int j = 0; j < 8; j++) acc[i][j] = 0.f;

    const int sbeg = c * 256;
    for (int s0 = sbeg; s0 < sbeg + 256; s0 += 32) {
        for (int i = threadIdx.x; i < 32 * 128; i += 256) {
            int ss = i >> 7, dd = i & 127;
            size_t idx = (size_t)(s0 + ss) * (NKV * HD) + h * HD + dd;
            Ak[ss][dd] = kn[idx];
            Bv[ss][dd] = vd[idx];
        }
        __syncthreads();
#pragma unroll 4
        for (int ss = 0; ss < 32; ss++) {
            float ra[8], rb[8];
#pragma unroll
            for (int i = 0; i < 8; i++) ra[i] = Ak[ss][trow + i];
#pragma unroll
            for (int j = 0; j < 8; j++) rb[j] = Bv[ss][tcol + j];
#pragma unroll
            for (int i = 0; i < 8; i++)
#pragma unroll
                for (int j = 0; j < 8; j++) acc[i][j] += ra[i] * rb[j];
        }
        __syncthreads();
    }
    float* Ph = part + (size_t)c * (NKV * HD * HD) + h * HD * HD;
#pragma unroll
    for (int i = 0; i < 8; i++)
#pragma unroll
        for (int j = 0; j < 8; j++)
            Ph[(trow + i) * HD + tcol + j] = acc[i][j];
}

__global__ __launch_bounds__(256) void delta_final_kernel(
    const float* __restrict__ part, const float* __restrict__ memory, float* __restrict__ outmem)
{
    const int i = blockIdx.x * 256 + threadIdx.x;
    float acc = memory[i];
#pragma unroll
    for (int c = 0; c < 8; c++) acc += part[(size_t)c * (NKV * HD * HD) + i];
    outmem[i] = acc;
}

// ---------------- updated_norm ----------------
__global__ __launch_bounds__(256) void norm_kernel(
    const float* __restrict__ norm_m, const float* __restrict__ knsum, float* __restrict__ out)
{
    const int i = blockIdx.x * 256 + threadIdx.x;
    const int h = i >> 14;
    const int j = i & 127;
    out[i] = norm_m[i] + knsum[h * HD + j];
}

// ---------------- launch ----------------
extern "C" void kernel_launch(void* const* d_in, const int* in_sizes, int n_in,
                              void* d_out, int out_size)
{
    const float* hidden = (const float*)d_in[0];
    const int*   pos    = (const int*)d_in[1];
    const float* wq     = (const float*)d_in[2];
    const float* wk     = (const float*)d_in[3];
    const float* wv     = (const float*)d_in[4];
    const float* wo     = (const float*)d_in[5];
    const float* memory = (const float*)d_in[6];
    const float* norm_m = (const float*)d_in[7];
    const float* beta   = (const float*)d_in[8];
    float* out = (float*)d_out;

    float *qproj, *kproj, *vproj, *qn, *kn, *memout, *vdelta, *knsum, *knpart, *combined, *dpart;
    float *hid_r, *wq_r, *wk_r, *wv_r, *wo_r;
    cudaGetSymbolAddress((void**)&qproj, g_qproj);
    cudaGetSymbolAddress((void**)&kproj, g_kproj);
    cudaGetSymbolAddress((void**)&vproj, g_vproj);
    cudaGetSymbolAddress((void**)&qn, g_qn);
    cudaGetSymbolAddress((void**)&kn, g_kn);
    cudaGetSymbolAddress((void**)&memout, g_memout);
    cudaGetSymbolAddress((void**)&vdelta, g_vdelta);
    cudaGetSymbolAddress((void**)&knsum, g_knsum);
    cudaGetSymbolAddress((void**)&knpart, g_knsum_part);
    cudaGetSymbolAddress((void**)&combined, g_combined);
    cudaGetSymbolAddress((void**)&dpart, g_delta_part);
    cudaGetSymbolAddress((void**)&hid_r, g_hid_r);
    cudaGetSymbolAddress((void**)&wq_r, g_wq_r);
    cudaGetSymbolAddress((void**)&wk_r, g_wk_r);
    cudaGetSymbolAddress((void**)&wv_r, g_wv_r);
    cudaGetSymbolAddress((void**)&wo_r, g_wo_r);

    cudaFuncSetAttribute(attn_mma_kernel,
                         cudaFuncAttributeMaxDynamicSharedMemorySize, ATT_SMEM_BYTES);
    cudaFuncSetAttribute(gemm_async_kernel,
                         cudaFuncAttributeMaxDynamicSharedMemorySize, GEMM_SMEM_BYTES);

    // pre-round GEMM inputs to tf32 (identical error to in-kernel cvt; enables cp.async path)
    round4_kernel<<<1024, 256>>>(hidden, hid_r, S * HID / 4);
    round4_kernel<<<2048, 256>>>(wq, wq_r, HID * HID / 4);
    round4_kernel<<<1024, 256>>>(wk, wk_r, HID * NKV * HD / 4);
    round4_kernel<<<1024, 256>>>(wv, wv_r, HID * NKV * HD / 4);
    round4_kernel<<<2048, 256>>>(wo, wo_r, HID * HID / 4);

    // projections (async tf32 tensor-core GEMM). K/V fused via gridDim.z.
    gemm_async_kernel<<<dim3(HID / 128, S / 128, 1), 256, GEMM_SMEM_BYTES>>>(
        hid_r, wq_r, qproj, wq_r, qproj, HID, HID);
    gemm_async_kernel<<<dim3(NKV * HD / 128, S / 128, 2), 256, GEMM_SMEM_BYTES>>>(
        hid_r, wk_r, kproj, wv_r, vproj, NKV * HD, HID);

    // normalized features from PRE-RoPE q/k
    qn_kernel<<<S, 128>>>(qproj, qn);
    kn_kernel<<<S, 128>>>(kproj, kn);
    knsum_part_kernel<<<dim3(NKV, 16), 128>>>(kn, knpart);
    knsum_final_kernel<<<1, 1024>>>(knpart, knsum);

    // compressive-memory retrieval + delta-rule prep
    retrieve_kernel<<<dim3(S / 16, NH), 128>>>(qn, memory, norm_m, memout);
    vdelta_kernel<<<dim3(S / 16, NKV), 128>>>(kn, vproj, memory, norm_m, vdelta);

    // RoPE in place, then MMA flash attention (fuses gated combine, emits tf32-rounded)
    rope_kernel<<<dim3(S, 10), 256>>>(qproj, kproj, pos);
    attn_mma_kernel<<<dim3(S / 128, NH), 256, ATT_SMEM_BYTES>>>(
        qproj, kproj, vproj, memout, beta, combined);

    // output projection
    gemm_async_kernel<<<dim3(HID / 128, S / 128, 1), 256, GEMM_SMEM_BYTES>>>(
        combined, wo_r, out, wo_r, out, HID, HID);

    // memory & norm updates (appended after the 8.4M-element `out`)
    delta_part_kernel<<<dim3(NKV, 8), 256>>>(kn, vdelta, dpart);
    delta_final_kernel<<<(NKV * HD * HD) / 256, 256>>>(dpart, memory, out + (size_t)S * HID);
    norm_kernel<<<(NKV * HD * HD) / 256, 256>>>(norm_m, knsum,
                                                out + (size_t)S * HID + NKV * HD * HD);
}

// round 6
// speedup vs baseline: 2.8603x; 1.0497x over previous
#include <cuda_runtime.h>
#include <cuda_bf16.h>
#include <math.h>
#include <stdint.h>

// ---------------- problem constants ----------------
#define S 2048
#define HID 4096
#define NH 32
#define NKV 8
#define HD 128
#define GROUPS 4
#define EPS 1e-8f
#define ATT_SCALE 0.08838834764831845f   // 128^-0.5
#define LN10000 9.210340371976184f

// ---------------- scratch (device globals; no allocation allowed) ----------------
__device__ float g_qproj[S * HID];
__device__ float g_kproj[S * NKV * HD];
__device__ float g_vproj[S * NKV * HD];
__device__ float g_qn[S * HID];
__device__ float g_kn[S * NKV * HD];
__device__ float g_memout[S * HID];
__device__ float g_vdelta[S * NKV * HD];
__device__ float g_knsum[NKV * HD];
__device__ float g_knsum_part[16][NKV * HD];
__device__ float g_combined[S * HID];
__device__ float g_delta_part[8][NKV * HD * HD];
// tf32-pre-rounded copies of GEMM inputs
__device__ float g_hid_r[S * HID];
__device__ float g_wq_r[HID * HID];
__device__ float g_wk_r[HID * NKV * HD];
__device__ float g_wv_r[HID * NKV * HD];
__device__ float g_wo_r[HID * HID];

// ---------------- tf32 helpers ----------------
__device__ __forceinline__ uint32_t f2tf32(float x) {
    uint32_t y;
    asm("cvt.rna.tf32.f32 %0, %1;" : "=r"(y) : "f"(x));
    return y;
}
__device__ __forceinline__ float f2tf32f(float x) {
    return __uint_as_float(f2tf32(x));
}
__device__ __forceinline__ void split_tf32(float f, uint32_t& hi, uint32_t& lo) {
    hi = f2tf32(f);
    lo = f2tf32(f - __uint_as_float(hi));
}

__device__ __forceinline__ void mma_tf32(
    float& c0, float& c1, float& c2, float& c3,
    uint32_t a0, uint32_t a1, uint32_t a2, uint32_t a3,
    uint32_t b0, uint32_t b1)
{
    asm volatile(
        "mma.sync.aligned.m16n8k8.row.col.f32.tf32.tf32.f32 "
        "{%0,%1,%2,%3},{%4,%5,%6,%7},{%8,%9},{%0,%1,%2,%3};"
        : "+f"(c0), "+f"(c1), "+f"(c2), "+f"(c3)
        : "r"(a0), "r"(a1), "r"(a2), "r"(a3), "r"(b0), "r"(b1));
}

// ---------------- fused tf32 pre-round of all GEMM inputs ----------------
__global__ __launch_bounds__(256) void round_all_kernel(
    const float* __restrict__ h,  float* __restrict__ hr,
    const float* __restrict__ wq, float* __restrict__ wqr,
    const float* __restrict__ wk, float* __restrict__ wkr,
    const float* __restrict__ wv, float* __restrict__ wvr,
    const float* __restrict__ wo, float* __restrict__ wor)
{
    const int stride = gridDim.x * 256;
    const int t0 = blockIdx.x * 256 + threadIdx.x;
#define RND_LOOP(src, dst, n4)                                   \
    for (int i = t0; i < (n4); i += stride) {                    \
        float4 v = ((const float4*)(src))[i];                    \
        v.x = f2tf32f(v.x); v.y = f2tf32f(v.y);                  \
        v.z = f2tf32f(v.z); v.w = f2tf32f(v.w);                  \
        ((float4*)(dst))[i] = v;                                 \
    }
    RND_LOOP(h, hr, S * HID / 4)
    RND_LOOP(wq, wqr, HID * HID / 4)
    RND_LOOP(wk, wkr, HID * NKV * HD / 4)
    RND_LOOP(wv, wvr, HID * NKV * HD / 4)
    RND_LOOP(wo, wor, HID * HID / 4)
#undef RND_LOOP
}

// ---------------- GEMM v3: 4 warps, 64x64 warp tile, BK=32, 3-stage cp.async ----------------
// C[M,N] = A[M,K] @ B[K,N]; inputs already tf32-rounded fp32.
// Block tile 128x128, 128 threads. mode: 0 -> single (B0,C0,N0); 1 -> z=1 splits K/V.
#define AS3_STR 36    // A[m][k] row stride (floats): 144B, 16B aligned, conflict-free
#define BS3_STR 136   // B[k][n] row stride: 544B
#define STG3 (128 * AS3_STR + 32 * BS3_STR)   // 4608 + 4352 = 8960 floats
#define GEMM3_SMEM (3 * STG3 * 4)             // 107520 B

#define CP16(dst_u32, src_ptr) \
    asm volatile("cp.async.cg.shared.global [%0], [%1], 16;" :: "r"(dst_u32), "l"(src_ptr))

__global__ __launch_bounds__(128, 2) void gemm_v3_kernel(
    const float* __restrict__ A,
    const float* __restrict__ B0, float* __restrict__ C0, int N0,
    const float* __restrict__ B1, float* __restrict__ C1,
    const float* __restrict__ B2, float* __restrict__ C2, int N12,
    int K)
{
    const float* B;
    float* C;
    int N, bx;
    if (blockIdx.z == 0) {
        B = B0; C = C0; N = N0; bx = blockIdx.x;
    } else {
        N = N12;
        const int nt12 = N12 / 128;
        if ((int)blockIdx.x < nt12) { B = B1; C = C1; bx = blockIdx.x; }
        else if ((int)blockIdx.x < 2 * nt12) { B = B2; C = C2; bx = blockIdx.x - nt12; }
        else return;
    }

    extern __shared__ float sm[];
    const uint32_t smu = (uint32_t)__cvta_generic_to_shared(sm);

    const int tid = threadIdx.x;
    const int lane = tid & 31;
    const int wid = tid >> 5;        // 0..3
    const int wm = wid >> 1;         // 0..1 -> 64 rows
    const int wn = wid & 1;          // 0..1 -> 64 cols
    const int lr = lane >> 2;        // 0..7
    const int lc = lane & 3;         // 0..3
    const int by = blockIdx.y;

    // cp.async mappings (128 threads)
    const int arow = tid >> 2;            // 0..31
    const int acol = (tid & 3) * 8;       // 0,8,16,24
    const int brow = tid >> 4;            // 0..7
    const int bcol = (tid & 15) * 8;      // 0..120

    const float* Abase = A + (size_t)(by * 128) * K;
    const float* Bbase = B + bx * 128;

    float acc[4][8][4];
#pragma unroll
    for (int i = 0; i < 4; i++)
#pragma unroll
        for (int j = 0; j < 8; j++)
#pragma unroll
            for (int r = 0; r < 4; r++) acc[i][j][r] = 0.f;

    const int NT = K / 32;

    // stage loader
#define LOAD_STAGE(stg, kt)                                                          \
    {                                                                                \
        const uint32_t sb = smu + (uint32_t)((stg) * STG3 * 4);                      \
        const int k0 = (kt) * 32;                                                    \
        _Pragma("unroll")                                                            \
        for (int i = 0; i < 4; i++) {                                                \
            const int r = i * 32 + arow;                                             \
            const float* src = Abase + (size_t)r * K + k0 + acol;                    \
            const uint32_t dst = sb + (uint32_t)((r * AS3_STR + acol) * 4);          \
            CP16(dst, src);                                                          \
            CP16(dst + 16, src + 4);                                                 \
        }                                                                            \
        _Pragma("unroll")                                                            \
        for (int i = 0; i < 4; i++) {                                                \
            const int r = i * 8 + brow;                                              \
            const float* src = Bbase + (size_t)(k0 + r) * N + bcol;                  \
            const uint32_t dst = sb + (uint32_t)((128 * AS3_STR + r * BS3_STR + bcol) * 4); \
            CP16(dst, src);                                                          \
            CP16(dst + 16, src + 4);                                                 \
        }                                                                            \
    }

    LOAD_STAGE(0, 0)
    asm volatile("cp.async.commit_group;" ::: "memory");
    LOAD_STAGE(1, 1)
    asm volatile("cp.async.commit_group;" ::: "memory");

    int stage = 0;
    for (int it = 0; it < NT; it++) {
        asm volatile("cp.async.wait_group 1;" ::: "memory");
        __syncthreads();

        const int pf = it + 2;
        if (pf < NT) {
            const int ps = (stage + 2) % 3;
            LOAD_STAGE(ps, pf)
        }
        asm volatile("cp.async.commit_group;" ::: "memory");

        const float* As_ = sm + stage * STG3;
        const float* Bs_ = As_ + 128 * AS3_STR;

#pragma unroll
        for (int ks = 0; ks < 4; ks++) {
            const int kb = ks * 8;
            uint32_t af[4][4], bf[8][2];
#pragma unroll
            for (int mt = 0; mt < 4; mt++) {
                const int m0 = wm * 64 + mt * 16 + lr;
                af[mt][0] = __float_as_uint(As_[m0 * AS3_STR + kb + lc]);
                af[mt][1] = __float_as_uint(As_[(m0 + 8) * AS3_STR + kb + lc]);
                af[mt][2] = __float_as_uint(As_[m0 * AS3_STR + kb + 4 + lc]);
                af[mt][3] = __float_as_uint(As_[(m0 + 8) * AS3_STR + kb + 4 + lc]);
            }
#pragma unroll
            for (int nt = 0; nt < 8; nt++) {
                const int n0 = wn * 64 + nt * 8 + lr;
                bf[nt][0] = __float_as_uint(Bs_[(kb + lc) * BS3_STR + n0]);
                bf[nt][1] = __float_as_uint(Bs_[(kb + 4 + lc) * BS3_STR + n0]);
            }
#pragma unroll
            for (int mt = 0; mt < 4; mt++)
#pragma unroll
                for (int nt = 0; nt < 8; nt++)
                    mma_tf32(acc[mt][nt][0], acc[mt][nt][1], acc[mt][nt][2], acc[mt][nt][3],
                             af[mt][0], af[mt][1], af[mt][2], af[mt][3],
                             bf[nt][0], bf[nt][1]);
        }
        stage = (stage + 1) % 3;
    }
#undef LOAD_STAGE

    // epilogue
#pragma unroll
    for (int mt = 0; mt < 4; mt++) {
        const int row = by * 128 + wm * 64 + mt * 16 + lr;
#pragma unroll
        for (int nt = 0; nt < 8; nt++) {
            const int col = bx * 128 + wn * 64 + nt * 8 + lc * 2;
            float2 v01 = make_float2(acc[mt][nt][0], acc[mt][nt][1]);
            float2 v23 = make_float2(acc[mt][nt][2], acc[mt][nt][3]);
            *(float2*)(C + (size_t)row * N + col) = v01;
            *(float2*)(C + (size_t)(row + 8) * N + col) = v23;
        }
    }
}

// ---------------- qn / kn ----------------
__global__ __launch_bounds__(128) void qn_kernel(const float* __restrict__ qp, float* __restrict__ qn)
{
    const int s = blockIdx.x;
    const int d = threadIdx.x;
    __shared__ float wsum[4];
    for (int h = 0; h < NH; h++) {
        float x = qp[(size_t)s * HID + h * HD + d];
        float f = x > 0.f ? x + 1.f : expf(x);
        float v = f;
#pragma unroll
        for (int o = 16; o; o >>= 1) v += __shfl_xor_sync(0xffffffffu, v, o);
        if ((d & 31) == 0) wsum[d >> 5] = v;
        __syncthreads();
        float tot = wsum[0] + wsum[1] + wsum[2] + wsum[3];
        qn[(size_t)s * HID + h * HD + d] = f / (tot + EPS);
        __syncthreads();
    }
}

__global__ __launch_bounds__(128) void kn_kernel(const float* __restrict__ kp, float* __restrict__ kn)
{
    const int s = blockIdx.x;
    const int d = threadIdx.x;
    __shared__ float wsum[4];
    for (int h = 0; h < NKV; h++) {
        float x = kp[(size_t)s * (NKV * HD) + h * HD + d];
        float f = x > 0.f ? x + 1.f : expf(x);
        float v = f;
#pragma unroll
        for (int o = 16; o; o >>= 1) v += __shfl_xor_sync(0xffffffffu, v, o);
        if ((d & 31) == 0) wsum[d >> 5] = v;
        __syncthreads();
        float tot = wsum[0] + wsum[1] + wsum[2] + wsum[3];
        kn[(size_t)s * (NKV * HD) + h * HD + d] = f / (tot + EPS);
        __syncthreads();
    }
}

// knsum two-pass deterministic reduction
__global__ __launch_bounds__(128) void knsum_part_kernel(const float* __restrict__ kn, float* __restrict__ part)
{
    const int h = blockIdx.x;
    const int p = blockIdx.y;
    const int d = threadIdx.x;
    float acc = 0.f;
    const int s0 = p * 128;
#pragma unroll 4
    for (int s = s0; s < s0 + 128; s++)
        acc += kn[(size_t)s * (NKV * HD) + h * HD + d];
    part[p * (NKV * HD) + h * HD + d] = acc;
}

__global__ __launch_bounds__(1024) void knsum_final_kernel(const float* __restrict__ part, float* __restrict__ knsum)
{
    const int i = threadIdx.x;
    float acc = 0.f;
#pragma unroll
    for (int p = 0; p < 16; p++) acc += part[p * (NKV * HD) + i];
    knsum[i] = acc;
}

// ---------------- memory retrieval ----------------
__global__ __launch_bounds__(128) void retrieve_kernel(
    const float* __restrict__ qn, const float* __restrict__ memory,
    const float* __restrict__ norm_m, float* __restrict__ memout)
{
    const int h = blockIdx.y;
    const int st = blockIdx.x;
    const int hm = h & (NKV - 1);
    const int e = threadIdx.x;
    __shared__ float Qs[16][128];
    __shared__ float Ms[32][128];
    __shared__ float Ns[128][33];

    for (int i = e; i < 16 * 128; i += 128) {
        int r = i >> 7, d = i & 127;
        Qs[r][d] = qn[(size_t)(st * 16 + r) * HID + h * HD + d];
    }
    float num[16], den[16];
#pragma unroll
    for (int r = 0; r < 16; r++) { num[r] = 0.f; den[r] = 0.f; }
    const float* M = memory + hm * HD * HD;
    const float* Nm = norm_m + hm * HD * HD;

    for (int d0 = 0; d0 < 128; d0 += 32) {
        __syncthreads();
        for (int i = e; i < 32 * 128; i += 128) {
            int dd = i >> 7, ee = i & 127;
            Ms[dd][ee] = M[(d0 + dd) * HD + ee];
        }
        for (int i = e; i < 128 * 32; i += 128) {
            int ee = i >> 5, dd = i & 31;
            Ns[ee][dd] = Nm[ee * HD + d0 + dd];
        }
        __syncthreads();
#pragma unroll 4
        for (int dd = 0; dd < 32; dd++) {
            float mv = Ms[dd][e];
            float nv = Ns[e][dd];
#pragma unroll
            for (int r = 0; r < 16; r++) {
                float qv = Qs[r][d0 + dd];
                num[r] += qv * mv;
                den[r] += qv * nv;
            }
        }
    }
#pragma unroll
    for (int r = 0; r < 16; r++)
        memout[(size_t)(st * 16 + r) * HID + h * HD + e] = num[r] / (den[r] + EPS);
}

// ---------------- v - v_ret for delta rule ----------------
__global__ __launch_bounds__(128) void vdelta_kernel(
    const float* __restrict__ kn, const float* __restrict__ vproj,
    const float* __restrict__ memory, const float* __restrict__ norm_m,
    float* __restrict__ vdelta)
{
    const int h = blockIdx.y;
    const int st = blockIdx.x;
    const int e = threadIdx.x;
    __shared__ float Qs[16][128];
    __shared__ float Ms[32][128];
    __shared__ float Ns[128][33];

    for (int i = e; i < 16 * 128; i += 128) {
        int r = i >> 7, d = i & 127;
        Qs[r][d] = kn[(size_t)(st * 16 + r) * (NKV * HD) + h * HD + d];
    }
    float num[16], den[16];
#pragma unroll
    for (int r = 0; r < 16; r++) { num[r] = 0.f; den[r] = 0.f; }
    const float* M = memory + h * HD * HD;
    const float* Nm = norm_m + h * HD * HD;

    for (int d0 = 0; d0 < 128; d0 += 32) {
        __syncthreads();
        for (int i = e; i < 32 * 128; i += 128) {
            int dd = i >> 7, ee = i & 127;
            Ms[dd][ee] = M[(d0 + dd) * HD + ee];
        }
        for (int i = e; i < 128 * 32; i += 128) {
            int ee = i >> 5, dd = i & 31;
            Ns[ee][dd] = Nm[ee * HD + d0 + dd];
        }
        __syncthreads();
#pragma unroll 4
        for (int dd = 0; dd < 32; dd++) {
            float mv = Ms[dd][e];
            float nv = Ns[e][dd];
#pragma unroll
            for (int r = 0; r < 16; r++) {
                float qv = Qs[r][d0 + dd];
                num[r] += qv * mv;
                den[r] += qv * nv;
            }
        }
    }
#pragma unroll
    for (int r = 0; r < 16; r++) {
        size_t idx = (size_t)(st * 16 + r) * (NKV * HD) + h * HD + e;
        vdelta[idx] = vproj[idx] - num[r] / (den[r] + EPS);
    }
}

// ---------------- RoPE ----------------
__global__ __launch_bounds__(256) void rope_kernel(
    float* __restrict__ q, float* __restrict__ k, const int* __restrict__ pos)
{
    const int s = blockIdx.x;
    const int idx = blockIdx.y * 256 + threadIdx.x;
    if (idx >= (NH + NKV) * 64) return;
    const int head = idx >> 6;
    const int d = idx & 63;
    const float p = (float)pos[s];
    const float invf = expf(-(2.0f * (float)d / 128.0f) * LN10000);
    const float a = p * invf;
    const float c = cosf(a), sn = sinf(a);
    float* base = (head < NH) ? (q + (size_t)s * HID + head * HD)
                              : (k + (size_t)s * (NKV * HD) + (head - NH) * HD);
    float x0 = base[d], x1 = base[d + 64];
    base[d]      = x0 * c - x1 * sn;
    base[d + 64] = x1 * c + x0 * sn;
}

// ---------------- MMA flash attention (3x-split tf32, fp32-accurate) ----------------
#define QS_STR 132
#define KS_STR 132
#define VS_STR 136
#define PS_STR 68
#define ATT_SMEM_FLOATS (128 * QS_STR + 64 * KS_STR + 64 * VS_STR + 128 * PS_STR)
#define ATT_SMEM_BYTES (ATT_SMEM_FLOATS * 4)

__global__ __launch_bounds__(256) void attn_mma_kernel(
    const float* __restrict__ q, const float* __restrict__ k,
    const float* __restrict__ v, const float* __restrict__ memout,
    const float* __restrict__ beta, float* __restrict__ outc)
{
    const int h = blockIdx.y;
    const int qt = (int)gridDim.x - 1 - (int)blockIdx.x;
    const int kvh = h >> 2;
    const int tid = threadIdx.x;
    const int warp = tid >> 5;
    const int lane = tid & 31;
    const int lr = lane >> 2;
    const int lc = lane & 3;

    extern __shared__ float smem[];
    float* Qs = smem;
    float* Ks = Qs + 128 * QS_STR;
    float* Vs = Ks + 64 * KS_STR;
    float* Ps = Vs + 64 * VS_STR;

#pragma unroll
    for (int it = 0; it < 16; it++) {
        int i = it * 256 + tid;
        int row = i >> 5, c4 = (i & 31) * 4;
        float4 t = *(const float4*)(q + (size_t)(qt * 128 + row) * HID + h * HD + c4);
        *(float4*)(Qs + row * QS_STR + c4) = t;
    }

    const int row0 = warp * 16 + lr;
    const int row1 = row0 + 8;
    const int grow0 = qt * 128 + row0;
    const int grow1 = grow0 + 8;

    float m0 = -1e30f, m1 = -1e30f, l0 = 0.f, l1 = 0.f;
    float o[16][4];
#pragma unroll
    for (int nt = 0; nt < 16; nt++)
#pragma unroll
        for (int r = 0; r < 4; r++) o[nt][r] = 0.f;

    const int ktmax = 2 * qt + 1;
    for (int kt = 0; kt <= ktmax; kt++) {
        __syncthreads();
#pragma unroll
        for (int it = 0; it < 8; it++) {
            int i = it * 256 + tid;
            int key = i >> 5, c4 = (i & 31) * 4;
            size_t gidx = (size_t)(kt * 64 + key) * (NKV * HD) + kvh * HD + c4;
            float4 tk = *(const float4*)(k + gidx);
            *(float4*)(Ks + key * KS_STR + c4) = tk;
            float4 tv = *(const float4*)(v + gidx);
            *(float4*)(Vs + key * VS_STR + c4) = tv;
        }
        __syncthreads();

        float sc[8][4];
#pragma unroll
        for (int nt = 0; nt < 8; nt++)
#pragma unroll
            for (int r = 0; r < 4; r++) sc[nt][r] = 0.f;

#pragma unroll
        for (int ks = 0; ks < 16; ks++) {
            const int d0 = ks * 8;
            uint32_t ah[4], al[4];
            split_tf32(Qs[row0 * QS_STR + d0 + lc],     ah[0], al[0]);
            split_tf32(Qs[row1 * QS_STR + d0 + lc],     ah[1], al[1]);
            split_tf32(Qs[row0 * QS_STR + d0 + lc + 4], ah[2], al[2]);
            split_tf32(Qs[row1 * QS_STR + d0 + lc + 4], ah[3], al[3]);
#pragma unroll
            for (int nt = 0; nt < 8; nt++) {
                uint32_t bh0, bl0, bh1, bl1;
                split_tf32(Ks[(nt * 8 + lr) * KS_STR + d0 + lc],     bh0, bl0);
                split_tf32(Ks[(nt * 8 + lr) * KS_STR + d0 + lc + 4], bh1, bl1);
                mma_tf32(sc[nt][0], sc[nt][1], sc[nt][2], sc[nt][3],
                         ah[0], ah[1], ah[2], ah[3], bh0, bh1);
                mma_tf32(sc[nt][0], sc[nt][1], sc[nt][2], sc[nt][3],
                         ah[0], ah[1], ah[2], ah[3], bl0, bl1);
                mma_tf32(sc[nt][0], sc[nt][1], sc[nt][2], sc[nt][3],
                         al[0], al[1], al[2], al[3], bh0, bh1);
            }
        }

        const bool need_mask = (kt >= 2 * qt);
        float mx0 = -1e30f, mx1 = -1e30f;
#pragma unroll
        for (int nt = 0; nt < 8; nt++) {
#pragma unroll
            for (int j = 0; j < 2; j++) {
                int col = kt * 64 + nt * 8 + 2 * lc + j;
                float s0 = sc[nt][j] * ATT_SCALE;
                float s1 = sc[nt][2 + j] * ATT_SCALE;
                if (need_mask) {
                    if (col > grow0) s0 = -1e30f;
                    if (col > grow1) s1 = -1e30f;
                }
                sc[nt][j] = s0;
                sc[nt][2 + j] = s1;
                mx0 = fmaxf(mx0, s0);
                mx1 = fmaxf(mx1, s1);
            }
        }
        mx0 = fmaxf(mx0, __shfl_xor_sync(0xffffffffu, mx0, 1));
        mx0 = fmaxf(mx0, __shfl_xor_sync(0xffffffffu, mx0, 2));
        mx1 = fmaxf(mx1, __shfl_xor_sync(0xffffffffu, mx1, 1));
        mx1 = fmaxf(mx1, __shfl_xor_sync(0xffffffffu, mx1, 2));
        const float mn0 = fmaxf(m0, mx0);
        const float mn1 = fmaxf(m1, mx1);
        const float scl0 = __expf(m0 - mn0);
        const float scl1 = __expf(m1 - mn1);
        float ls0 = 0.f, ls1 = 0.f;
#pragma unroll
        for (int nt = 0; nt < 8; nt++) {
#pragma unroll
            for (int j = 0; j < 2; j++) {
                float p0 = __expf(sc[nt][j] - mn0);
                float p1 = __expf(sc[nt][2 + j] - mn1);
                ls0 += p0;
                ls1 += p1;
                Ps[row0 * PS_STR + nt * 8 + 2 * lc + j] = p0;
                Ps[row1 * PS_STR + nt * 8 + 2 * lc + j] = p1;
            }
        }
        ls0 += __shfl_xor_sync(0xffffffffu, ls0, 1);
        ls0 += __shfl_xor_sync(0xffffffffu, ls0, 2);
        ls1 += __shfl_xor_sync(0xffffffffu, ls1, 1);
        ls1 += __shfl_xor_sync(0xffffffffu, ls1, 2);
        l0 = l0 * scl0 + ls0;
        l1 = l1 * scl1 + ls1;
        m0 = mn0;
        m1 = mn1;

#pragma unroll
        for (int nt = 0; nt < 16; nt++) {
            o[nt][0] *= scl0;
            o[nt][1] *= scl0;
            o[nt][2] *= scl1;
            o[nt][3] *= scl1;
        }
        __syncwarp();

#pragma unroll
        for (int ks2 = 0; ks2 < 8; ks2++) {
            const int k0 = ks2 * 8;
            uint32_t ah[4], al[4];
            split_tf32(Ps[row0 * PS_STR + k0 + lc],     ah[0], al[0]);
            split_tf32(Ps[row1 * PS_STR + k0 + lc],     ah[1], al[1]);
            split_tf32(Ps[row0 * PS_STR + k0 + lc + 4], ah[2], al[2]);
            split_tf32(Ps[row1 * PS_STR + k0 + lc + 4], ah[3], al[3]);
#pragma unroll
            for (int nt = 0; nt < 16; nt++) {
                uint32_t bh0, bl0, bh1, bl1;
                split_tf32(Vs[(k0 + lc) * VS_STR + nt * 8 + lr],       bh0, bl0);
                split_tf32(Vs[(k0 + 4 + lc) * VS_STR + nt * 8 + lr],   bh1, bl1);
                mma_tf32(o[nt][0], o[nt][1], o[nt][2], o[nt][3],
                         ah[0], ah[1], ah[2], ah[3], bh0, bh1);
                mma_tf32(o[nt][0], o[nt][1], o[nt][2], o[nt][3],
                         ah[0], ah[1], ah[2], ah[3], bl0, bl1);
                mma_tf32(o[nt][0], o[nt][1], o[nt][2], o[nt][3],
                         al[0], al[1], al[2], al[3], bh0, bh1);
            }
        }
    }

    // epilogue: gate-combine, store tf32-rounded (O-proj GEMM consumes raw bits)
    const float g = 1.f / (1.f + __expf(-beta[0]));
    const float og = 1.f - g;
    const float li0 = 1.f / l0;
    const float li1 = 1.f / l1;
#pragma unroll
    for (int nt = 0; nt < 16; nt++) {
        const int col = nt * 8 + 2 * lc;
        size_t i0 = (size_t)grow0 * HID + h * HD + col;
        size_t i1 = (size_t)grow1 * HID + h * HD + col;
        float2 mo0 = *(const float2*)(memout + i0);
        float2 mo1 = *(const float2*)(memout + i1);
        float2 r0, r1;
        r0.x = f2tf32f(g * mo0.x + og * (o[nt][0] * li0));
        r0.y = f2tf32f(g * mo0.y + og * (o[nt][1] * li0));
        r1.x = f2tf32f(g * mo1.x + og * (o[nt][2] * li1));
        r1.y = f2tf32f(g * mo1.y + og * (o[nt][3] * li1));
        *(float2*)(outc + i0) = r0;
        *(float2*)(outc + i1) = r1;
    }
}

// ---------------- delta-rule partials ----------------
__global__ __launch_bounds__(256) void delta_part_kernel(
    const float* __restrict__ kn, const float* __restrict__ vd, float* __restrict__ part)
{
    const int h = blockIdx.x;
    const int c = blockIdx.y;
    __shared__ float Ak[32][128];
    __shared__ float Bv[32][128];
    const int trow = (threadIdx.x >> 4) * 8;
    const int tcol = (threadIdx.x & 15) * 8;
    float acc[8][8];
#pragma unroll
    for (int i = 0; i < 8; i++)
#pragma unroll
        for (int j = 0; j < 8; j++) acc[i][j] = 0.f;

    const int sbeg = c * 256;
    for (int s0 = sbeg; s0 < sbeg + 256; s0 += 32) {
        for (int i = threadIdx.x; i < 32 * 128; i += 256) {
            int ss = i >> 7, dd = i & 127;
            size_t idx = (size_t)(s0 + ss) * (NKV * HD) + h * HD + dd;
            Ak[ss][dd] = kn[idx];
            Bv[ss][dd] = vd[idx];
        }
        __syncthreads();
#pragma unroll 4
        for (int ss = 0; ss < 32; ss++) {
            float ra[8], rb[8];
#pragma unroll
            for (int i = 0; i < 8; i++) ra[i] = Ak[ss][trow + i];
#pragma unroll
            for (int j = 0; j < 8; j++) rb[j] = Bv[ss][tcol + j];
#pragma unroll
            for (int i = 0; i < 8; i++)
#pragma unroll
                for (int j = 0; j < 8; j++) acc[i][j] += ra[i] * rb[j];
        }
        __syncthreads();
    }
    float* Ph = part + (size_t)c * (NKV * HD * HD) + h * HD * HD;
#pragma unroll
    for (int i = 0; i < 8; i++)
#pragma unroll
        for (int j = 0; j < 8; j++)
            Ph[(trow + i) * HD + tcol + j] = acc[i][j];
}

__global__ __launch_bounds__(256) void delta_final_kernel(
    const float* __restrict__ part, const float* __restrict__ memory, float* __restrict__ outmem)
{
    const int i = blockIdx.x * 256 + threadIdx.x;
    float acc = memory[i];
#pragma unroll
    for (int c = 0; c < 8; c++) acc += part[(size_t)c * (NKV * HD * HD) + i];
    outmem[i] = acc;
}

// ---------------- updated_norm ----------------
__global__ __launch_bounds__(256) void norm_kernel(
    const float* __restrict__ norm_m, const float* __restrict__ knsum, float* __restrict__ out)
{
    const int i = blockIdx.x * 256 + threadIdx.x;
    const int h = i >> 14;
    const int j = i & 127;
    out[i] = norm_m[i] + knsum[h * HD + j];
}

// ---------------- launch ----------------
extern "C" void kernel_launch(void* const* d_in, const int* in_sizes, int n_in,
                              void* d_out, int out_size)
{
    const float* hidden = (const float*)d_in[0];
    const int*   pos    = (const int*)d_in[1];
    const float* wq     = (const float*)d_in[2];
    const float* wk     = (const float*)d_in[3];
    const float* wv     = (const float*)d_in[4];
    const float* wo     = (const float*)d_in[5];
    const float* memory = (const float*)d_in[6];
    const float* norm_m = (const float*)d_in[7];
    const float* beta   = (const float*)d_in[8];
    float* out = (float*)d_out;

    float *qproj, *kproj, *vproj, *qn, *kn, *memout, *vdelta, *knsum, *knpart, *combined, *dpart;
    float *hid_r, *wq_r, *wk_r, *wv_r, *wo_r;
    cudaGetSymbolAddress((void**)&qproj, g_qproj);
    cudaGetSymbolAddress((void**)&kproj, g_kproj);
    cudaGetSymbolAddress((void**)&vproj, g_vproj);
    cudaGetSymbolAddress((void**)&qn, g_qn);
    cudaGetSymbolAddress((void**)&kn, g_kn);
    cudaGetSymbolAddress((void**)&memout, g_memout);
    cudaGetSymbolAddress((void**)&vdelta, g_vdelta);
    cudaGetSymbolAddress((void**)&knsum, g_knsum);
    cudaGetSymbolAddress((void**)&knpart, g_knsum_part);
    cudaGetSymbolAddress((void**)&combined, g_combined);
    cudaGetSymbolAddress((void**)&dpart, g_delta_part);
    cudaGetSymbolAddress((void**)&hid_r, g_hid_r);
    cudaGetSymbolAddress((void**)&wq_r, g_wq_r);
    cudaGetSymbolAddress((void**)&wk_r, g_wk_r);
    cudaGetSymbolAddress((void**)&wv_r, g_wv_r);
    cudaGetSymbolAddress((void**)&wo_r, g_wo_r);

    cudaFuncSetAttribute(attn_mma_kernel,
                         cudaFuncAttributeMaxDynamicSharedMemorySize, ATT_SMEM_BYTES);
    cudaFuncSetAttribute(gemm_v3_kernel,
                         cudaFuncAttributeMaxDynamicSharedMemorySize, GEMM3_SMEM);

    // pre-round all GEMM inputs to tf32 (one fused launch)
    round_all_kernel<<<2048, 256>>>(hidden, hid_r, wq, wq_r, wk, wk_r, wv, wv_r, wo, wo_r);

    // all three projections in ONE launch: z=0 -> Q (N=4096); z=1 -> x<8: K, x<16: V (N=1024)
    gemm_v3_kernel<<<dim3(HID / 128, S / 128, 2), 128, GEMM3_SMEM>>>(
        hid_r, wq_r, qproj, HID, wk_r, kproj, wv_r, vproj, NKV * HD, HID);

    // normalized features from PRE-RoPE q/k
    qn_kernel<<<S, 128>>>(qproj, qn);
    kn_kernel<<<S, 128>>>(kproj, kn);
    knsum_part_kernel<<<dim3(NKV, 16), 128>>>(kn, knpart);
    knsum_final_kernel<<<1, 1024>>>(knpart, knsum);

    // compressive-memory retrieval + delta-rule prep
    retrieve_kernel<<<dim3(S / 16, NH), 128>>>(qn, memory, norm_m, memout);
    vdelta_kernel<<<dim3(S / 16, NKV), 128>>>(kn, vproj, memory, norm_m, vdelta);

    // RoPE in place, then MMA flash attention (fuses gated combine, emits tf32-rounded)
    rope_kernel<<<dim3(S, 10), 256>>>(qproj, kproj, pos);
    attn_mma_kernel<<<dim3(S / 128, NH), 256, ATT_SMEM_BYTES>>>(
        qproj, kproj, vproj, memout, beta, combined);

    // output projection
    gemm_v3_kernel<<<dim3(HID / 128, S / 128, 1), 128, GEMM3_SMEM>>>(
        combined, wo_r, out, HID, wo_r, out, wo_r, out, HID, HID);

    // memory & norm updates (appended after the 8.4M-element `out`)
    delta_part_kernel<<<dim3(NKV, 8), 256>>>(kn, vdelta, dpart);
    delta_final_kernel<<<(NKV * HD * HD) / 256, 256>>>(dpart, memory, out + (size_t)S * HID);
    norm_kernel<<<(NKV * HD * HD) / 256, 256>>>(norm_m, knsum,
                                                out + (size_t)S * HID + NKV * HD * HD);
}

// round 8
// speedup vs baseline: 3.6998x; 1.2935x over previous
#include <cuda_runtime.h>
#include <cuda_bf16.h>
#include <cuda_fp16.h>
#include <math.h>
#include <stdint.h>

// ---------------- problem constants ----------------
#define S 2048
#define HID 4096
#define NH 32
#define NKV 8
#define HD 128
#define GROUPS 4
#define EPS 1e-8f
#define ATT_SCALE 0.08838834764831845f   // 128^-0.5
#define LN10000 9.210340371976184f

// ---------------- scratch (device globals; no allocation allowed) ----------------
__device__ float g_qproj[S * HID];
__device__ float g_kproj[S * NKV * HD];
__device__ float g_vproj[S * NKV * HD];
__device__ float g_qn[S * HID];
__device__ float g_kn[S * NKV * HD];
__device__ float g_memout[S * HID];
__device__ float g_vdelta[S * NKV * HD];
__device__ float g_knsum[NKV * HD];
__device__ float g_knsum_part[16][NKV * HD];
__device__ float g_delta_part[8][NKV * HD * HD];
// fp16 GEMM operands
__device__ __half g_hh[S * HID];             // hidden, [M][K]
__device__ __half g_wqT[HID * HID];          // [N][K]
__device__ __half g_wkT[NKV * HD * HID];
__device__ __half g_wvT[NKV * HD * HID];
__device__ __half g_woT[HID * HID];
__device__ __half g_ch[S * HID];             // combined (attention out), [M][K]

// ---------------- tf32 helpers (attention only) ----------------
__device__ __forceinline__ uint32_t f2tf32(float x) {
    uint32_t y;
    asm("cvt.rna.tf32.f32 %0, %1;" : "=r"(y) : "f"(x));
    return y;
}
__device__ __forceinline__ void split_tf32(float f, uint32_t& hi, uint32_t& lo) {
    hi = f2tf32(f);
    lo = f2tf32(f - __uint_as_float(hi));
}
__device__ __forceinline__ void mma_tf32(
    float& c0, float& c1, float& c2, float& c3,
    uint32_t a0, uint32_t a1, uint32_t a2, uint32_t a3,
    uint32_t b0, uint32_t b1)
{
    asm volatile(
        "mma.sync.aligned.m16n8k8.row.col.f32.tf32.tf32.f32 "
        "{%0,%1,%2,%3},{%4,%5,%6,%7},{%8,%9},{%0,%1,%2,%3};"
        : "+f"(c0), "+f"(c1), "+f"(c2), "+f"(c3)
        : "r"(a0), "r"(a1), "r"(a2), "r"(a3), "r"(b0), "r"(b1));
}

// ---------------- fp16 mma ----------------
__device__ __forceinline__ void mma_f16(
    float& c0, float& c1, float& c2, float& c3,
    uint32_t a0, uint32_t a1, uint32_t a2, uint32_t a3,
    uint32_t b0, uint32_t b1)
{
    asm volatile(
        "mma.sync.aligned.m16n8k16.row.col.f32.f16.f16.f32 "
        "{%0,%1,%2,%3},{%4,%5,%6,%7},{%8,%9},{%0,%1,%2,%3};"
        : "+f"(c0), "+f"(c1), "+f"(c2), "+f"(c3)
        : "r"(a0), "r"(a1), "r"(a2), "r"(a3), "r"(b0), "r"(b1));
}

__device__ __forceinline__ uint32_t h2pack(float a, float b) {
    __half2 h = __floats2half2_rn(a, b);
    return *(uint32_t*)&h;
}

// ---------------- pre-pass: fp32 -> fp16 ----------------
__global__ __launch_bounds__(256) void h2h_kernel(
    const float* __restrict__ src, __half* __restrict__ dst, int n4)
{
    for (int i = blockIdx.x * 256 + threadIdx.x; i < n4; i += gridDim.x * 256) {
        float4 v = ((const float4*)src)[i];
        uint2 p = make_uint2(h2pack(v.x, v.y), h2pack(v.z, v.w));
        ((uint2*)dst)[i] = p;
    }
}

// transpose: w[K][N] fp32 -> wT[N][K] fp16
__global__ __launch_bounds__(256) void wtrans_kernel(
    const float* __restrict__ w, __half* __restrict__ wt, int Kd, int Nd)
{
    __shared__ float t[32][33];
    const int bx = blockIdx.x;   // N tile
    const int by = blockIdx.y;   // K tile
    const int x = threadIdx.x & 31;
    const int y = threadIdx.x >> 5;
#pragma unroll
    for (int j = 0; j < 4; j++) {
        int kr = y + 8 * j;
        t[kr][x] = w[(size_t)(by * 32 + kr) * Nd + bx * 32 + x];
    }
    __syncthreads();
#pragma unroll
    for (int j = 0; j < 4; j++) {
        int nr = y + 8 * j;
        wt[(size_t)(bx * 32 + nr) * Kd + by * 32 + x] = __float2half_rn(t[x][nr]);
    }
}

// ---------------- GEMM v4: fp16 m16n8k16, 4 warps, 64x64 warp tile, BK=32, 3-stage ----------------
// C[M,N] = A[M,K] @ Bt[N,K]^T; A,Bt fp16, C fp32.
#define HAS_STR 40    // halves per A row (80B) - conflict-free
#define HBS_STR 40    // halves per B row
#define STG4_BYTES ((128 * HAS_STR + 128 * HBS_STR) * 2)   // 20480
#define GEMM4_SMEM (3 * STG4_BYTES)                        // 61440

#define CP16(dst_u32, src_ptr) \
    asm volatile("cp.async.cg.shared.global [%0], [%1], 16;" :: "r"(dst_u32), "l"(src_ptr))

__global__ __launch_bounds__(128, 2) void gemm_f16_kernel(
    const __half* __restrict__ A,
    const __half* __restrict__ B0, float* __restrict__ C0, int N0,
    const __half* __restrict__ B1, float* __restrict__ C1,
    const __half* __restrict__ B2, float* __restrict__ C2, int N12,
    int K)
{
    const __half* Bt;
    float* C;
    int N, bx;
    if (blockIdx.z == 0) {
        Bt = B0; C = C0; N = N0; bx = blockIdx.x;
        if (bx * 128 >= N0) return;
    } else {
        N = N12;
        const int nt12 = N12 / 128;
        if ((int)blockIdx.x < nt12) { Bt = B1; C = C1; bx = blockIdx.x; }
        else if ((int)blockIdx.x < 2 * nt12) { Bt = B2; C = C2; bx = blockIdx.x - nt12; }
        else return;
    }

    extern __shared__ __half smh[];
    const uint32_t smu = (uint32_t)__cvta_generic_to_shared(smh);

    const int tid = threadIdx.x;
    const int lane = tid & 31;
    const int wid = tid >> 5;        // 0..3
    const int wm = wid >> 1;         // 0..1 -> 64 rows
    const int wn = wid & 1;          // 0..1 -> 64 cols
    const int lr = lane >> 2;        // 0..7
    const int lc = lane & 3;         // 0..3
    const int by = blockIdx.y;

    // cp.async mapping: 128 rows x 4 chunks (16B = 8 halves), 128 threads, 4 iters each
    const int crow = tid >> 2;       // 0..31 base row
    const int cchk = (tid & 3) * 8;  // halves offset 0,8,16,24

    const __half* Ab = A + (size_t)(by * 128) * K;
    const __half* Bb = Bt + (size_t)(bx * 128) * K;

    float acc[4][8][4];
#pragma unroll
    for (int i = 0; i < 4; i++)
#pragma unroll
        for (int j = 0; j < 8; j++)
#pragma unroll
            for (int r = 0; r < 4; r++) acc[i][j][r] = 0.f;

    const int NT = K / 32;

#define LOAD_STAGE(stg, ch)                                                           \
    {                                                                                 \
        const uint32_t sb = smu + (uint32_t)((stg) * STG4_BYTES);                     \
        const int k0 = (ch) * 32;                                                     \
        _Pragma("unroll")                                                             \
        for (int i = 0; i < 4; i++) {                                                 \
            const int r = i * 32 + crow;                                              \
            CP16(sb + (uint32_t)((r * HAS_STR + cchk) * 2), Ab + (size_t)r * K + k0 + cchk); \
        }                                                                             \
        _Pragma("unroll")                                                             \
        for (int i = 0; i < 4; i++) {                                                 \
            const int r = i * 32 + crow;                                              \
            CP16(sb + (uint32_t)((128 * HAS_STR + r * HBS_STR + cchk) * 2),           \
                 Bb + (size_t)r * K + k0 + cchk);                                     \
        }                                                                             \
    }

    LOAD_STAGE(0, 0)
    asm volatile("cp.async.commit_group;" ::: "memory");
    LOAD_STAGE(1, 1)
    asm volatile("cp.async.commit_group;" ::: "memory");

    int stage = 0;
    for (int it = 0; it < NT; it++) {
        asm volatile("cp.async.wait_group 1;" ::: "memory");
        __syncthreads();

        const int pf = it + 2;
        if (pf < NT) {
            const int ps = (stage + 2) % 3;
            LOAD_STAGE(ps, pf)
        }
        asm volatile("cp.async.commit_group;" ::: "memory");

        const __half* As_ = smh + stage * (STG4_BYTES / 2);
        const __half* Bs_ = As_ + 128 * HAS_STR;

#pragma unroll
        for (int ks = 0; ks < 2; ks++) {
            const int kb = ks * 16;
            uint32_t af[4][4], bf[8][2];
#pragma unroll
            for (int mt = 0; mt < 4; mt++) {
                const int m0 = wm * 64 + mt * 16 + lr;
                const __half* p0 = As_ + m0 * HAS_STR + kb + 2 * lc;
                const __half* p1 = As_ + (m0 + 8) * HAS_STR + kb + 2 * lc;
                af[mt][0] = *(const uint32_t*)(p0);
                af[mt][1] = *(const uint32_t*)(p1);
                af[mt][2] = *(const uint32_t*)(p0 + 8);
                af[mt][3] = *(const uint32_t*)(p1 + 8);
            }
#pragma unroll
            for (int nt = 0; nt < 8; nt++) {
                const int n0 = wn * 64 + nt * 8 + lr;
                const __half* p = Bs_ + n0 * HBS_STR + kb + 2 * lc;
                bf[nt][0] = *(const uint32_t*)(p);
                bf[nt][1] = *(const uint32_t*)(p + 8);
            }
#pragma unroll
            for (int mt = 0; mt < 4; mt++)
#pragma unroll
                for (int nt = 0; nt < 8; nt++)
                    mma_f16(acc[mt][nt][0], acc[mt][nt][1], acc[mt][nt][2], acc[mt][nt][3],
                            af[mt][0], af[mt][1], af[mt][2], af[mt][3],
                            bf[nt][0], bf[nt][1]);
        }
        stage = (stage + 1) % 3;
    }
#undef LOAD_STAGE

    // epilogue
#pragma unroll
    for (int mt = 0; mt < 4; mt++) {
        const int row = by * 128 + wm * 64 + mt * 16 + lr;
#pragma unroll
        for (int nt = 0; nt < 8; nt++) {
            const int col = bx * 128 + wn * 64 + nt * 8 + lc * 2;
            float2 v01 = make_float2(acc[mt][nt][0], acc[mt][nt][1]);
            float2 v23 = make_float2(acc[mt][nt][2], acc[mt][nt][3]);
            *(float2*)(C + (size_t)row * N + col) = v01;
            *(float2*)(C + (size_t)(row + 8) * N + col) = v23;
        }
    }
}

// ---------------- qn / kn ----------------
__global__ __launch_bounds__(128) void qn_kernel(const float* __restrict__ qp, float* __restrict__ qn)
{
    const int s = blockIdx.x;
    const int d = threadIdx.x;
    __shared__ float wsum[4];
    for (int h = 0; h < NH; h++) {
        float x = qp[(size_t)s * HID + h * HD + d];
        float f = x > 0.f ? x + 1.f : expf(x);
        float v = f;
#pragma unroll
        for (int o = 16; o; o >>= 1) v += __shfl_xor_sync(0xffffffffu, v, o);
        if ((d & 31) == 0) wsum[d >> 5] = v;
        __syncthreads();
        float tot = wsum[0] + wsum[1] + wsum[2] + wsum[3];
        qn[(size_t)s * HID + h * HD + d] = f / (tot + EPS);
        __syncthreads();
    }
}

__global__ __launch_bounds__(128) void kn_kernel(const float* __restrict__ kp, float* __restrict__ kn)
{
    const int s = blockIdx.x;
    const int d = threadIdx.x;
    __shared__ float wsum[4];
    for (int h = 0; h < NKV; h++) {
        float x = kp[(size_t)s * (NKV * HD) + h * HD + d];
        float f = x > 0.f ? x + 1.f : expf(x);
        float v = f;
#pragma unroll
        for (int o = 16; o; o >>= 1) v += __shfl_xor_sync(0xffffffffu, v, o);
        if ((d & 31) == 0) wsum[d >> 5] = v;
        __syncthreads();
        float tot = wsum[0] + wsum[1] + wsum[2] + wsum[3];
        kn[(size_t)s * (NKV * HD) + h * HD + d] = f / (tot + EPS);
        __syncthreads();
    }
}

__global__ __launch_bounds__(128) void knsum_part_kernel(const float* __restrict__ kn, float* __restrict__ part)
{
    const int h = blockIdx.x;
    const int p = blockIdx.y;
    const int d = threadIdx.x;
    float acc = 0.f;
    const int s0 = p * 128;
#pragma unroll 4
    for (int s = s0; s < s0 + 128; s++)
        acc += kn[(size_t)s * (NKV * HD) + h * HD + d];
    part[p * (NKV * HD) + h * HD + d] = acc;
}

__global__ __launch_bounds__(1024) void knsum_final_kernel(const float* __restrict__ part, float* __restrict__ knsum)
{
    const int i = threadIdx.x;
    float acc = 0.f;
#pragma unroll
    for (int p = 0; p < 16; p++) acc += part[p * (NKV * HD) + i];
    knsum[i] = acc;
}

// ---------------- memory retrieval ----------------
__global__ __launch_bounds__(128) void retrieve_kernel(
    const float* __restrict__ qn, const float* __restrict__ memory,
    const float* __restrict__ norm_m, float* __restrict__ memout)
{
    const int h = blockIdx.y;
    const int st = blockIdx.x;
    const int hm = h & (NKV - 1);
    const int e = threadIdx.x;
    __shared__ float Qs[16][128];
    __shared__ float Ms[32][128];
    __shared__ float Ns[128][33];

    for (int i = e; i < 16 * 128; i += 128) {
        int r = i >> 7, d = i & 127;
        Qs[r][d] = qn[(size_t)(st * 16 + r) * HID + h * HD + d];
    }
    float num[16], den[16];
#pragma unroll
    for (int r = 0; r < 16; r++) { num[r] = 0.f; den[r] = 0.f; }
    const float* M = memory + hm * HD * HD;
    const float* Nm = norm_m + hm * HD * HD;

    for (int d0 = 0; d0 < 128; d0 += 32) {
        __syncthreads();
        for (int i = e; i < 32 * 128; i += 128) {
            int dd = i >> 7, ee = i & 127;
            Ms[dd][ee] = M[(d0 + dd) * HD + ee];
        }
        for (int i = e; i < 128 * 32; i += 128) {
            int ee = i >> 5, dd = i & 31;
            Ns[ee][dd] = Nm[ee * HD + d0 + dd];
        }
        __syncthreads();
#pragma unroll 4
        for (int dd = 0; dd < 32; dd++) {
            float mv = Ms[dd][e];
            float nv = Ns[e][dd];
#pragma unroll
            for (int r = 0; r < 16; r++) {
                float qv = Qs[r][d0 + dd];
                num[r] += qv * mv;
                den[r] += qv * nv;
            }
        }
    }
#pragma unroll
    for (int r = 0; r < 16; r++)
        memout[(size_t)(st * 16 + r) * HID + h * HD + e] = num[r] / (den[r] + EPS);
}

// ---------------- v - v_ret for delta rule ----------------
__global__ __launch_bounds__(128) void vdelta_kernel(
    const float* __restrict__ kn, const float* __restrict__ vproj,
    const float* __restrict__ memory, const float* __restrict__ norm_m,
    float* __restrict__ vdelta)
{
    const int h = blockIdx.y;
    const int st = blockIdx.x;
    const int e = threadIdx.x;
    __shared__ float Qs[16][128];
    __shared__ float Ms[32][128];
    __shared__ float Ns[128][33];

    for (int i = e; i < 16 * 128; i += 128) {
        int r = i >> 7, d = i & 127;
        Qs[r][d] = kn[(size_t)(st * 16 + r) * (NKV * HD) + h * HD + d];
    }
    float num[16], den[16];
#pragma unroll
    for (int r = 0; r < 16; r++) { num[r] = 0.f; den[r] = 0.f; }
    const float* M = memory + h * HD * HD;
    const float* Nm = norm_m + h * HD * HD;

    for (int d0 = 0; d0 < 128; d0 += 32) {
        __syncthreads();
        for (int i = e; i < 32 * 128; i += 128) {
            int dd = i >> 7, ee = i & 127;
            Ms[dd][ee] = M[(d0 + dd) * HD + ee];
        }
        for (int i = e; i < 128 * 32; i += 128) {
            int ee = i >> 5, dd = i & 31;
            Ns[ee][dd] = Nm[ee * HD + d0 + dd];
        }
        __syncthreads();
#pragma unroll 4
        for (int dd = 0; dd < 32; dd++) {
            float mv = Ms[dd][e];
            float nv = Ns[e][dd];
#pragma unroll
            for (int r = 0; r < 16; r++) {
                float qv = Qs[r][d0 + dd];
                num[r] += qv * mv;
                den[r] += qv * nv;
            }
        }
    }
#pragma unroll
    for (int r = 0; r < 16; r++) {
        size_t idx = (size_t)(st * 16 + r) * (NKV * HD) + h * HD + e;
        vdelta[idx] = vproj[idx] - num[r] / (den[r] + EPS);
    }
}

// ---------------- RoPE ----------------
__global__ __launch_bounds__(256) void rope_kernel(
    float* __restrict__ q, float* __restrict__ k, const int* __restrict__ pos)
{
    const int s = blockIdx.x;
    const int idx = blockIdx.y * 256 + threadIdx.x;
    if (idx >= (NH + NKV) * 64) return;
    const int head = idx >> 6;
    const int d = idx & 63;
    const float p = (float)pos[s];
    const float invf = expf(-(2.0f * (float)d / 128.0f) * LN10000);
    const float a = p * invf;
    const float c = cosf(a), sn = sinf(a);
    float* base = (head < NH) ? (q + (size_t)s * HID + head * HD)
                              : (k + (size_t)s * (NKV * HD) + (head - NH) * HD);
    float x0 = base[d], x1 = base[d + 64];
    base[d]      = x0 * c - x1 * sn;
    base[d + 64] = x1 * c + x0 * sn;
}

// ---------------- MMA flash attention (3x-split tf32, fp32-accurate) ----------------
// Emits combined = g*memout + (1-g)*attn as fp16 for the O-proj GEMM.
#define QS_STR 132
#define KS_STR 132
#define VS_STR 136
#define PS_STR 68
#define ATT_SMEM_FLOATS (128 * QS_STR + 64 * KS_STR + 64 * VS_STR + 128 * PS_STR)
#define ATT_SMEM_BYTES (ATT_SMEM_FLOATS * 4)

__global__ __launch_bounds__(256) void attn_mma_kernel(
    const float* __restrict__ q, const float* __restrict__ k,
    const float* __restrict__ v, const float* __restrict__ memout,
    const float* __restrict__ beta, __half* __restrict__ ch)
{
    const int h = blockIdx.y;
    const int qt = (int)gridDim.x - 1 - (int)blockIdx.x;
    const int kvh = h >> 2;
    const int tid = threadIdx.x;
    const int warp = tid >> 5;
    const int lane = tid & 31;
    const int lr = lane >> 2;
    const int lc = lane & 3;

    extern __shared__ float smem[];
    float* Qs = smem;
    float* Ks = Qs + 128 * QS_STR;
    float* Vs = Ks + 64 * KS_STR;
    float* Ps = Vs + 64 * VS_STR;

#pragma unroll
    for (int it = 0; it < 16; it++) {
        int i = it * 256 + tid;
        int row = i >> 5, c4 = (i & 31) * 4;
        float4 t = *(const float4*)(q + (size_t)(qt * 128 + row) * HID + h * HD + c4);
        *(float4*)(Qs + row * QS_STR + c4) = t;
    }

    const int row0 = warp * 16 + lr;
    const int row1 = row0 + 8;
    const int grow0 = qt * 128 + row0;
    const int grow1 = grow0 + 8;

    float m0 = -1e30f, m1 = -1e30f, l0 = 0.f, l1 = 0.f;
    float o[16][4];
#pragma unroll
    for (int nt = 0; nt < 16; nt++)
#pragma unroll
        for (int r = 0; r < 4; r++) o[nt][r] = 0.f;

    const int ktmax = 2 * qt + 1;
    for (int kt = 0; kt <= ktmax; kt++) {
        __syncthreads();
#pragma unroll
        for (int it = 0; it < 8; it++) {
            int i = it * 256 + tid;
            int key = i >> 5, c4 = (i & 31) * 4;
            size_t gidx = (size_t)(kt * 64 + key) * (NKV * HD) + kvh * HD + c4;
            float4 tk = *(const float4*)(k + gidx);
            *(float4*)(Ks + key * KS_STR + c4) = tk;
            float4 tv = *(const float4*)(v + gidx);
            *(float4*)(Vs + key * VS_STR + c4) = tv;
        }
        __syncthreads();

        float sc[8][4];
#pragma unroll
        for (int nt = 0; nt < 8; nt++)
#pragma unroll
            for (int r = 0; r < 4; r++) sc[nt][r] = 0.f;

#pragma unroll
        for (int ks = 0; ks < 16; ks++) {
            const int d0 = ks * 8;
            uint32_t ah[4], al[4];
            split_tf32(Qs[row0 * QS_STR + d0 + lc],     ah[0], al[0]);
            split_tf32(Qs[row1 * QS_STR + d0 + lc],     ah[1], al[1]);
            split_tf32(Qs[row0 * QS_STR + d0 + lc + 4], ah[2], al[2]);
            split_tf32(Qs[row1 * QS_STR + d0 + lc + 4], ah[3], al[3]);
#pragma unroll
            for (int nt = 0; nt < 8; nt++) {
                uint32_t bh0, bl0, bh1, bl1;
                split_tf32(Ks[(nt * 8 + lr) * KS_STR + d0 + lc],     bh0, bl0);
                split_tf32(Ks[(nt * 8 + lr) * KS_STR + d0 + lc + 4], bh1, bl1);
                mma_tf32(sc[nt][0], sc[nt][1], sc[nt][2], sc[nt][3],
                         ah[0], ah[1], ah[2], ah[3], bh0, bh1);
                mma_tf32(sc[nt][0], sc[nt][1], sc[nt][2], sc[nt][3],
                         ah[0], ah[1], ah[2], ah[3], bl0, bl1);
                mma_tf32(sc[nt][0], sc[nt][1], sc[nt][2], sc[nt][3],
                         al[0], al[1], al[2], al[3], bh0, bh1);
            }
        }

        const bool need_mask = (kt >= 2 * qt);
        float mx0 = -1e30f, mx1 = -1e30f;
#pragma unroll
        for (int nt = 0; nt < 8; nt++) {
#pragma unroll
            for (int j = 0; j < 2; j++) {
                int col = kt * 64 + nt * 8 + 2 * lc + j;
                float s0 = sc[nt][j] * ATT_SCALE;
                float s1 = sc[nt][2 + j] * ATT_SCALE;
                if (need_mask) {
                    if (col > grow0) s0 = -1e30f;
                    if (col > grow1) s1 = -1e30f;
                }
                sc[nt][j] = s0;
                sc[nt][2 + j] = s1;
                mx0 = fmaxf(mx0, s0);
                mx1 = fmaxf(mx1, s1);
            }
        }
        mx0 = fmaxf(mx0, __shfl_xor_sync(0xffffffffu, mx0, 1));
        mx0 = fmaxf(mx0, __shfl_xor_sync(0xffffffffu, mx0, 2));
        mx1 = fmaxf(mx1, __shfl_xor_sync(0xffffffffu, mx1, 1));
        mx1 = fmaxf(mx1, __shfl_xor_sync(0xffffffffu, mx1, 2));
        const float mn0 = fmaxf(m0, mx0);
        const float mn1 = fmaxf(m1, mx1);
        const float scl0 = __expf(m0 - mn0);
        const float scl1 = __expf(m1 - mn1);
        float ls0 = 0.f, ls1 = 0.f;
#pragma unroll
        for (int nt = 0; nt < 8; nt++) {
#pragma unroll
            for (int j = 0; j < 2; j++) {
                float p0 = __expf(sc[nt][j] - mn0);
                float p1 = __expf(sc[nt][2 + j] - mn1);
                ls0 += p0;
                ls1 += p1;
                Ps[row0 * PS_STR + nt * 8 + 2 * lc + j] = p0;
                Ps[row1 * PS_STR + nt * 8 + 2 * lc + j] = p1;
            }
        }
        ls0 += __shfl_xor_sync(0xffffffffu, ls0, 1);
        ls0 += __shfl_xor_sync(0xffffffffu, ls0, 2);
        ls1 += __shfl_xor_sync(0xffffffffu, ls1, 1);
        ls1 += __shfl_xor_sync(0xffffffffu, ls1, 2);
        l0 = l0 * scl0 + ls0;
        l1 = l1 * scl1 + ls1;
        m0 = mn0;
        m1 = mn1;

#pragma unroll
        for (int nt = 0; nt < 16; nt++) {
            o[nt][0] *= scl0;
            o[nt][1] *= scl0;
            o[nt][2] *= scl1;
            o[nt][3] *= scl1;
        }
        __syncwarp();

#pragma unroll
        for (int ks2 = 0; ks2 < 8; ks2++) {
            const int k0 = ks2 * 8;
            uint32_t ah[4], al[4];
            split_tf32(Ps[row0 * PS_STR + k0 + lc],     ah[0], al[0]);
            split_tf32(Ps[row1 * PS_STR + k0 + lc],     ah[1], al[1]);
            split_tf32(Ps[row0 * PS_STR + k0 + lc + 4], ah[2], al[2]);
            split_tf32(Ps[row1 * PS_STR + k0 + lc + 4], ah[3], al[3]);
#pragma unroll
            for (int nt = 0; nt < 16; nt++) {
                uint32_t bh0, bl0, bh1, bl1;
                split_tf32(Vs[(k0 + lc) * VS_STR + nt * 8 + lr],       bh0, bl0);
                split_tf32(Vs[(k0 + 4 + lc) * VS_STR + nt * 8 + lr],   bh1, bl1);
                mma_tf32(o[nt][0], o[nt][1], o[nt][2], o[nt][3],
                         ah[0], ah[1], ah[2], ah[3], bh0, bh1);
                mma_tf32(o[nt][0], o[nt][1], o[nt][2], o[nt][3],
                         ah[0], ah[1], ah[2], ah[3], bl0, bl1);
                mma_tf32(o[nt][0], o[nt][1], o[nt][2], o[nt][3],
                         al[0], al[1], al[2], al[3], bh0, bh1);
            }
        }
    }

    // epilogue: gate-combine, emit fp16 (O-proj GEMM quantizes to fp16 anyway)
    const float g = 1.f / (1.f + __expf(-beta[0]));
    const float og = 1.f - g;
    const float li0 = 1.f / l0;
    const float li1 = 1.f / l1;
#pragma unroll
    for (int nt = 0; nt < 16; nt++) {
        const int col = nt * 8 + 2 * lc;
        size_t i0 = (size_t)grow0 * HID + h * HD + col;
        size_t i1 = (size_t)grow1 * HID + h * HD + col;
        float2 mo0 = *(const float2*)(memout + i0);
        float2 mo1 = *(const float2*)(memout + i1);
        *(uint32_t*)(ch + i0) = h2pack(g * mo0.x + og * (o[nt][0] * li0),
                                       g * mo0.y + og * (o[nt][1] * li0));
        *(uint32_t*)(ch + i1) = h2pack(g * mo1.x + og * (o[nt][2] * li1),
                                       g * mo1.y + og * (o[nt][3] * li1));
    }
}

// ---------------- delta-rule partials ----------------
__global__ __launch_bounds__(256) void delta_part_kernel(
    const float* __restrict__ kn, const float* __restrict__ vd, float* __restrict__ part)
{
    const int h = blockIdx.x;
    const int c = blockIdx.y;
    __shared__ float Ak[32][128];
    __shared__ float Bv[32][128];
    const int trow = (threadIdx.x >> 4) * 8;
    const int tcol = (threadIdx.x & 15) * 8;
    float acc[8][8];
#pragma unroll
    for (int i = 0; i < 8; i++)
#pragma unroll
        for (int j = 0; j < 8; j++) acc[i][j] = 0.f;

    const int sbeg = c * 256;
    for (int s0 = sbeg; s0 < sbeg + 256; s0 += 32) {
        for (int i = threadIdx.x; i < 32 * 128; i += 256) {
            int ss = i >> 7, dd = i & 127;
            size_t idx = (size_t)(s0 + ss) * (NKV * HD) + h * HD + dd;
            Ak[ss][dd] = kn[idx];
            Bv[ss][dd] = vd[idx];
        }
        __syncthreads();
#pragma unroll 4
        for (int ss = 0; ss < 32; ss++) {
            float ra[8], rb[8];
#pragma unroll
            for (int i = 0; i < 8; i++) ra[i] = Ak[ss][trow + i];
#pragma unroll
            for (int j = 0; j < 8; j++) rb[j] = Bv[ss][tcol + j];
#pragma unroll
            for (int i = 0; i < 8; i++)
#pragma unroll
                for (int j = 0; j < 8; j++) acc[i][j] += ra[i] * rb[j];
        }
        __syncthreads();
    }
    float* Ph = part + (size_t)c * (NKV * HD * HD) + h * HD * HD;
#pragma unroll
    for (int i = 0; i < 8; i++)
#pragma unroll
        for (int j = 0; j < 8; j++)
            Ph[(trow + i) * HD + tcol + j] = acc[i][j];
}

__global__ __launch_bounds__(256) void delta_final_kernel(
    const float* __restrict__ part, const float* __restrict__ memory, float* __restrict__ outmem)
{
    const int i = blockIdx.x * 256 + threadIdx.x;
    float acc = memory[i];
#pragma unroll
    for (int c = 0; c < 8; c++) acc += part[(size_t)c * (NKV * HD * HD) + i];
    outmem[i] = acc;
}

// ---------------- updated_norm ----------------
__global__ __launch_bounds__(256) void norm_kernel(
    const float* __restrict__ norm_m, const float* __restrict__ knsum, float* __restrict__ out)
{
    const int i = blockIdx.x * 256 + threadIdx.x;
    const int h = i >> 14;
    const int j = i & 127;
    out[i] = norm_m[i] + knsum[h * HD + j];
}

// ---------------- launch ----------------
extern "C" void kernel_launch(void* const* d_in, const int* in_sizes, int n_in,
                              void* d_out, int out_size)
{
    const float* hidden = (const float*)d_in[0];
    const int*   pos    = (const int*)d_in[1];
    const float* wq     = (const float*)d_in[2];
    const float* wk     = (const float*)d_in[3];
    const float* wv     = (const float*)d_in[4];
    const float* wo     = (const float*)d_in[5];
    const float* memory = (const float*)d_in[6];
    const float* norm_m = (const float*)d_in[7];
    const float* beta   = (const float*)d_in[8];
    float* out = (float*)d_out;

    float *qproj, *kproj, *vproj, *qn, *kn, *memout, *vdelta, *knsum, *knpart, *dpart;
    __half *hh, *wqT, *wkT, *wvT, *woT, *ch;
    cudaGetSymbolAddress((void**)&qproj, g_qproj);
    cudaGetSymbolAddress((void**)&kproj, g_kproj);
    cudaGetSymbolAddress((void**)&vproj, g_vproj);
    cudaGetSymbolAddress((void**)&qn, g_qn);
    cudaGetSymbolAddress((void**)&kn, g_kn);
    cudaGetSymbolAddress((void**)&memout, g_memout);
    cudaGetSymbolAddress((void**)&vdelta, g_vdelta);
    cudaGetSymbolAddress((void**)&knsum, g_knsum);
    cudaGetSymbolAddress((void**)&knpart, g_knsum_part);
    cudaGetSymbolAddress((void**)&dpart, g_delta_part);
    cudaGetSymbolAddress((void**)&hh, g_hh);
    cudaGetSymbolAddress((void**)&wqT, g_wqT);
    cudaGetSymbolAddress((void**)&wkT, g_wkT);
    cudaGetSymbolAddress((void**)&wvT, g_wvT);
    cudaGetSymbolAddress((void**)&woT, g_woT);
    cudaGetSymbolAddress((void**)&ch, g_ch);

    cudaFuncSetAttribute(attn_mma_kernel,
                         cudaFuncAttributeMaxDynamicSharedMemorySize, ATT_SMEM_BYTES);
    cudaFuncSetAttribute(gemm_f16_kernel,
                         cudaFuncAttributeMaxDynamicSharedMemorySize, GEMM4_SMEM);

    // pre-pass: hidden -> fp16; weights -> transposed [N][K] fp16
    h2h_kernel<<<1024, 256>>>(hidden, hh, S * HID / 4);
    wtrans_kernel<<<dim3(HID / 32, HID / 32), 256>>>(wq, wqT, HID, HID);
    wtrans_kernel<<<dim3(NKV * HD / 32, HID / 32), 256>>>(wk, wkT, HID, NKV * HD);
    wtrans_kernel<<<dim3(NKV * HD / 32, HID / 32), 256>>>(wv, wvT, HID, NKV * HD);
    wtrans_kernel<<<dim3(HID / 32, HID / 32), 256>>>(wo, woT, HID, HID);

    // projections (fp16 m16n8k16). z=0: Q (32 tiles); z=1: bx<8 K, bx<16 V.
    gemm_f16_kernel<<<dim3(HID / 128, S / 128, 2), 128, GEMM4_SMEM>>>(
        hh, wqT, qproj, HID, wkT, kproj, wvT, vproj, NKV * HD, HID);

    // normalized features from PRE-RoPE q/k
    qn_kernel<<<S, 128>>>(qproj, qn);
    kn_kernel<<<S, 128>>>(kproj, kn);
    knsum_part_kernel<<<dim3(NKV, 16), 128>>>(kn, knpart);
    knsum_final_kernel<<<1, 1024>>>(knpart, knsum);

    // compressive-memory retrieval + delta-rule prep
    retrieve_kernel<<<dim3(S / 16, NH), 128>>>(qn, memory, norm_m, memout);
    vdelta_kernel<<<dim3(S / 16, NKV), 128>>>(kn, vproj, memory, norm_m, vdelta);

    // RoPE in place, then MMA flash attention (fuses gated combine, emits fp16)
    rope_kernel<<<dim3(S, 10), 256>>>(qproj, kproj, pos);
    attn_mma_kernel<<<dim3(S / 128, NH), 256, ATT_SMEM_BYTES>>>(
        qproj, kproj, vproj, memout, beta, ch);

    // output projection (fp16)
    gemm_f16_kernel<<<dim3(HID / 128, S / 128, 1), 128, GEMM4_SMEM>>>(
        ch, woT, out, HID, woT, out, woT, out, HID, HID);

    // memory & norm updates (appended after the 8.4M-element `out`)
    delta_part_kernel<<<dim3(NKV, 8), 256>>>(kn, vdelta, dpart);
    delta_final_kernel<<<(NKV * HD * HD) / 256, 256>>>(dpart, memory, out + (size_t)S * HID);
    norm_kernel<<<(NKV * HD * HD) / 256, 256>>>(norm_m, knsum,
                                                out + (size_t)S * HID + NKV * HD * HD);
}

// round 9
// speedup vs baseline: 4.8399x; 1.3081x over previous
#include <cuda_runtime.h>
#include <cuda_fp16.h>
#include <math.h>
#include <stdint.h>

// ---------------- problem constants ----------------
#define S 2048
#define HID 4096
#define NH 32
#define NKV 8
#define HD 128
#define GROUPS 4
#define EPS 1e-8f
#define ATT_SCALE 0.08838834764831845f   // 128^-0.5
#define LN10000 9.210340371976184f

// ---------------- scratch (device globals; no allocation allowed) ----------------
__device__ float g_qproj[S * HID];
__device__ float g_kproj[S * NKV * HD];
__device__ float g_vproj[S * NKV * HD];
__device__ float g_qn[S * HID];
__device__ float g_kn[S * NKV * HD];
__device__ float g_memout[S * HID];
__device__ float g_vdelta[S * NKV * HD];
__device__ float g_knsum[NKV * HD];
__device__ float g_knsum_part[16][NKV * HD];
__device__ float g_delta_part[8][NKV * HD * HD];
// fp16 GEMM operands
__device__ __half g_hh[S * HID];             // hidden, [M][K]
__device__ __half g_wqT[HID * HID];          // [N][K]
__device__ __half g_wkT[NKV * HD * HID];
__device__ __half g_wvT[NKV * HD * HID];
__device__ __half g_woT[HID * HID];
__device__ __half g_ch[S * HID];             // combined (attention out), [M][K]
// fp16 hi/lo planes for attention
__device__ __half g_qh[S * HID];             // RoPE'd q hi
__device__ __half g_ql[S * HID];             // RoPE'd q lo
__device__ __half g_kh[S * NKV * HD];
__device__ __half g_kl[S * NKV * HD];
__device__ __half g_vth[NKV * HD * S];       // V^T hi: [h*HD+d][s]
__device__ __half g_vtl[NKV * HD * S];

// ---------------- fp16 mma ----------------
__device__ __forceinline__ void mma_f16(
    float& c0, float& c1, float& c2, float& c3,
    uint32_t a0, uint32_t a1, uint32_t a2, uint32_t a3,
    uint32_t b0, uint32_t b1)
{
    asm volatile(
        "mma.sync.aligned.m16n8k16.row.col.f32.f16.f16.f32 "
        "{%0,%1,%2,%3},{%4,%5,%6,%7},{%8,%9},{%0,%1,%2,%3};"
        : "+f"(c0), "+f"(c1), "+f"(c2), "+f"(c3)
        : "r"(a0), "r"(a1), "r"(a2), "r"(a3), "r"(b0), "r"(b1));
}

__device__ __forceinline__ uint32_t h2pack(float a, float b) {
    __half2 h = __floats2half2_rn(a, b);
    return *(uint32_t*)&h;
}
__device__ __forceinline__ void h16split(float x, __half& h, __half& l) {
    h = __float2half_rn(x);
    l = __float2half_rn(x - __half2float(h));
}

// ---------------- pre-pass: fp32 -> fp16 ----------------
__global__ __launch_bounds__(256) void h2h_kernel(
    const float* __restrict__ src, __half* __restrict__ dst, int n4)
{
    for (int i = blockIdx.x * 256 + threadIdx.x; i < n4; i += gridDim.x * 256) {
        float4 v = ((const float4*)src)[i];
        uint2 p = make_uint2(h2pack(v.x, v.y), h2pack(v.z, v.w));
        ((uint2*)dst)[i] = p;
    }
}

// transpose: w[K][N] fp32 -> wT[N][K] fp16
__global__ __launch_bounds__(256) void wtrans_kernel(
    const float* __restrict__ w, __half* __restrict__ wt, int Kd, int Nd)
{
    __shared__ float t[32][33];
    const int bx = blockIdx.x;   // N tile
    const int by = blockIdx.y;   // K tile
    const int x = threadIdx.x & 31;
    const int y = threadIdx.x >> 5;
#pragma unroll
    for (int j = 0; j < 4; j++) {
        int kr = y + 8 * j;
        t[kr][x] = w[(size_t)(by * 32 + kr) * Nd + bx * 32 + x];
    }
    __syncthreads();
#pragma unroll
    for (int j = 0; j < 4; j++) {
        int nr = y + 8 * j;
        wt[(size_t)(bx * 32 + nr) * Kd + by * 32 + x] = __float2half_rn(t[x][nr]);
    }
}

// ---------------- GEMM: fp16 m16n8k16, 4 warps, 64x64 warp tile, BK=32, 3-stage ----------------
#define HAS_STR 40
#define HBS_STR 40
#define STG4_BYTES ((128 * HAS_STR + 128 * HBS_STR) * 2)   // 20480
#define GEMM4_SMEM (3 * STG4_BYTES)                        // 61440

#define CP16(dst_u32, src_ptr) \
    asm volatile("cp.async.cg.shared.global [%0], [%1], 16;" :: "r"(dst_u32), "l"(src_ptr))

__global__ __launch_bounds__(128, 2) void gemm_f16_kernel(
    const __half* __restrict__ A,
    const __half* __restrict__ B0, float* __restrict__ C0, int N0,
    const __half* __restrict__ B1, float* __restrict__ C1,
    const __half* __restrict__ B2, float* __restrict__ C2, int N12,
    int K)
{
    const __half* Bt;
    float* C;
    int N, bx;
    if (blockIdx.z == 0) {
        Bt = B0; C = C0; N = N0; bx = blockIdx.x;
        if (bx * 128 >= N0) return;
    } else {
        N = N12;
        const int nt12 = N12 / 128;
        if ((int)blockIdx.x < nt12) { Bt = B1; C = C1; bx = blockIdx.x; }
        else if ((int)blockIdx.x < 2 * nt12) { Bt = B2; C = C2; bx = blockIdx.x - nt12; }
        else return;
    }

    extern __shared__ __half smh[];
    const uint32_t smu = (uint32_t)__cvta_generic_to_shared(smh);

    const int tid = threadIdx.x;
    const int lane = tid & 31;
    const int wid = tid >> 5;
    const int wm = wid >> 1;
    const int wn = wid & 1;
    const int lr = lane >> 2;
    const int lc = lane & 3;
    const int by = blockIdx.y;

    const int crow = tid >> 2;
    const int cchk = (tid & 3) * 8;

    const __half* Ab = A + (size_t)(by * 128) * K;
    const __half* Bb = Bt + (size_t)(bx * 128) * K;

    float acc[4][8][4];
#pragma unroll
    for (int i = 0; i < 4; i++)
#pragma unroll
        for (int j = 0; j < 8; j++)
#pragma unroll
            for (int r = 0; r < 4; r++) acc[i][j][r] = 0.f;

    const int NT = K / 32;

#define LOAD_STAGE(stg, ch)                                                           \
    {                                                                                 \
        const uint32_t sb = smu + (uint32_t)((stg) * STG4_BYTES);                     \
        const int k0 = (ch) * 32;                                                     \
        _Pragma("unroll")                                                             \
        for (int i = 0; i < 4; i++) {                                                 \
            const int r = i * 32 + crow;                                              \
            CP16(sb + (uint32_t)((r * HAS_STR + cchk) * 2), Ab + (size_t)r * K + k0 + cchk); \
        }                                                                             \
        _Pragma("unroll")                                                             \
        for (int i = 0; i < 4; i++) {                                                 \
            const int r = i * 32 + crow;                                              \
            CP16(sb + (uint32_t)((128 * HAS_STR + r * HBS_STR + cchk) * 2),           \
                 Bb + (size_t)r * K + k0 + cchk);                                     \
        }                                                                             \
    }

    LOAD_STAGE(0, 0)
    asm volatile("cp.async.commit_group;" ::: "memory");
    LOAD_STAGE(1, 1)
    asm volatile("cp.async.commit_group;" ::: "memory");

    int stage = 0;
    for (int it = 0; it < NT; it++) {
        asm volatile("cp.async.wait_group 1;" ::: "memory");
        __syncthreads();

        const int pf = it + 2;
        if (pf < NT) {
            const int ps = (stage + 2) % 3;
            LOAD_STAGE(ps, pf)
        }
        asm volatile("cp.async.commit_group;" ::: "memory");

        const __half* As_ = smh + stage * (STG4_BYTES / 2);
        const __half* Bs_ = As_ + 128 * HAS_STR;

#pragma unroll
        for (int ks = 0; ks < 2; ks++) {
            const int kb = ks * 16;
            uint32_t af[4][4], bf[8][2];
#pragma unroll
            for (int mt = 0; mt < 4; mt++) {
                const int m0 = wm * 64 + mt * 16 + lr;
                const __half* p0 = As_ + m0 * HAS_STR + kb + 2 * lc;
                const __half* p1 = As_ + (m0 + 8) * HAS_STR + kb + 2 * lc;
                af[mt][0] = *(const uint32_t*)(p0);
                af[mt][1] = *(const uint32_t*)(p1);
                af[mt][2] = *(const uint32_t*)(p0 + 8);
                af[mt][3] = *(const uint32_t*)(p1 + 8);
            }
#pragma unroll
            for (int nt = 0; nt < 8; nt++) {
                const int n0 = wn * 64 + nt * 8 + lr;
                const __half* p = Bs_ + n0 * HBS_STR + kb + 2 * lc;
                bf[nt][0] = *(const uint32_t*)(p);
                bf[nt][1] = *(const uint32_t*)(p + 8);
            }
#pragma unroll
            for (int mt = 0; mt < 4; mt++)
#pragma unroll
                for (int nt = 0; nt < 8; nt++)
                    mma_f16(acc[mt][nt][0], acc[mt][nt][1], acc[mt][nt][2], acc[mt][nt][3],
                            af[mt][0], af[mt][1], af[mt][2], af[mt][3],
                            bf[nt][0], bf[nt][1]);
        }
        stage = (stage + 1) % 3;
    }
#undef LOAD_STAGE

#pragma unroll
    for (int mt = 0; mt < 4; mt++) {
        const int row = by * 128 + wm * 64 + mt * 16 + lr;
#pragma unroll
        for (int nt = 0; nt < 8; nt++) {
            const int col = bx * 128 + wn * 64 + nt * 8 + lc * 2;
            float2 v01 = make_float2(acc[mt][nt][0], acc[mt][nt][1]);
            float2 v23 = make_float2(acc[mt][nt][2], acc[mt][nt][3]);
            *(float2*)(C + (size_t)row * N + col) = v01;
            *(float2*)(C + (size_t)(row + 8) * N + col) = v23;
        }
    }
}

// ---------------- qn / kn ----------------
__global__ __launch_bounds__(128) void qn_kernel(const float* __restrict__ qp, float* __restrict__ qn)
{
    const int s = blockIdx.x;
    const int d = threadIdx.x;
    __shared__ float wsum[4];
    for (int h = 0; h < NH; h++) {
        float x = qp[(size_t)s * HID + h * HD + d];
        float f = x > 0.f ? x + 1.f : expf(x);
        float v = f;
#pragma unroll
        for (int o = 16; o; o >>= 1) v += __shfl_xor_sync(0xffffffffu, v, o);
        if ((d & 31) == 0) wsum[d >> 5] = v;
        __syncthreads();
        float tot = wsum[0] + wsum[1] + wsum[2] + wsum[3];
        qn[(size_t)s * HID + h * HD + d] = f / (tot + EPS);
        __syncthreads();
    }
}

__global__ __launch_bounds__(128) void kn_kernel(const float* __restrict__ kp, float* __restrict__ kn)
{
    const int s = blockIdx.x;
    const int d = threadIdx.x;
    __shared__ float wsum[4];
    for (int h = 0; h < NKV; h++) {
        float x = kp[(size_t)s * (NKV * HD) + h * HD + d];
        float f = x > 0.f ? x + 1.f : expf(x);
        float v = f;
#pragma unroll
        for (int o = 16; o; o >>= 1) v += __shfl_xor_sync(0xffffffffu, v, o);
        if ((d & 31) == 0) wsum[d >> 5] = v;
        __syncthreads();
        float tot = wsum[0] + wsum[1] + wsum[2] + wsum[3];
        kn[(size_t)s * (NKV * HD) + h * HD + d] = f / (tot + EPS);
        __syncthreads();
    }
}

__global__ __launch_bounds__(128) void knsum_part_kernel(const float* __restrict__ kn, float* __restrict__ part)
{
    const int h = blockIdx.x;
    const int p = blockIdx.y;
    const int d = threadIdx.x;
    float acc = 0.f;
    const int s0 = p * 128;
#pragma unroll 4
    for (int s = s0; s < s0 + 128; s++)
        acc += kn[(size_t)s * (NKV * HD) + h * HD + d];
    part[p * (NKV * HD) + h * HD + d] = acc;
}

__global__ __launch_bounds__(1024) void knsum_final_kernel(const float* __restrict__ part, float* __restrict__ knsum)
{
    const int i = threadIdx.x;
    float acc = 0.f;
#pragma unroll
    for (int p = 0; p < 16; p++) acc += part[p * (NKV * HD) + i];
    knsum[i] = acc;
}

// ---------------- memory retrieval ----------------
__global__ __launch_bounds__(128) void retrieve_kernel(
    const float* __restrict__ qn, const float* __restrict__ memory,
    const float* __restrict__ norm_m, float* __restrict__ memout)
{
    const int h = blockIdx.y;
    const int st = blockIdx.x;
    const int hm = h & (NKV - 1);
    const int e = threadIdx.x;
    __shared__ float Qs[16][128];
    __shared__ float Ms[32][128];
    __shared__ float Ns[128][33];

    for (int i = e; i < 16 * 128; i += 128) {
        int r = i >> 7, d = i & 127;
        Qs[r][d] = qn[(size_t)(st * 16 + r) * HID + h * HD + d];
    }
    float num[16], den[16];
#pragma unroll
    for (int r = 0; r < 16; r++) { num[r] = 0.f; den[r] = 0.f; }
    const float* M = memory + hm * HD * HD;
    const float* Nm = norm_m + hm * HD * HD;

    for (int d0 = 0; d0 < 128; d0 += 32) {
        __syncthreads();
        for (int i = e; i < 32 * 128; i += 128) {
            int dd = i >> 7, ee = i & 127;
            Ms[dd][ee] = M[(d0 + dd) * HD + ee];
        }
        for (int i = e; i < 128 * 32; i += 128) {
            int ee = i >> 5, dd = i & 31;
            Ns[ee][dd] = Nm[ee * HD + d0 + dd];
        }
        __syncthreads();
#pragma unroll 4
        for (int dd = 0; dd < 32; dd++) {
            float mv = Ms[dd][e];
            float nv = Ns[e][dd];
#pragma unroll
            for (int r = 0; r < 16; r++) {
                float qv = Qs[r][d0 + dd];
                num[r] += qv * mv;
                den[r] += qv * nv;
            }
        }
    }
#pragma unroll
    for (int r = 0; r < 16; r++)
        memout[(size_t)(st * 16 + r) * HID + h * HD + e] = num[r] / (den[r] + EPS);
}

// ---------------- v - v_ret for delta rule ----------------
__global__ __launch_bounds__(128) void vdelta_kernel(
    const float* __restrict__ kn, const float* __restrict__ vproj,
    const float* __restrict__ memory, const float* __restrict__ norm_m,
    float* __restrict__ vdelta)
{
    const int h = blockIdx.y;
    const int st = blockIdx.x;
    const int e = threadIdx.x;
    __shared__ float Qs[16][128];
    __shared__ float Ms[32][128];
    __shared__ float Ns[128][33];

    for (int i = e; i < 16 * 128; i += 128) {
        int r = i >> 7, d = i & 127;
        Qs[r][d] = kn[(size_t)(st * 16 + r) * (NKV * HD) + h * HD + d];
    }
    float num[16], den[16];
#pragma unroll
    for (int r = 0; r < 16; r++) { num[r] = 0.f; den[r] = 0.f; }
    const float* M = memory + h * HD * HD;
    const float* Nm = norm_m + h * HD * HD;

    for (int d0 = 0; d0 < 128; d0 += 32) {
        __syncthreads();
        for (int i = e; i < 32 * 128; i += 128) {
            int dd = i >> 7, ee = i & 127;
            Ms[dd][ee] = M[(d0 + dd) * HD + ee];
        }
        for (int i = e; i < 128 * 32; i += 128) {
            int ee = i >> 5, dd = i & 31;
            Ns[ee][dd] = Nm[ee * HD + d0 + dd];
        }
        __syncthreads();
#pragma unroll 4
        for (int dd = 0; dd < 32; dd++) {
            float mv = Ms[dd][e];
            float nv = Ns[e][dd];
#pragma unroll
            for (int r = 0; r < 16; r++) {
                float qv = Qs[r][d0 + dd];
                num[r] += qv * mv;
                den[r] += qv * nv;
            }
        }
    }
#pragma unroll
    for (int r = 0; r < 16; r++) {
        size_t idx = (size_t)(st * 16 + r) * (NKV * HD) + h * HD + e;
        vdelta[idx] = vproj[idx] - num[r] / (den[r] + EPS);
    }
}

// ---------------- RoPE + fp16 hi/lo split for Q,K ----------------
__global__ __launch_bounds__(256) void rope_split_kernel(
    const float* __restrict__ q, const float* __restrict__ k, const int* __restrict__ pos,
    __half* __restrict__ qh, __half* __restrict__ ql,
    __half* __restrict__ kh, __half* __restrict__ kl)
{
    const int s = blockIdx.x;
    const int idx = blockIdx.y * 256 + threadIdx.x;   // 0..2559
    if (idx >= (NH + NKV) * 64) return;
    const int head = idx >> 6;
    const int d = idx & 63;
    const float p = (float)pos[s];
    const float invf = expf(-(2.0f * (float)d / 128.0f) * LN10000);
    const float a = p * invf;
    const float c = cosf(a), sn = sinf(a);
    const float* base;
    __half *oh, *ol;
    if (head < NH) {
        size_t off = (size_t)s * HID + head * HD;
        base = q + off; oh = qh + off; ol = ql + off;
    } else {
        size_t off = (size_t)s * (NKV * HD) + (head - NH) * HD;
        base = k + off; oh = kh + off; ol = kl + off;
    }
    float x0 = base[d], x1 = base[d + 64];
    float r0 = x0 * c - x1 * sn;
    float r1 = x1 * c + x0 * sn;
    __half h, l;
    h16split(r0, h, l);
    oh[d] = h; ol[d] = l;
    h16split(r1, h, l);
    oh[d + 64] = h; ol[d + 64] = l;
}

// ---------------- V transpose + split: [S][NKV*HD] fp32 -> [NKV*HD][S] fp16 hi/lo ----------------
__global__ __launch_bounds__(256) void vtrans_split_kernel(
    const float* __restrict__ v, __half* __restrict__ vth, __half* __restrict__ vtl)
{
    __shared__ float t[32][33];
    const int bx = blockIdx.x;   // s tile
    const int by = blockIdx.y;   // channel tile
    const int x = threadIdx.x & 31;
    const int y = threadIdx.x >> 5;
#pragma unroll
    for (int j = 0; j < 4; j++) {
        int sr = y + 8 * j;
        t[sr][x] = v[(size_t)(bx * 32 + sr) * (NKV * HD) + by * 32 + x];
    }
    __syncthreads();
#pragma unroll
    for (int j = 0; j < 4; j++) {
        int cr = y + 8 * j;
        float val = t[x][cr];
        __half h, l;
        h16split(val, h, l);
        size_t idx = (size_t)(by * 32 + cr) * S + bx * 32 + x;
        vth[idx] = h;
        vtl[idx] = l;
    }
}

// ---------------- fp16-split MMA flash attention ----------------
// Bq=128, Bk=64, 8 warps. 3-MMA fp16 split for QK^T and PV (fp32-class accuracy).
#define QH_STR 136
#define KH_STR 136
#define VT_STR 72
#define PH_STR 72
#define SM_QH 0
#define SM_QL (128 * QH_STR)                 // 17408
#define SM_KH (SM_QL + 128 * QH_STR)         // 34816
#define SM_KL (SM_KH + 64 * KH_STR)          // 43520
#define SM_VTH (SM_KL + 64 * KH_STR)         // 52224
#define SM_VTL (SM_VTH + 128 * VT_STR)       // 61440
#define SM_PH (SM_VTL + 128 * VT_STR)        // 70656
#define SM_PL (SM_PH + 128 * PH_STR)         // 79872
#define ATT2_SMEM_HALVES (SM_PL + 128 * PH_STR)  // 89088
#define ATT2_SMEM_BYTES (ATT2_SMEM_HALVES * 2)   // 178176

__global__ __launch_bounds__(256) void attn_f16_kernel(
    const __half* __restrict__ qh, const __half* __restrict__ ql,
    const __half* __restrict__ kh, const __half* __restrict__ kl,
    const __half* __restrict__ vth, const __half* __restrict__ vtl,
    const float* __restrict__ memout, const float* __restrict__ beta,
    __half* __restrict__ ch)
{
    const int h = blockIdx.y;
    const int qt = (int)gridDim.x - 1 - (int)blockIdx.x;
    const int kvh = h >> 2;
    const int tid = threadIdx.x;
    const int warp = tid >> 5;
    const int lane = tid & 31;
    const int lr = lane >> 2;
    const int lc = lane & 3;

    extern __shared__ __half sh[];
    __half* Qh_ = sh + SM_QH;
    __half* Ql_ = sh + SM_QL;
    __half* Kh_ = sh + SM_KH;
    __half* Kl_ = sh + SM_KL;
    __half* Vth_ = sh + SM_VTH;
    __half* Vtl_ = sh + SM_VTL;
    __half* Ph_ = sh + SM_PH;
    __half* Pl_ = sh + SM_PL;

    // load Q tiles (hi/lo), 128 rows x 128 halves each
#pragma unroll
    for (int it = 0; it < 8; it++) {
        int i = it * 256 + tid;
        int row = i >> 4, c8 = (i & 15) * 8;
        size_t gidx = (size_t)(qt * 128 + row) * HID + h * HD + c8;
        *(uint4*)(Qh_ + row * QH_STR + c8) = *(const uint4*)(qh + gidx);
        *(uint4*)(Ql_ + row * QH_STR + c8) = *(const uint4*)(ql + gidx);
    }

    const int row0 = warp * 16 + lr;
    const int row1 = row0 + 8;
    const int grow0 = qt * 128 + row0;
    const int grow1 = grow0 + 8;

    float m0 = -1e30f, m1 = -1e30f, l0 = 0.f, l1 = 0.f;
    float o[16][4];
#pragma unroll
    for (int nt = 0; nt < 16; nt++)
#pragma unroll
        for (int r = 0; r < 4; r++) o[nt][r] = 0.f;

    const int ktmax = 2 * qt + 1;
    for (int kt = 0; kt <= ktmax; kt++) {
        __syncthreads();
        // K tiles: 64 rows x 128 halves per plane
#pragma unroll
        for (int it = 0; it < 4; it++) {
            int i = it * 256 + tid;
            int key = i >> 4, c8 = (i & 15) * 8;
            size_t gidx = (size_t)(kt * 64 + key) * (NKV * HD) + kvh * HD + c8;
            *(uint4*)(Kh_ + key * KH_STR + c8) = *(const uint4*)(kh + gidx);
            *(uint4*)(Kl_ + key * KH_STR + c8) = *(const uint4*)(kl + gidx);
        }
        // V^T tiles: 128 d-rows x 64 keys per plane (coalesced from [ch][S] layout)
#pragma unroll
        for (int it = 0; it < 4; it++) {
            int i = it * 256 + tid;
            int dr = i >> 3, kc = (i & 7) * 8;
            size_t gidx = (size_t)(kvh * HD + dr) * S + kt * 64 + kc;
            *(uint4*)(Vth_ + dr * VT_STR + kc) = *(const uint4*)(vth + gidx);
            *(uint4*)(Vtl_ + dr * VT_STR + kc) = *(const uint4*)(vtl + gidx);
        }
        __syncthreads();

        // ---- scores S = Q K^T (3x fp16 split) ----
        float sc[8][4];
#pragma unroll
        for (int nt = 0; nt < 8; nt++)
#pragma unroll
            for (int r = 0; r < 4; r++) sc[nt][r] = 0.f;

#pragma unroll
        for (int ks = 0; ks < 8; ks++) {
            const int kb = ks * 16;
            uint32_t ah[4], al[4];
            {
                const __half* p0 = Qh_ + row0 * QH_STR + kb + 2 * lc;
                const __half* p1 = Qh_ + row1 * QH_STR + kb + 2 * lc;
                ah[0] = *(const uint32_t*)(p0);
                ah[1] = *(const uint32_t*)(p1);
                ah[2] = *(const uint32_t*)(p0 + 8);
                ah[3] = *(const uint32_t*)(p1 + 8);
                const __half* q0 = Ql_ + row0 * QH_STR + kb + 2 * lc;
                const __half* q1 = Ql_ + row1 * QH_STR + kb + 2 * lc;
                al[0] = *(const uint32_t*)(q0);
                al[1] = *(const uint32_t*)(q1);
                al[2] = *(const uint32_t*)(q0 + 8);
                al[3] = *(const uint32_t*)(q1 + 8);
            }
#pragma unroll
            for (int nt = 0; nt < 8; nt++) {
                const int n0 = nt * 8 + lr;
                const __half* ph = Kh_ + n0 * KH_STR + kb + 2 * lc;
                const __half* pl = Kl_ + n0 * KH_STR + kb + 2 * lc;
                uint32_t bh0 = *(const uint32_t*)(ph);
                uint32_t bh1 = *(const uint32_t*)(ph + 8);
                uint32_t bl0 = *(const uint32_t*)(pl);
                uint32_t bl1 = *(const uint32_t*)(pl + 8);
                mma_f16(sc[nt][0], sc[nt][1], sc[nt][2], sc[nt][3],
                        ah[0], ah[1], ah[2], ah[3], bh0, bh1);
                mma_f16(sc[nt][0], sc[nt][1], sc[nt][2], sc[nt][3],
                        ah[0], ah[1], ah[2], ah[3], bl0, bl1);
                mma_f16(sc[nt][0], sc[nt][1], sc[nt][2], sc[nt][3],
                        al[0], al[1], al[2], al[3], bh0, bh1);
            }
        }

        // ---- online softmax (fp32) ----
        const bool need_mask = (kt >= 2 * qt);
        float mx0 = -1e30f, mx1 = -1e30f;
#pragma unroll
        for (int nt = 0; nt < 8; nt++) {
#pragma unroll
            for (int j = 0; j < 2; j++) {
                int col = kt * 64 + nt * 8 + 2 * lc + j;
                float s0 = sc[nt][j] * ATT_SCALE;
                float s1 = sc[nt][2 + j] * ATT_SCALE;
                if (need_mask) {
                    if (col > grow0) s0 = -1e30f;
                    if (col > grow1) s1 = -1e30f;
                }
                sc[nt][j] = s0;
                sc[nt][2 + j] = s1;
                mx0 = fmaxf(mx0, s0);
                mx1 = fmaxf(mx1, s1);
            }
        }
        mx0 = fmaxf(mx0, __shfl_xor_sync(0xffffffffu, mx0, 1));
        mx0 = fmaxf(mx0, __shfl_xor_sync(0xffffffffu, mx0, 2));
        mx1 = fmaxf(mx1, __shfl_xor_sync(0xffffffffu, mx1, 1));
        mx1 = fmaxf(mx1, __shfl_xor_sync(0xffffffffu, mx1, 2));
        const float mn0 = fmaxf(m0, mx0);
        const float mn1 = fmaxf(m1, mx1);
        const float scl0 = __expf(m0 - mn0);
        const float scl1 = __expf(m1 - mn1);
        float ls0 = 0.f, ls1 = 0.f;
#pragma unroll
        for (int nt = 0; nt < 8; nt++) {
            float p00 = __expf(sc[nt][0] - mn0);
            float p01 = __expf(sc[nt][1] - mn0);
            float p10 = __expf(sc[nt][2] - mn1);
            float p11 = __expf(sc[nt][3] - mn1);
            ls0 += p00 + p01;
            ls1 += p10 + p11;
            __half h0, l0h, h1, l1h;
            h16split(p00, h0, l0h);
            h16split(p01, h1, l1h);
            *(uint32_t*)(Ph_ + row0 * PH_STR + nt * 8 + 2 * lc) =
                (uint32_t)__half_as_ushort(h0) | ((uint32_t)__half_as_ushort(h1) << 16);
            *(uint32_t*)(Pl_ + row0 * PH_STR + nt * 8 + 2 * lc) =
                (uint32_t)__half_as_ushort(l0h) | ((uint32_t)__half_as_ushort(l1h) << 16);
            h16split(p10, h0, l0h);
            h16split(p11, h1, l1h);
            *(uint32_t*)(Ph_ + row1 * PH_STR + nt * 8 + 2 * lc) =
                (uint32_t)__half_as_ushort(h0) | ((uint32_t)__half_as_ushort(h1) << 16);
            *(uint32_t*)(Pl_ + row1 * PH_STR + nt * 8 + 2 * lc) =
                (uint32_t)__half_as_ushort(l0h) | ((uint32_t)__half_as_ushort(l1h) << 16);
        }
        ls0 += __shfl_xor_sync(0xffffffffu, ls0, 1);
        ls0 += __shfl_xor_sync(0xffffffffu, ls0, 2);
        ls1 += __shfl_xor_sync(0xffffffffu, ls1, 1);
        ls1 += __shfl_xor_sync(0xffffffffu, ls1, 2);
        l0 = l0 * scl0 + ls0;
        l1 = l1 * scl1 + ls1;
        m0 = mn0;
        m1 = mn1;

#pragma unroll
        for (int nt = 0; nt < 16; nt++) {
            o[nt][0] *= scl0;
            o[nt][1] *= scl0;
            o[nt][2] *= scl1;
            o[nt][3] *= scl1;
        }
        __syncwarp();

        // ---- O += P V (3x fp16 split) ----
#pragma unroll
        for (int ks2 = 0; ks2 < 4; ks2++) {
            const int kb = ks2 * 16;
            uint32_t ah[4], al[4];
            {
                const __half* p0 = Ph_ + row0 * PH_STR + kb + 2 * lc;
                const __half* p1 = Ph_ + row1 * PH_STR + kb + 2 * lc;
                ah[0] = *(const uint32_t*)(p0);
                ah[1] = *(const uint32_t*)(p1);
                ah[2] = *(const uint32_t*)(p0 + 8);
                ah[3] = *(const uint32_t*)(p1 + 8);
                const __half* q0 = Pl_ + row0 * PH_STR + kb + 2 * lc;
                const __half* q1 = Pl_ + row1 * PH_STR + kb + 2 * lc;
                al[0] = *(const uint32_t*)(q0);
                al[1] = *(const uint32_t*)(q1);
                al[2] = *(const uint32_t*)(q0 + 8);
                al[3] = *(const uint32_t*)(q1 + 8);
            }
#pragma unroll
            for (int nt = 0; nt < 16; nt++) {
                const int n0 = nt * 8 + lr;
                const __half* ph = Vth_ + n0 * VT_STR + kb + 2 * lc;
                const __half* pl = Vtl_ + n0 * VT_STR + kb + 2 * lc;
                uint32_t bh0 = *(const uint32_t*)(ph);
                uint32_t bh1 = *(const uint32_t*)(ph + 8);
                uint32_t bl0 = *(const uint32_t*)(pl);
                uint32_t bl1 = *(const uint32_t*)(pl + 8);
                mma_f16(o[nt][0], o[nt][1], o[nt][2], o[nt][3],
                        ah[0], ah[1], ah[2], ah[3], bh0, bh1);
                mma_f16(o[nt][0], o[nt][1], o[nt][2], o[nt][3],
                        ah[0], ah[1], ah[2], ah[3], bl0, bl1);
                mma_f16(o[nt][0], o[nt][1], o[nt][2], o[nt][3],
                        al[0], al[1], al[2], al[3], bh0, bh1);
            }
        }
    }

    // epilogue: gate-combine, emit fp16
    const float g = 1.f / (1.f + __expf(-beta[0]));
    const float og = 1.f - g;
    const float li0 = 1.f / l0;
    const float li1 = 1.f / l1;
#pragma unroll
    for (int nt = 0; nt < 16; nt++) {
        const int col = nt * 8 + 2 * lc;
        size_t i0 = (size_t)grow0 * HID + h * HD + col;
        size_t i1 = (size_t)grow1 * HID + h * HD + col;
        float2 mo0 = *(const float2*)(memout + i0);
        float2 mo1 = *(const float2*)(memout + i1);
        *(uint32_t*)(ch + i0) = h2pack(g * mo0.x + og * (o[nt][0] * li0),
                                       g * mo0.y + og * (o[nt][1] * li0));
        *(uint32_t*)(ch + i1) = h2pack(g * mo1.x + og * (o[nt][2] * li1),
                                       g * mo1.y + og * (o[nt][3] * li1));
    }
}

// ---------------- delta-rule partials ----------------
__global__ __launch_bounds__(256) void delta_part_kernel(
    const float* __restrict__ kn, const float* __restrict__ vd, float* __restrict__ part)
{
    const int h = blockIdx.x;
    const int c = blockIdx.y;
    __shared__ float Ak[32][128];
    __shared__ float Bv[32][128];
    const int trow = (threadIdx.x >> 4) * 8;
    const int tcol = (threadIdx.x & 15) * 8;
    float acc[8][8];
#pragma unroll
    for (int i = 0; i < 8; i++)
#pragma unroll
        for (int j = 0; j < 8; j++) acc[i][j] = 0.f;

    const int sbeg = c * 256;
    for (int s0 = sbeg; s0 < sbeg + 256; s0 += 32) {
        for (int i = threadIdx.x; i < 32 * 128; i += 256) {
            int ss = i >> 7, dd = i & 127;
            size_t idx = (size_t)(s0 + ss) * (NKV * HD) + h * HD + dd;
            Ak[ss][dd] = kn[idx];
            Bv[ss][dd] = vd[idx];
        }
        __syncthreads();
#pragma unroll 4
        for (int ss = 0; ss < 32; ss++) {
            float ra[8], rb[8];
#pragma unroll
            for (int i = 0; i < 8; i++) ra[i] = Ak[ss][trow + i];
#pragma unroll
            for (int j = 0; j < 8; j++) rb[j] = Bv[ss][tcol + j];
#pragma unroll
            for (int i = 0; i < 8; i++)
#pragma unroll
                for (int j = 0; j < 8; j++) acc[i][j] += ra[i] * rb[j];
        }
        __syncthreads();
    }
    float* Ph = part + (size_t)c * (NKV * HD * HD) + h * HD * HD;
#pragma unroll
    for (int i = 0; i < 8; i++)
#pragma unroll
        for (int j = 0; j < 8; j++)
            Ph[(trow + i) * HD + tcol + j] = acc[i][j];
}

__global__ __launch_bounds__(256) void delta_final_kernel(
    const float* __restrict__ part, const float* __restrict__ memory, float* __restrict__ outmem)
{
    const int i = blockIdx.x * 256 + threadIdx.x;
    float acc = memory[i];
#pragma unroll
    for (int c = 0; c < 8; c++) acc += part[(size_t)c * (NKV * HD * HD) + i];
    outmem[i] = acc;
}

// ---------------- updated_norm ----------------
__global__ __launch_bounds__(256) void norm_kernel(
    const float* __restrict__ norm_m, const float* __restrict__ knsum, float* __restrict__ out)
{
    const int i = blockIdx.x * 256 + threadIdx.x;
    const int h = i >> 14;
    const int j = i & 127;
    out[i] = norm_m[i] + knsum[h * HD + j];
}

// ---------------- launch ----------------
extern "C" void kernel_launch(void* const* d_in, const int* in_sizes, int n_in,
                              void* d_out, int out_size)
{
    const float* hidden = (const float*)d_in[0];
    const int*   pos    = (const int*)d_in[1];
    const float* wq     = (const float*)d_in[2];
    const float* wk     = (const float*)d_in[3];
    const float* wv     = (const float*)d_in[4];
    const float* wo     = (const float*)d_in[5];
    const float* memory = (const float*)d_in[6];
    const float* norm_m = (const float*)d_in[7];
    const float* beta   = (const float*)d_in[8];
    float* out = (float*)d_out;

    float *qproj, *kproj, *vproj, *qn, *kn, *memout, *vdelta, *knsum, *knpart, *dpart;
    __half *hh, *wqT, *wkT, *wvT, *woT, *ch, *qh, *ql, *kh, *kl, *vth, *vtl;
    cudaGetSymbolAddress((void**)&qproj, g_qproj);
    cudaGetSymbolAddress((void**)&kproj, g_kproj);
    cudaGetSymbolAddress((void**)&vproj, g_vproj);
    cudaGetSymbolAddress((void**)&qn, g_qn);
    cudaGetSymbolAddress((void**)&kn, g_kn);
    cudaGetSymbolAddress((void**)&memout, g_memout);
    cudaGetSymbolAddress((void**)&vdelta, g_vdelta);
    cudaGetSymbolAddress((void**)&knsum, g_knsum);
    cudaGetSymbolAddress((void**)&knpart, g_knsum_part);
    cudaGetSymbolAddress((void**)&dpart, g_delta_part);
    cudaGetSymbolAddress((void**)&hh, g_hh);
    cudaGetSymbolAddress((void**)&wqT, g_wqT);
    cudaGetSymbolAddress((void**)&wkT, g_wkT);
    cudaGetSymbolAddress((void**)&wvT, g_wvT);
    cudaGetSymbolAddress((void**)&woT, g_woT);
    cudaGetSymbolAddress((void**)&ch, g_ch);
    cudaGetSymbolAddress((void**)&qh, g_qh);
    cudaGetSymbolAddress((void**)&ql, g_ql);
    cudaGetSymbolAddress((void**)&kh, g_kh);
    cudaGetSymbolAddress((void**)&kl, g_kl);
    cudaGetSymbolAddress((void**)&vth, g_vth);
    cudaGetSymbolAddress((void**)&vtl, g_vtl);

    cudaFuncSetAttribute(attn_f16_kernel,
                         cudaFuncAttributeMaxDynamicSharedMemorySize, ATT2_SMEM_BYTES);
    cudaFuncSetAttribute(gemm_f16_kernel,
                         cudaFuncAttributeMaxDynamicSharedMemorySize, GEMM4_SMEM);

    // pre-pass: hidden -> fp16; weights -> transposed [N][K] fp16
    h2h_kernel<<<1024, 256>>>(hidden, hh, S * HID / 4);
    wtrans_kernel<<<dim3(HID / 32, HID / 32), 256>>>(wq, wqT, HID, HID);
    wtrans_kernel<<<dim3(NKV * HD / 32, HID / 32), 256>>>(wk, wkT, HID, NKV * HD);
    wtrans_kernel<<<dim3(NKV * HD / 32, HID / 32), 256>>>(wv, wvT, HID, NKV * HD);
    wtrans_kernel<<<dim3(HID / 32, HID / 32), 256>>>(wo, woT, HID, HID);

    // projections (fp16 m16n8k16). z=0: Q; z=1: bx<8 K, bx<16 V.
    gemm_f16_kernel<<<dim3(HID / 128, S / 128, 2), 128, GEMM4_SMEM>>>(
        hh, wqT, qproj, HID, wkT, kproj, wvT, vproj, NKV * HD, HID);

    // normalized features from PRE-RoPE q/k
    qn_kernel<<<S, 128>>>(qproj, qn);
    kn_kernel<<<S, 128>>>(kproj, kn);
    knsum_part_kernel<<<dim3(NKV, 16), 128>>>(kn, knpart);
    knsum_final_kernel<<<1, 1024>>>(knpart, knsum);

    // compressive-memory retrieval + delta-rule prep
    retrieve_kernel<<<dim3(S / 16, NH), 128>>>(qn, memory, norm_m, memout);
    vdelta_kernel<<<dim3(S / 16, NKV), 128>>>(kn, vproj, memory, norm_m, vdelta);

    // RoPE + fp16 hi/lo split; V transpose + split
    rope_split_kernel<<<dim3(S, 10), 256>>>(qproj, kproj, pos, qh, ql, kh, kl);
    vtrans_split_kernel<<<dim3(S / 32, NKV * HD / 32), 256>>>(vproj, vth, vtl);

    // fp16-split flash attention (fuses gated combine, emits fp16 combined)
    attn_f16_kernel<<<dim3(S / 128, NH), 256, ATT2_SMEM_BYTES>>>(
        qh, ql, kh, kl, vth, vtl, memout, beta, ch);

    // output projection (fp16)
    gemm_f16_kernel<<<dim3(HID / 128, S / 128, 1), 128, GEMM4_SMEM>>>(
        ch, woT, out, HID, woT, out, woT, out, HID, HID);

    // memory & norm updates (appended after the 8.4M-element `out`)
    delta_part_kernel<<<dim3(NKV, 8), 256>>>(kn, vdelta, dpart);
    delta_final_kernel<<<(NKV * HD * HD) / 256, 256>>>(dpart, memory, out + (size_t)S * HID);
    norm_kernel<<<(NKV * HD * HD) / 256, 256>>>(norm_m, knsum,
                                                out + (size_t)S * HID + NKV * HD * HD);
}

// round 10
// speedup vs baseline: 5.5300x; 1.1426x over previous
#include <cuda_runtime.h>
#include <cuda_fp16.h>
#include <math.h>
#include <stdint.h>

// ---------------- problem constants ----------------
#define S 2048
#define HID 4096
#define NH 32
#define NKV 8
#define HD 128
#define GROUPS 4
#define EPS 1e-8f
#define ATT_SCALE 0.08838834764831845f   // 128^-0.5
#define LN10000 9.210340371976184f

// ---------------- scratch (device globals; no allocation allowed) ----------------
__device__ float g_qproj[S * HID];
__device__ float g_kproj[S * NKV * HD];
__device__ float g_vproj[S * NKV * HD];
__device__ float g_qn[S * HID];
__device__ float g_kn[S * NKV * HD];
__device__ float g_memout[S * HID];
__device__ float g_vdelta[S * NKV * HD];
__device__ float g_knsum[NKV * HD];
__device__ float g_knsum_part[16][NKV * HD];
__device__ float g_delta_part[8][NKV * HD * HD];
// fp16 GEMM operands
__device__ __half g_hh[S * HID];             // hidden, [M][K]
__device__ __half g_wqT[HID * HID];          // [N][K]
__device__ __half g_wkT[NKV * HD * HID];
__device__ __half g_wvT[NKV * HD * HID];
__device__ __half g_woT[HID * HID];
__device__ __half g_ch[S * HID];             // combined (attention out), [M][K]
// fp16 hi/lo planes for attention
__device__ __half g_qh[S * HID];
__device__ __half g_ql[S * HID];
__device__ __half g_kh[S * NKV * HD];
__device__ __half g_kl[S * NKV * HD];
__device__ __half g_vth[NKV * HD * S];       // V^T hi: [h*HD+d][s]
__device__ __half g_vtl[NKV * HD * S];

// ---------------- fp16 mma + ldmatrix ----------------
__device__ __forceinline__ void mma_f16(
    float& c0, float& c1, float& c2, float& c3,
    uint32_t a0, uint32_t a1, uint32_t a2, uint32_t a3,
    uint32_t b0, uint32_t b1)
{
    asm volatile(
        "mma.sync.aligned.m16n8k16.row.col.f32.f16.f16.f32 "
        "{%0,%1,%2,%3},{%4,%5,%6,%7},{%8,%9},{%0,%1,%2,%3};"
        : "+f"(c0), "+f"(c1), "+f"(c2), "+f"(c3)
        : "r"(a0), "r"(a1), "r"(a2), "r"(a3), "r"(b0), "r"(b1));
}

#define LDSM4(r0, r1, r2, r3, addr) \
    asm volatile("ldmatrix.sync.aligned.m8n8.x4.shared.b16 {%0,%1,%2,%3}, [%4];" \
                 : "=r"(r0), "=r"(r1), "=r"(r2), "=r"(r3) : "r"(addr))

__device__ __forceinline__ uint32_t h2pack(float a, float b) {
    __half2 h = __floats2half2_rn(a, b);
    return *(uint32_t*)&h;
}
__device__ __forceinline__ void h16split(float x, __half& h, __half& l) {
    h = __float2half_rn(x);
    l = __float2half_rn(x - __half2float(h));
}

// ---------------- pre-pass: fp32 -> fp16 ----------------
__global__ __launch_bounds__(256) void h2h_kernel(
    const float* __restrict__ src, __half* __restrict__ dst, int n4)
{
    for (int i = blockIdx.x * 256 + threadIdx.x; i < n4; i += gridDim.x * 256) {
        float4 v = ((const float4*)src)[i];
        uint2 p = make_uint2(h2pack(v.x, v.y), h2pack(v.z, v.w));
        ((uint2*)dst)[i] = p;
    }
}

// transpose: w[K][N] fp32 -> wT[N][K] fp16
__global__ __launch_bounds__(256) void wtrans_kernel(
    const float* __restrict__ w, __half* __restrict__ wt, int Kd, int Nd)
{
    __shared__ float t[32][33];
    const int bx = blockIdx.x;
    const int by = blockIdx.y;
    const int x = threadIdx.x & 31;
    const int y = threadIdx.x >> 5;
#pragma unroll
    for (int j = 0; j < 4; j++) {
        int kr = y + 8 * j;
        t[kr][x] = w[(size_t)(by * 32 + kr) * Nd + bx * 32 + x];
    }
    __syncthreads();
#pragma unroll
    for (int j = 0; j < 4; j++) {
        int nr = y + 8 * j;
        wt[(size_t)(bx * 32 + nr) * Kd + by * 32 + x] = __float2half_rn(t[x][nr]);
    }
}

// ---------------- GEMM: fp16 m16n8k16 + ldmatrix, 4 warps, 64x64 warp tile, BK=32 ----------------
#define HAS_STR 40
#define HBS_STR 40
#define STG4_BYTES ((128 * HAS_STR + 128 * HBS_STR) * 2)   // 20480
#define GEMM4_SMEM (3 * STG4_BYTES)                        // 61440

#define CP16(dst_u32, src_ptr) \
    asm volatile("cp.async.cg.shared.global [%0], [%1], 16;" :: "r"(dst_u32), "l"(src_ptr))

__global__ __launch_bounds__(128, 2) void gemm_f16_kernel(
    const __half* __restrict__ A,
    const __half* __restrict__ B0, float* __restrict__ C0, int N0,
    const __half* __restrict__ B1, float* __restrict__ C1,
    const __half* __restrict__ B2, float* __restrict__ C2, int N12,
    int K)
{
    const __half* Bt;
    float* C;
    int N, bx;
    if (blockIdx.z == 0) {
        Bt = B0; C = C0; N = N0; bx = blockIdx.x;
        if (bx * 128 >= N0) return;
    } else {
        N = N12;
        const int nt12 = N12 / 128;
        if ((int)blockIdx.x < nt12) { Bt = B1; C = C1; bx = blockIdx.x; }
        else if ((int)blockIdx.x < 2 * nt12) { Bt = B2; C = C2; bx = blockIdx.x - nt12; }
        else return;
    }

    extern __shared__ __half smh[];
    const uint32_t smu = (uint32_t)__cvta_generic_to_shared(smh);

    const int tid = threadIdx.x;
    const int lane = tid & 31;
    const int wid = tid >> 5;
    const int wm = wid >> 1;
    const int wn = wid & 1;
    const int lr = lane >> 2;
    const int lc = lane & 3;
    const int by = blockIdx.y;

    const int crow = tid >> 2;
    const int cchk = (tid & 3) * 8;

    const __half* Ab = A + (size_t)(by * 128) * K;
    const __half* Bb = Bt + (size_t)(bx * 128) * K;

    // ldmatrix per-lane offsets (bytes)
    // A x4: matrices = [rows 0-7,k0-7][rows 8-15,k0-7][rows 0-7,k8-15][rows 8-15,k8-15]
    const uint32_t a_lane_off =
        (uint32_t)(((lane & 15) * HAS_STR + ((lane >> 4) << 3)) * 2);
    // B x4: matrices = [nt rows,k0-7][nt rows,k8-15][nt+1 rows,k0-7][nt+1 rows,k8-15]
    const uint32_t b_lane_off =
        (uint32_t)((((lane & 7) + ((lane >> 4) << 3)) * HBS_STR + (((lane >> 3) & 1) << 3)) * 2);

    float acc[4][8][4];
#pragma unroll
    for (int i = 0; i < 4; i++)
#pragma unroll
        for (int j = 0; j < 8; j++)
#pragma unroll
            for (int r = 0; r < 4; r++) acc[i][j][r] = 0.f;

    const int NT = K / 32;

#define LOAD_STAGE(stg, ch)                                                           \
    {                                                                                 \
        const uint32_t sb = smu + (uint32_t)((stg) * STG4_BYTES);                     \
        const int k0 = (ch) * 32;                                                     \
        _Pragma("unroll")                                                             \
        for (int i = 0; i < 4; i++) {                                                 \
            const int r = i * 32 + crow;                                              \
            CP16(sb + (uint32_t)((r * HAS_STR + cchk) * 2), Ab + (size_t)r * K + k0 + cchk); \
        }                                                                             \
        _Pragma("unroll")                                                             \
        for (int i = 0; i < 4; i++) {                                                 \
            const int r = i * 32 + crow;                                              \
            CP16(sb + (uint32_t)((128 * HAS_STR + r * HBS_STR + cchk) * 2),           \
                 Bb + (size_t)r * K + k0 + cchk);                                     \
        }                                                                             \
    }

    LOAD_STAGE(0, 0)
    asm volatile("cp.async.commit_group;" ::: "memory");
    LOAD_STAGE(1, 1)
    asm volatile("cp.async.commit_group;" ::: "memory");

    int stage = 0;
    for (int it = 0; it < NT; it++) {
        asm volatile("cp.async.wait_group 1;" ::: "memory");
        __syncthreads();

        const int pf = it + 2;
        if (pf < NT) {
            const int ps = (stage + 2) % 3;
            LOAD_STAGE(ps, pf)
        }
        asm volatile("cp.async.commit_group;" ::: "memory");

        const uint32_t sbA = smu + (uint32_t)(stage * STG4_BYTES);
        const uint32_t sbB = sbA + (uint32_t)(128 * HAS_STR * 2);

#pragma unroll
        for (int ks = 0; ks < 2; ks++) {
            const uint32_t kbB = (uint32_t)(ks * 16 * 2);   // bytes
            uint32_t af[4][4], bf[8][2];
#pragma unroll
            for (int mt = 0; mt < 4; mt++) {
                const uint32_t addr = sbA
                    + (uint32_t)(((wm * 64 + mt * 16) * HAS_STR) * 2)
                    + a_lane_off + kbB;
                LDSM4(af[mt][0], af[mt][1], af[mt][2], af[mt][3], addr);
            }
#pragma unroll
            for (int ntp = 0; ntp < 4; ntp++) {
                const uint32_t addr = sbB
                    + (uint32_t)(((wn * 64 + ntp * 16) * HBS_STR) * 2)
                    + b_lane_off + kbB;
                LDSM4(bf[2 * ntp][0], bf[2 * ntp][1], bf[2 * ntp + 1][0], bf[2 * ntp + 1][1], addr);
            }
#pragma unroll
            for (int mt = 0; mt < 4; mt++)
#pragma unroll
                for (int nt = 0; nt < 8; nt++)
                    mma_f16(acc[mt][nt][0], acc[mt][nt][1], acc[mt][nt][2], acc[mt][nt][3],
                            af[mt][0], af[mt][1], af[mt][2], af[mt][3],
                            bf[nt][0], bf[nt][1]);
        }
        stage = (stage + 1) % 3;
    }
#undef LOAD_STAGE

#pragma unroll
    for (int mt = 0; mt < 4; mt++) {
        const int row = by * 128 + wm * 64 + mt * 16 + lr;
#pragma unroll
        for (int nt = 0; nt < 8; nt++) {
            const int col = bx * 128 + wn * 64 + nt * 8 + lc * 2;
            float2 v01 = make_float2(acc[mt][nt][0], acc[mt][nt][1]);
            float2 v23 = make_float2(acc[mt][nt][2], acc[mt][nt][3]);
            *(float2*)(C + (size_t)row * N + col) = v01;
            *(float2*)(C + (size_t)(row + 8) * N + col) = v23;
        }
    }
}

// ---------------- qn / kn ----------------
__global__ __launch_bounds__(128) void qn_kernel(const float* __restrict__ qp, float* __restrict__ qn)
{
    const int s = blockIdx.x;
    const int d = threadIdx.x;
    __shared__ float wsum[4];
    for (int h = 0; h < NH; h++) {
        float x = qp[(size_t)s * HID + h * HD + d];
        float f = x > 0.f ? x + 1.f : expf(x);
        float v = f;
#pragma unroll
        for (int o = 16; o; o >>= 1) v += __shfl_xor_sync(0xffffffffu, v, o);
        if ((d & 31) == 0) wsum[d >> 5] = v;
        __syncthreads();
        float tot = wsum[0] + wsum[1] + wsum[2] + wsum[3];
        qn[(size_t)s * HID + h * HD + d] = f / (tot + EPS);
        __syncthreads();
    }
}

__global__ __launch_bounds__(128) void kn_kernel(const float* __restrict__ kp, float* __restrict__ kn)
{
    const int s = blockIdx.x;
    const int d = threadIdx.x;
    __shared__ float wsum[4];
    for (int h = 0; h < NKV; h++) {
        float x = kp[(size_t)s * (NKV * HD) + h * HD + d];
        float f = x > 0.f ? x + 1.f : expf(x);
        float v = f;
#pragma unroll
        for (int o = 16; o; o >>= 1) v += __shfl_xor_sync(0xffffffffu, v, o);
        if ((d & 31) == 0) wsum[d >> 5] = v;
        __syncthreads();
        float tot = wsum[0] + wsum[1] + wsum[2] + wsum[3];
        kn[(size_t)s * (NKV * HD) + h * HD + d] = f / (tot + EPS);
        __syncthreads();
    }
}

__global__ __launch_bounds__(128) void knsum_part_kernel(const float* __restrict__ kn, float* __restrict__ part)
{
    const int h = blockIdx.x;
    const int p = blockIdx.y;
    const int d = threadIdx.x;
    float acc = 0.f;
    const int s0 = p * 128;
#pragma unroll 4
    for (int s = s0; s < s0 + 128; s++)
        acc += kn[(size_t)s * (NKV * HD) + h * HD + d];
    part[p * (NKV * HD) + h * HD + d] = acc;
}

__global__ __launch_bounds__(1024) void knsum_final_kernel(const float* __restrict__ part, float* __restrict__ knsum)
{
    const int i = threadIdx.x;
    float acc = 0.f;
#pragma unroll
    for (int p = 0; p < 16; p++) acc += part[p * (NKV * HD) + i];
    knsum[i] = acc;
}

// ---------------- memory retrieval ----------------
__global__ __launch_bounds__(128) void retrieve_kernel(
    const float* __restrict__ qn, const float* __restrict__ memory,
    const float* __restrict__ norm_m, float* __restrict__ memout)
{
    const int h = blockIdx.y;
    const int st = blockIdx.x;
    const int hm = h & (NKV - 1);
    const int e = threadIdx.x;
    __shared__ float Qs[16][128];
    __shared__ float Ms[32][128];
    __shared__ float Ns[128][33];

    for (int i = e; i < 16 * 128; i += 128) {
        int r = i >> 7, d = i & 127;
        Qs[r][d] = qn[(size_t)(st * 16 + r) * HID + h * HD + d];
    }
    float num[16], den[16];
#pragma unroll
    for (int r = 0; r < 16; r++) { num[r] = 0.f; den[r] = 0.f; }
    const float* M = memory + hm * HD * HD;
    const float* Nm = norm_m + hm * HD * HD;

    for (int d0 = 0; d0 < 128; d0 += 32) {
        __syncthreads();
        for (int i = e; i < 32 * 128; i += 128) {
            int dd = i >> 7, ee = i & 127;
            Ms[dd][ee] = M[(d0 + dd) * HD + ee];
        }
        for (int i = e; i < 128 * 32; i += 128) {
            int ee = i >> 5, dd = i & 31;
            Ns[ee][dd] = Nm[ee * HD + d0 + dd];
        }
        __syncthreads();
#pragma unroll 4
        for (int dd = 0; dd < 32; dd++) {
            float mv = Ms[dd][e];
            float nv = Ns[e][dd];
#pragma unroll
            for (int r = 0; r < 16; r++) {
                float qv = Qs[r][d0 + dd];
                num[r] += qv * mv;
                den[r] += qv * nv;
            }
        }
    }
#pragma unroll
    for (int r = 0; r < 16; r++)
        memout[(size_t)(st * 16 + r) * HID + h * HD + e] = num[r] / (den[r] + EPS);
}

// ---------------- v - v_ret for delta rule ----------------
__global__ __launch_bounds__(128) void vdelta_kernel(
    const float* __restrict__ kn, const float* __restrict__ vproj,
    const float* __restrict__ memory, const float* __restrict__ norm_m,
    float* __restrict__ vdelta)
{
    const int h = blockIdx.y;
    const int st = blockIdx.x;
    const int e = threadIdx.x;
    __shared__ float Qs[16][128];
    __shared__ float Ms[32][128];
    __shared__ float Ns[128][33];

    for (int i = e; i < 16 * 128; i += 128) {
        int r = i >> 7, d = i & 127;
        Qs[r][d] = kn[(size_t)(st * 16 + r) * (NKV * HD) + h * HD + d];
    }
    float num[16], den[16];
#pragma unroll
    for (int r = 0; r < 16; r++) { num[r] = 0.f; den[r] = 0.f; }
    const float* M = memory + h * HD * HD;
    const float* Nm = norm_m + h * HD * HD;

    for (int d0 = 0; d0 < 128; d0 += 32) {
        __syncthreads();
        for (int i = e; i < 32 * 128; i += 128) {
            int dd = i >> 7, ee = i & 127;
            Ms[dd][ee] = M[(d0 + dd) * HD + ee];
        }
        for (int i = e; i < 128 * 32; i += 128) {
            int ee = i >> 5, dd = i & 31;
            Ns[ee][dd] = Nm[ee * HD + d0 + dd];
        }
        __syncthreads();
#pragma unroll 4
        for (int dd = 0; dd < 32; dd++) {
            float mv = Ms[dd][e];
            float nv = Ns[e][dd];
#pragma unroll
            for (int r = 0; r < 16; r++) {
                float qv = Qs[r][d0 + dd];
                num[r] += qv * mv;
                den[r] += qv * nv;
            }
        }
    }
#pragma unroll
    for (int r = 0; r < 16; r++) {
        size_t idx = (size_t)(st * 16 + r) * (NKV * HD) + h * HD + e;
        vdelta[idx] = vproj[idx] - num[r] / (den[r] + EPS);
    }
}

// ---------------- RoPE + fp16 hi/lo split for Q,K ----------------
__global__ __launch_bounds__(256) void rope_split_kernel(
    const float* __restrict__ q, const float* __restrict__ k, const int* __restrict__ pos,
    __half* __restrict__ qh, __half* __restrict__ ql,
    __half* __restrict__ kh, __half* __restrict__ kl)
{
    const int s = blockIdx.x;
    const int idx = blockIdx.y * 256 + threadIdx.x;
    if (idx >= (NH + NKV) * 64) return;
    const int head = idx >> 6;
    const int d = idx & 63;
    const float p = (float)pos[s];
    const float invf = expf(-(2.0f * (float)d / 128.0f) * LN10000);
    const float a = p * invf;
    const float c = cosf(a), sn = sinf(a);
    const float* base;
    __half *oh, *ol;
    if (head < NH) {
        size_t off = (size_t)s * HID + head * HD;
        base = q + off; oh = qh + off; ol = ql + off;
    } else {
        size_t off = (size_t)s * (NKV * HD) + (head - NH) * HD;
        base = k + off; oh = kh + off; ol = kl + off;
    }
    float x0 = base[d], x1 = base[d + 64];
    float r0 = x0 * c - x1 * sn;
    float r1 = x1 * c + x0 * sn;
    __half h, l;
    h16split(r0, h, l);
    oh[d] = h; ol[d] = l;
    h16split(r1, h, l);
    oh[d + 64] = h; ol[d + 64] = l;
}

// ---------------- V transpose + split ----------------
__global__ __launch_bounds__(256) void vtrans_split_kernel(
    const float* __restrict__ v, __half* __restrict__ vth, __half* __restrict__ vtl)
{
    __shared__ float t[32][33];
    const int bx = blockIdx.x;
    const int by = blockIdx.y;
    const int x = threadIdx.x & 31;
    const int y = threadIdx.x >> 5;
#pragma unroll
    for (int j = 0; j < 4; j++) {
        int sr = y + 8 * j;
        t[sr][x] = v[(size_t)(bx * 32 + sr) * (NKV * HD) + by * 32 + x];
    }
    __syncthreads();
#pragma unroll
    for (int j = 0; j < 4; j++) {
        int cr = y + 8 * j;
        float val = t[x][cr];
        __half h, l;
        h16split(val, h, l);
        size_t idx = (size_t)(by * 32 + cr) * S + bx * 32 + x;
        vth[idx] = h;
        vtl[idx] = l;
    }
}

// ---------------- fp16-split MMA flash attention ----------------
#define QH_STR 136
#define KH_STR 136
#define VT_STR 72
#define PH_STR 72
#define SM_QH 0
#define SM_QL (128 * QH_STR)
#define SM_KH (SM_QL + 128 * QH_STR)
#define SM_KL (SM_KH + 64 * KH_STR)
#define SM_VTH (SM_KL + 64 * KH_STR)
#define SM_VTL (SM_VTH + 128 * VT_STR)
#define SM_PH (SM_VTL + 128 * VT_STR)
#define SM_PL (SM_PH + 128 * PH_STR)
#define ATT2_SMEM_HALVES (SM_PL + 128 * PH_STR)
#define ATT2_SMEM_BYTES (ATT2_SMEM_HALVES * 2)

__global__ __launch_bounds__(256) void attn_f16_kernel(
    const __half* __restrict__ qh, const __half* __restrict__ ql,
    const __half* __restrict__ kh, const __half* __restrict__ kl,
    const __half* __restrict__ vth, const __half* __restrict__ vtl,
    const float* __restrict__ memout, const float* __restrict__ beta,
    __half* __restrict__ ch)
{
    const int h = blockIdx.y;
    const int qt = (int)gridDim.x - 1 - (int)blockIdx.x;
    const int kvh = h >> 2;
    const int tid = threadIdx.x;
    const int warp = tid >> 5;
    const int lane = tid & 31;
    const int lr = lane >> 2;
    const int lc = lane & 3;

    extern __shared__ __half sh[];
    __half* Qh_ = sh + SM_QH;
    __half* Ql_ = sh + SM_QL;
    __half* Kh_ = sh + SM_KH;
    __half* Kl_ = sh + SM_KL;
    __half* Vth_ = sh + SM_VTH;
    __half* Vtl_ = sh + SM_VTL;
    __half* Ph_ = sh + SM_PH;
    __half* Pl_ = sh + SM_PL;

#pragma unroll
    for (int it = 0; it < 8; it++) {
        int i = it * 256 + tid;
        int row = i >> 4, c8 = (i & 15) * 8;
        size_t gidx = (size_t)(qt * 128 + row) * HID + h * HD + c8;
        *(uint4*)(Qh_ + row * QH_STR + c8) = *(const uint4*)(qh + gidx);
        *(uint4*)(Ql_ + row * QH_STR + c8) = *(const uint4*)(ql + gidx);
    }

    const int row0 = warp * 16 + lr;
    const int row1 = row0 + 8;
    const int grow0 = qt * 128 + row0;
    const int grow1 = grow0 + 8;

    float m0 = -1e30f, m1 = -1e30f, l0 = 0.f, l1 = 0.f;
    float o[16][4];
#pragma unroll
    for (int nt = 0; nt < 16; nt++)
#pragma unroll
        for (int r = 0; r < 4; r++) o[nt][r] = 0.f;

    const int ktmax = 2 * qt + 1;
    for (int kt = 0; kt <= ktmax; kt++) {
        __syncthreads();
#pragma unroll
        for (int it = 0; it < 4; it++) {
            int i = it * 256 + tid;
            int key = i >> 4, c8 = (i & 15) * 8;
            size_t gidx = (size_t)(kt * 64 + key) * (NKV * HD) + kvh * HD + c8;
            *(uint4*)(Kh_ + key * KH_STR + c8) = *(const uint4*)(kh + gidx);
            *(uint4*)(Kl_ + key * KH_STR + c8) = *(const uint4*)(kl + gidx);
        }
#pragma unroll
        for (int it = 0; it < 4; it++) {
            int i = it * 256 + tid;
            int dr = i >> 3, kc = (i & 7) * 8;
            size_t gidx = (size_t)(kvh * HD + dr) * S + kt * 64 + kc;
            *(uint4*)(Vth_ + dr * VT_STR + kc) = *(const uint4*)(vth + gidx);
            *(uint4*)(Vtl_ + dr * VT_STR + kc) = *(const uint4*)(vtl + gidx);
        }
        __syncthreads();

        float sc[8][4];
#pragma unroll
        for (int nt = 0; nt < 8; nt++)
#pragma unroll
            for (int r = 0; r < 4; r++) sc[nt][r] = 0.f;

#pragma unroll
        for (int ks = 0; ks < 8; ks++) {
            const int kb = ks * 16;
            uint32_t ah[4], al[4];
            {
                const __half* p0 = Qh_ + row0 * QH_STR + kb + 2 * lc;
                const __half* p1 = Qh_ + row1 * QH_STR + kb + 2 * lc;
                ah[0] = *(const uint32_t*)(p0);
                ah[1] = *(const uint32_t*)(p1);
                ah[2] = *(const uint32_t*)(p0 + 8);
                ah[3] = *(const uint32_t*)(p1 + 8);
                const __half* q0 = Ql_ + row0 * QH_STR + kb + 2 * lc;
                const __half* q1 = Ql_ + row1 * QH_STR + kb + 2 * lc;
                al[0] = *(const uint32_t*)(q0);
                al[1] = *(const uint32_t*)(q1);
                al[2] = *(const uint32_t*)(q0 + 8);
                al[3] = *(const uint32_t*)(q1 + 8);
            }
#pragma unroll
            for (int nt = 0; nt < 8; nt++) {
                const int n0 = nt * 8 + lr;
                const __half* ph = Kh_ + n0 * KH_STR + kb + 2 * lc;
                const __half* pl = Kl_ + n0 * KH_STR + kb + 2 * lc;
                uint32_t bh0 = *(const uint32_t*)(ph);
                uint32_t bh1 = *(const uint32_t*)(ph + 8);
                uint32_t bl0 = *(const uint32_t*)(pl);
                uint32_t bl1 = *(const uint32_t*)(pl + 8);
                mma_f16(sc[nt][0], sc[nt][1], sc[nt][2], sc[nt][3],
                        ah[0], ah[1], ah[2], ah[3], bh0, bh1);
                mma_f16(sc[nt][0], sc[nt][1], sc[nt][2], sc[nt][3],
                        ah[0], ah[1], ah[2], ah[3], bl0, bl1);
                mma_f16(sc[nt][0], sc[nt][1], sc[nt][2], sc[nt][3],
                        al[0], al[1], al[2], al[3], bh0, bh1);
            }
        }

        const bool need_mask = (kt >= 2 * qt);
        float mx0 = -1e30f, mx1 = -1e30f;
#pragma unroll
        for (int nt = 0; nt < 8; nt++) {
#pragma unroll
            for (int j = 0; j < 2; j++) {
                int col = kt * 64 + nt * 8 + 2 * lc + j;
                float s0 = sc[nt][j] * ATT_SCALE;
                float s1 = sc[nt][2 + j] * ATT_SCALE;
                if (need_mask) {
                    if (col > grow0) s0 = -1e30f;
                    if (col > grow1) s1 = -1e30f;
                }
                sc[nt][j] = s0;
                sc[nt][2 + j] = s1;
                mx0 = fmaxf(mx0, s0);
                mx1 = fmaxf(mx1, s1);
            }
        }
        mx0 = fmaxf(mx0, __shfl_xor_sync(0xffffffffu, mx0, 1));
        mx0 = fmaxf(mx0, __shfl_xor_sync(0xffffffffu, mx0, 2));
        mx1 = fmaxf(mx1, __shfl_xor_sync(0xffffffffu, mx1, 1));
        mx1 = fmaxf(mx1, __shfl_xor_sync(0xffffffffu, mx1, 2));
        const float mn0 = fmaxf(m0, mx0);
        const float mn1 = fmaxf(m1, mx1);
        const float scl0 = __expf(m0 - mn0);
        const float scl1 = __expf(m1 - mn1);
        float ls0 = 0.f, ls1 = 0.f;
#pragma unroll
        for (int nt = 0; nt < 8; nt++) {
            float p00 = __expf(sc[nt][0] - mn0);
            float p01 = __expf(sc[nt][1] - mn0);
            float p10 = __expf(sc[nt][2] - mn1);
            float p11 = __expf(sc[nt][3] - mn1);
            ls0 += p00 + p01;
            ls1 += p10 + p11;
            __half h0, l0h, h1, l1h;
            h16split(p00, h0, l0h);
            h16split(p01, h1, l1h);
            *(uint32_t*)(Ph_ + row0 * PH_STR + nt * 8 + 2 * lc) =
                (uint32_t)__half_as_ushort(h0) | ((uint32_t)__half_as_ushort(h1) << 16);
            *(uint32_t*)(Pl_ + row0 * PH_STR + nt * 8 + 2 * lc) =
                (uint32_t)__half_as_ushort(l0h) | ((uint32_t)__half_as_ushort(l1h) << 16);
            h16split(p10, h0, l0h);
            h16split(p11, h1, l1h);
            *(uint32_t*)(Ph_ + row1 * PH_STR + nt * 8 + 2 * lc) =
                (uint32_t)__half_as_ushort(h0) | ((uint32_t)__half_as_ushort(h1) << 16);
            *(uint32_t*)(Pl_ + row1 * PH_STR + nt * 8 + 2 * lc) =
                (uint32_t)__half_as_ushort(l0h) | ((uint32_t)__half_as_ushort(l1h) << 16);
        }
        ls0 += __shfl_xor_sync(0xffffffffu, ls0, 1);
        ls0 += __shfl_xor_sync(0xffffffffu, ls0, 2);
        ls1 += __shfl_xor_sync(0xffffffffu, ls1, 1);
        ls1 += __shfl_xor_sync(0xffffffffu, ls1, 2);
        l0 = l0 * scl0 + ls0;
        l1 = l1 * scl1 + ls1;
        m0 = mn0;
        m1 = mn1;

#pragma unroll
        for (int nt = 0; nt < 16; nt++) {
            o[nt][0] *= scl0;
            o[nt][1] *= scl0;
            o[nt][2] *= scl1;
            o[nt][3] *= scl1;
        }
        __syncwarp();

#pragma unroll
        for (int ks2 = 0; ks2 < 4; ks2++) {
            const int kb = ks2 * 16;
            uint32_t ah[4], al[4];
            {
                const __half* p0 = Ph_ + row0 * PH_STR + kb + 2 * lc;
                const __half* p1 = Ph_ + row1 * PH_STR + kb + 2 * lc;
                ah[0] = *(const uint32_t*)(p0);
                ah[1] = *(const uint32_t*)(p1);
                ah[2] = *(const uint32_t*)(p0 + 8);
                ah[3] = *(const uint32_t*)(p1 + 8);
                const __half* q0 = Pl_ + row0 * PH_STR + kb + 2 * lc;
                const __half* q1 = Pl_ + row1 * PH_STR + kb + 2 * lc;
                al[0] = *(const uint32_t*)(q0);
                al[1] = *(const uint32_t*)(q1);
                al[2] = *(const uint32_t*)(q0 + 8);
                al[3] = *(const uint32_t*)(q1 + 8);
            }
#pragma unroll
            for (int nt = 0; nt < 16; nt++) {
                const int n0 = nt * 8 + lr;
                const __half* ph = Vth_ + n0 * VT_STR + kb + 2 * lc;
                const __half* pl = Vtl_ + n0 * VT_STR + kb + 2 * lc;
                uint32_t bh0 = *(const uint32_t*)(ph);
                uint32_t bh1 = *(const uint32_t*)(ph + 8);
                uint32_t bl0 = *(const uint32_t*)(pl);
                uint32_t bl1 = *(const uint32_t*)(pl + 8);
                mma_f16(o[nt][0], o[nt][1], o[nt][2], o[nt][3],
                        ah[0], ah[1], ah[2], ah[3], bh0, bh1);
                mma_f16(o[nt][0], o[nt][1], o[nt][2], o[nt][3],
                        ah[0], ah[1], ah[2], ah[3], bl0, bl1);
                mma_f16(o[nt][0], o[nt][1], o[nt][2], o[nt][3],
                        al[0], al[1], al[2], al[3], bh0, bh1);
            }
        }
    }

    // epilogue: gate-combine, emit fp16
    const float g = 1.f / (1.f + __expf(-beta[0]));
    const float og = 1.f - g;
    const float li0 = 1.f / l0;
    const float li1 = 1.f / l1;
#pragma unroll
    for (int nt = 0; nt < 16; nt++) {
        const int col = nt * 8 + 2 * lc;
        size_t i0 = (size_t)grow0 * HID + h * HD + col;
        size_t i1 = (size_t)grow1 * HID + h * HD + col;
        float2 mo0 = *(const float2*)(memout + i0);
        float2 mo1 = *(const float2*)(memout + i1);
        *(uint32_t*)(ch + i0) = h2pack(g * mo0.x + og * (o[nt][0] * li0),
                                       g * mo0.y + og * (o[nt][1] * li0));
        *(uint32_t*)(ch + i1) = h2pack(g * mo1.x + og * (o[nt][2] * li1),
                                       g * mo1.y + og * (o[nt][3] * li1));
    }
}

// ---------------- delta-rule partials ----------------
__global__ __launch_bounds__(256) void delta_part_kernel(
    const float* __restrict__ kn, const float* __restrict__ vd, float* __restrict__ part)
{
    const int h = blockIdx.x;
    const int c = blockIdx.y;
    __shared__ float Ak[32][128];
    __shared__ float Bv[32][128];
    const int trow = (threadIdx.x >> 4) * 8;
    const int tcol = (threadIdx.x & 15) * 8;
    float acc[8][8];
#pragma unroll
    for (int i = 0; i < 8; i++)
#pragma unroll
        for (int j = 0; j < 8; j++) acc[i][j] = 0.f;

    const int sbeg = c * 256;
    for (int s0 = sbeg; s0 < sbeg + 256; s0 += 32) {
        for (int i = threadIdx.x; i < 32 * 128; i += 256) {
            int ss = i >> 7, dd = i & 127;
            size_t idx = (size_t)(s0 + ss) * (NKV * HD) + h * HD + dd;
            Ak[ss][dd] = kn[idx];
            Bv[ss][dd] = vd[idx];
        }
        __syncthreads();
#pragma unroll 4
        for (int ss = 0; ss < 32; ss++) {
            float ra[8], rb[8];
#pragma unroll
            for (int i = 0; i < 8; i++) ra[i] = Ak[ss][trow + i];
#pragma unroll
            for (int j = 0; j < 8; j++) rb[j] = Bv[ss][tcol + j];
#pragma unroll
            for (int i = 0; i < 8; i++)
#pragma unroll
                for (int j = 0; j < 8; j++) acc[i][j] += ra[i] * rb[j];
        }
        __syncthreads();
    }
    float* Ph = part + (size_t)c * (NKV * HD * HD) + h * HD * HD;
#pragma unroll
    for (int i = 0; i < 8; i++)
#pragma unroll
        for (int j = 0; j < 8; j++)
            Ph[(trow + i) * HD + tcol + j] = acc[i][j];
}

__global__ __launch_bounds__(256) void delta_final_kernel(
    const float* __restrict__ part, const float* __restrict__ memory, float* __restrict__ outmem)
{
    const int i = blockIdx.x * 256 + threadIdx.x;
    float acc = memory[i];
#pragma unroll
    for (int c = 0; c < 8; c++) acc += part[(size_t)c * (NKV * HD * HD) + i];
    outmem[i] = acc;
}

// ---------------- updated_norm ----------------
__global__ __launch_bounds__(256) void norm_kernel(
    const float* __restrict__ norm_m, const float* __restrict__ knsum, float* __restrict__ out)
{
    const int i = blockIdx.x * 256 + threadIdx.x;
    const int h = i >> 14;
    const int j = i & 127;
    out[i] = norm_m[i] + knsum[h * HD + j];
}

// ---------------- launch ----------------
extern "C" void kernel_launch(void* const* d_in, const int* in_sizes, int n_in,
                              void* d_out, int out_size)
{
    const float* hidden = (const float*)d_in[0];
    const int*   pos    = (const int*)d_in[1];
    const float* wq     = (const float*)d_in[2];
    const float* wk     = (const float*)d_in[3];
    const float* wv     = (const float*)d_in[4];
    const float* wo     = (const float*)d_in[5];
    const float* memory = (const float*)d_in[6];
    const float* norm_m = (const float*)d_in[7];
    const float* beta   = (const float*)d_in[8];
    float* out = (float*)d_out;

    float *qproj, *kproj, *vproj, *qn, *kn, *memout, *vdelta, *knsum, *knpart, *dpart;
    __half *hh, *wqT, *wkT, *wvT, *woT, *ch, *qh, *ql, *kh, *kl, *vth, *vtl;
    cudaGetSymbolAddress((void**)&qproj, g_qproj);
    cudaGetSymbolAddress((void**)&kproj, g_kproj);
    cudaGetSymbolAddress((void**)&vproj, g_vproj);
    cudaGetSymbolAddress((void**)&qn, g_qn);
    cudaGetSymbolAddress((void**)&kn, g_kn);
    cudaGetSymbolAddress((void**)&memout, g_memout);
    cudaGetSymbolAddress((void**)&vdelta, g_vdelta);
    cudaGetSymbolAddress((void**)&knsum, g_knsum);
    cudaGetSymbolAddress((void**)&knpart, g_knsum_part);
    cudaGetSymbolAddress((void**)&dpart, g_delta_part);
    cudaGetSymbolAddress((void**)&hh, g_hh);
    cudaGetSymbolAddress((void**)&wqT, g_wqT);
    cudaGetSymbolAddress((void**)&wkT, g_wkT);
    cudaGetSymbolAddress((void**)&wvT, g_wvT);
    cudaGetSymbolAddress((void**)&woT, g_woT);
    cudaGetSymbolAddress((void**)&ch, g_ch);
    cudaGetSymbolAddress((void**)&qh, g_qh);
    cudaGetSymbolAddress((void**)&ql, g_ql);
    cudaGetSymbolAddress((void**)&kh, g_kh);
    cudaGetSymbolAddress((void**)&kl, g_kl);
    cudaGetSymbolAddress((void**)&vth, g_vth);
    cudaGetSymbolAddress((void**)&vtl, g_vtl);

    cudaFuncSetAttribute(attn_f16_kernel,
                         cudaFuncAttributeMaxDynamicSharedMemorySize, ATT2_SMEM_BYTES);
    cudaFuncSetAttribute(gemm_f16_kernel,
                         cudaFuncAttributeMaxDynamicSharedMemorySize, GEMM4_SMEM);

    // pre-pass: hidden -> fp16; weights -> transposed [N][K] fp16
    h2h_kernel<<<1024, 256>>>(hidden, hh, S * HID / 4);
    wtrans_kernel<<<dim3(HID / 32, HID / 32), 256>>>(wq, wqT, HID, HID);
    wtrans_kernel<<<dim3(NKV * HD / 32, HID / 32), 256>>>(wk, wkT, HID, NKV * HD);
    wtrans_kernel<<<dim3(NKV * HD / 32, HID / 32), 256>>>(wv, wvT, HID, NKV * HD);
    wtrans_kernel<<<dim3(HID / 32, HID / 32), 256>>>(wo, woT, HID, HID);

    // projections (fp16 m16n8k16 + ldmatrix). z=0: Q; z=1: bx<8 K, bx<16 V.
    gemm_f16_kernel<<<dim3(HID / 128, S / 128, 2), 128, GEMM4_SMEM>>>(
        hh, wqT, qproj, HID, wkT, kproj, wvT, vproj, NKV * HD, HID);

    // normalized features from PRE-RoPE q/k
    qn_kernel<<<S, 128>>>(qproj, qn);
    kn_kernel<<<S, 128>>>(kproj, kn);
    knsum_part_kernel<<<dim3(NKV, 16), 128>>>(kn, knpart);
    knsum_final_kernel<<<1, 1024>>>(knpart, knsum);

    // compressive-memory retrieval + delta-rule prep
    retrieve_kernel<<<dim3(S / 16, NH), 128>>>(qn, memory, norm_m, memout);
    vdelta_kernel<<<dim3(S / 16, NKV), 128>>>(kn, vproj, memory, norm_m, vdelta);

    // RoPE + fp16 hi/lo split; V transpose + split
    rope_split_kernel<<<dim3(S, 10), 256>>>(qproj, kproj, pos, qh, ql, kh, kl);
    vtrans_split_kernel<<<dim3(S / 32, NKV * HD / 32), 256>>>(vproj, vth, vtl);

    // fp16-split flash attention (fuses gated combine, emits fp16 combined)
    attn_f16_kernel<<<dim3(S / 128, NH), 256, ATT2_SMEM_BYTES>>>(
        qh, ql, kh, kl, vth, vtl, memout, beta, ch);

    // output projection (fp16)
    gemm_f16_kernel<<<dim3(HID / 128, S / 128, 1), 128, GEMM4_SMEM>>>(
        ch, woT, out, HID, woT, out, woT, out, HID, HID);

    // memory & norm updates (appended after the 8.4M-element `out`)
    delta_part_kernel<<<dim3(NKV, 8), 256>>>(kn, vdelta, dpart);
    delta_final_kernel<<<(NKV * HD * HD) / 256, 256>>>(dpart, memory, out + (size_t)S * HID);
    norm_kernel<<<(NKV * HD * HD) / 256, 256>>>(norm_m, knsum,
                                                out + (size_t)S * HID + NKV * HD * HD);
}